// round 7
// baseline (speedup 1.0000x reference)
#include <cuda_runtime.h>
#include <math.h>

// ---------------- problem constants ----------------
#define BB    8
#define LSEQ  1024            // 2*L_IN
#define ROWS  (BB*LSEQ)       // 8192 tokens
#define CC    512
#define DI    1024
#define DS    16
#define NDEPTH 4

// ---------------- scratch (device globals; no allocs allowed) ----------------
__device__ float g_up_tmp[4096*1024];   // up GEMM raw output [b*512+l, o*2+k]
__device__ float g_up   [ROWS*CC];      // rearranged up tokens
__device__ float g_h    [ROWS*CC];      // h1 / post-rms-silu
__device__ float g_x    [ROWS*CC];      // residual stream
__device__ float g_ln   [ROWS*CC];      // per-layer layernorm out
__device__ float g_xz   [ROWS*2*DI];    // in_proj out (xc_raw | z)
__device__ float g_xc   [ROWS*DI];      // conv+silu out (u)
__device__ float g_xdbc [ROWS*64];      // x_proj out (dtp|B|C)
__device__ float g_dt   [ROWS*DI];      // softplus dt
__device__ float g_y    [ROWS*DI];      // scan out * silu(z)

// ---------------- helpers ----------------
__device__ __forceinline__ float softplusf(float x) {
    return (x > 20.f) ? x : log1pf(__expf(x));
}
__device__ __forceinline__ float siluf(float x) {
    return x / (1.f + __expf(-x));
}

// packed fp32x2 (Blackwell full-rate fp32 path; ptxas never emits it from C++)
__device__ __forceinline__ unsigned long long pack_dup(float x) {
    unsigned long long r;
    asm("mov.b64 %0, {%1, %1};" : "=l"(r) : "f"(x));
    return r;
}
__device__ __forceinline__ void ffma2(unsigned long long& d,
                                      unsigned long long a,
                                      unsigned long long b) {
    asm("fma.rn.f32x2 %0, %1, %2, %0;" : "+l"(d) : "l"(a), "l"(b));
}
__device__ __forceinline__ void unpack2(unsigned long long v, float& lo, float& hi) {
    asm("mov.b64 {%0, %1}, %2;" : "=f"(lo), "=f"(hi) : "l"(v));
}

// ---------------- tiled SGEMM, BK=16, double-buffered, FFMA2 core ----------------
// C[M,N] = A[M,K(lda)] * op(B) (+bias[col]) (+rowvec[(row>>10)*ldc+col]) (+beta*C) (softplus)
// BKXN=false: B is [N,K] row-major (A @ B^T)
// BKXN=true : B is [K,N] row-major (A @ B)   -- used for w_up
template<bool BKXN>
__global__ __launch_bounds__(256, 2)
void sgemm_k(const float* __restrict__ A, int lda,
             const float* __restrict__ B, int ldb,
             float* __restrict__ C, int ldc,
             const float* __restrict__ bias,
             const float* __restrict__ rowvec,
             int M, int N, int K,
             int beta, int do_softplus)
{
    __shared__ __align__(16) float As[2][16][128];
    __shared__ __align__(16) float Bs[2][16][128];

    const int tid = threadIdx.x;
    const int m0 = blockIdx.y * 128;
    const int n0 = blockIdx.x * 128;
    const int ty = tid >> 4;      // 0..15
    const int tx = tid & 15;      // 0..15

    // A staging: each thread 2 float4 -> rows (tid>>2, tid>>2+64), cols (tid&3)*4
    const int a_r = tid >> 2;          // 0..63
    const int a_c = (tid & 3) * 4;     // 0,4,8,12
    // B NK staging: same pattern over n-rows
    const int b_r = a_r;
    const int b_c = a_c;
    // B KN staging: rows tid>>5 (+8), cols (tid&31)*4
    const int bk_r = tid >> 5;         // 0..7
    const int bk_c = (tid & 31) * 4;   // 0..124

    // packed accumulators: acc2[i][j2] holds cols (2*j2, 2*j2+1) of row i
    unsigned long long acc2[8][4];
#pragma unroll
    for (int i = 0; i < 8; i++)
#pragma unroll
        for (int j = 0; j < 4; j++) acc2[i][j] = 0ULL;

    const float* Ab = A + (size_t)m0 * lda;

    float4 a0, a1, b0, b1;

    // ---- prologue: stage k0 = 0 ----
    a0 = *(const float4*)(Ab + (size_t)a_r * lda + a_c);
    a1 = *(const float4*)(Ab + (size_t)(a_r + 64) * lda + a_c);
    if (BKXN) {
        b0 = make_float4(0.f, 0.f, 0.f, 0.f); b1 = b0;
        if (n0 + bk_c < N) {
            b0 = *(const float4*)(B + (size_t)bk_r * ldb + n0 + bk_c);
            b1 = *(const float4*)(B + (size_t)(bk_r + 8) * ldb + n0 + bk_c);
        }
    } else {
        b0 = make_float4(0.f, 0.f, 0.f, 0.f); b1 = b0;
        if (n0 + b_r < N)
            b0 = *(const float4*)(B + (size_t)(n0 + b_r) * ldb + b_c);
        if (n0 + b_r + 64 < N)
            b1 = *(const float4*)(B + (size_t)(n0 + b_r + 64) * ldb + b_c);
    }
    {
        As[0][a_c + 0][a_r] = a0.x; As[0][a_c + 1][a_r] = a0.y;
        As[0][a_c + 2][a_r] = a0.z; As[0][a_c + 3][a_r] = a0.w;
        As[0][a_c + 0][a_r + 64] = a1.x; As[0][a_c + 1][a_r + 64] = a1.y;
        As[0][a_c + 2][a_r + 64] = a1.z; As[0][a_c + 3][a_r + 64] = a1.w;
        if (BKXN) {
            *(float4*)&Bs[0][bk_r][bk_c]     = b0;
            *(float4*)&Bs[0][bk_r + 8][bk_c] = b1;
        } else {
            Bs[0][b_c + 0][b_r] = b0.x; Bs[0][b_c + 1][b_r] = b0.y;
            Bs[0][b_c + 2][b_r] = b0.z; Bs[0][b_c + 3][b_r] = b0.w;
            Bs[0][b_c + 0][b_r + 64] = b1.x; Bs[0][b_c + 1][b_r + 64] = b1.y;
            Bs[0][b_c + 2][b_r + 64] = b1.z; Bs[0][b_c + 3][b_r + 64] = b1.w;
        }
    }
    __syncthreads();

    int buf = 0;
    for (int k0 = 0; k0 < K; k0 += 16) {
        const bool nxt = (k0 + 16 < K);
        // prefetch next tile into registers (overlaps with FFMA2 below)
        if (nxt) {
            const int kn = k0 + 16;
            a0 = *(const float4*)(Ab + (size_t)a_r * lda + kn + a_c);
            a1 = *(const float4*)(Ab + (size_t)(a_r + 64) * lda + kn + a_c);
            if (BKXN) {
                b0 = make_float4(0.f, 0.f, 0.f, 0.f); b1 = b0;
                if (n0 + bk_c < N) {
                    b0 = *(const float4*)(B + (size_t)(kn + bk_r) * ldb + n0 + bk_c);
                    b1 = *(const float4*)(B + (size_t)(kn + bk_r + 8) * ldb + n0 + bk_c);
                }
            } else {
                b0 = make_float4(0.f, 0.f, 0.f, 0.f); b1 = b0;
                if (n0 + b_r < N)
                    b0 = *(const float4*)(B + (size_t)(n0 + b_r) * ldb + kn + b_c);
                if (n0 + b_r + 64 < N)
                    b1 = *(const float4*)(B + (size_t)(n0 + b_r + 64) * ldb + kn + b_c);
            }
        }

#pragma unroll
        for (int kk = 0; kk < 16; kk++) {
            float arr[8];
            *(float4*)&arr[0] = *(const float4*)&As[buf][kk][ty * 8];
            *(float4*)&arr[4] = *(const float4*)&As[buf][kk][ty * 8 + 4];
            unsigned long long b2[4];
            {
                ulonglong2 q0 = *(const ulonglong2*)&Bs[buf][kk][tx * 8];
                ulonglong2 q1 = *(const ulonglong2*)&Bs[buf][kk][tx * 8 + 4];
                b2[0] = q0.x; b2[1] = q0.y; b2[2] = q1.x; b2[3] = q1.y;
            }
#pragma unroll
            for (int i = 0; i < 8; i++) {
                const unsigned long long ai = pack_dup(arr[i]);
#pragma unroll
                for (int j = 0; j < 4; j++)
                    ffma2(acc2[i][j], ai, b2[j]);
            }
        }

        if (nxt) {
            const int nb = buf ^ 1;
            As[nb][a_c + 0][a_r] = a0.x; As[nb][a_c + 1][a_r] = a0.y;
            As[nb][a_c + 2][a_r] = a0.z; As[nb][a_c + 3][a_r] = a0.w;
            As[nb][a_c + 0][a_r + 64] = a1.x; As[nb][a_c + 1][a_r + 64] = a1.y;
            As[nb][a_c + 2][a_r + 64] = a1.z; As[nb][a_c + 3][a_r + 64] = a1.w;
            if (BKXN) {
                *(float4*)&Bs[nb][bk_r][bk_c]     = b0;
                *(float4*)&Bs[nb][bk_r + 8][bk_c] = b1;
            } else {
                Bs[nb][b_c + 0][b_r] = b0.x; Bs[nb][b_c + 1][b_r] = b0.y;
                Bs[nb][b_c + 2][b_r] = b0.z; Bs[nb][b_c + 3][b_r] = b0.w;
                Bs[nb][b_c + 0][b_r + 64] = b1.x; Bs[nb][b_c + 1][b_r + 64] = b1.y;
                Bs[nb][b_c + 2][b_r + 64] = b1.z; Bs[nb][b_c + 3][b_r + 64] = b1.w;
            }
            __syncthreads();
            buf = nb;
        }
    }

    const int col = n0 + tx * 8;
    if (col >= N) return;   // N multiple of 8; 8-col block fully in/out

#pragma unroll
    for (int i = 0; i < 8; i++) {
        const int row = m0 + ty * 8 + i;
        float* cp = C + (size_t)row * ldc + col;
        float v[8];
#pragma unroll
        for (int j = 0; j < 4; j++)
            unpack2(acc2[i][j], v[2 * j], v[2 * j + 1]);
#pragma unroll
        for (int j = 0; j < 8; j++) {
            float t = v[j];
            if (bias)   t += bias[col + j];
            if (rowvec) t += rowvec[(row >> 10) * ldc + col + j];
            if (beta)   t += cp[j];
            if (do_softplus) t = softplusf(t);
            v[j] = t;
        }
        *(float4*)cp       = *(float4*)&v[0];
        *(float4*)(cp + 4) = *(float4*)&v[4];
    }
}

// ---------------- layernorm (C = 512, 128 threads/row) ----------------
__global__ void layernorm_k(const float* __restrict__ x,
                            const float* __restrict__ w,
                            const float* __restrict__ b,
                            float* __restrict__ out)
{
    const int row = blockIdx.x;
    const int tid = threadIdx.x;
    float4 v = ((const float4*)(x + (size_t)row * 512))[tid];
    float s  = v.x + v.y + v.z + v.w;
    float sq = v.x * v.x + v.y * v.y + v.z * v.z + v.w * v.w;
#pragma unroll
    for (int o = 16; o > 0; o >>= 1) {
        s  += __shfl_xor_sync(0xffffffffu, s,  o);
        sq += __shfl_xor_sync(0xffffffffu, sq, o);
    }
    __shared__ float ss[4], ssq[4];
    const int wid = tid >> 5;
    if ((tid & 31) == 0) { ss[wid] = s; ssq[wid] = sq; }
    __syncthreads();
    s  = ss[0]  + ss[1]  + ss[2]  + ss[3];
    sq = ssq[0] + ssq[1] + ssq[2] + ssq[3];
    const float m   = s  * (1.f / 512.f);
    const float var = sq * (1.f / 512.f) - m * m;
    const float inv = rsqrtf(var + 1e-5f);
    float4 wv = ((const float4*)w)[tid];
    float4 bv = ((const float4*)b)[tid];
    float4 o4;
    o4.x = (v.x - m) * inv * wv.x + bv.x;
    o4.y = (v.y - m) * inv * wv.y + bv.y;
    o4.z = (v.z - m) * inv * wv.z + bv.z;
    o4.w = (v.w - m) * inv * wv.w + bv.w;
    ((float4*)(out + (size_t)row * 512))[tid] = o4;
}

// ---------------- rmsnorm + silu, in place (C = 512) ----------------
__global__ void rmsnorm_silu_k(float* __restrict__ x, const float* __restrict__ w)
{
    const int row = blockIdx.x;
    const int tid = threadIdx.x;
    float4 v = ((const float4*)(x + (size_t)row * 512))[tid];
    float sq = v.x * v.x + v.y * v.y + v.z * v.z + v.w * v.w;
#pragma unroll
    for (int o = 16; o > 0; o >>= 1) sq += __shfl_xor_sync(0xffffffffu, sq, o);
    __shared__ float ssq[4];
    const int wid = tid >> 5;
    if ((tid & 31) == 0) ssq[wid] = sq;
    __syncthreads();
    sq = ssq[0] + ssq[1] + ssq[2] + ssq[3];
    const float inv = rsqrtf(sq * (1.f / 512.f) + 1e-5f);
    float4 wv = ((const float4*)w)[tid];
    float4 o4;
    float a;
    a = v.x * inv * wv.x; o4.x = siluf(a);
    a = v.y * inv * wv.y; o4.y = siluf(a);
    a = v.z * inv * wv.z; o4.z = siluf(a);
    a = v.w * inv * wv.w; o4.w = siluf(a);
    ((float4*)(x + (size_t)row * 512))[tid] = o4;
}

// ---------------- up rearrange: [b,l, o*2+k] -> [b, 2l+k, o] (+b_up) ----------------
__global__ void up_rearrange_k(const float* __restrict__ up_tmp,
                               const float* __restrict__ b_up,
                               float* __restrict__ up)
{
    const int idx  = blockIdx.x * blockDim.x + threadIdx.x;  // ROWS*512
    const int o    = idx & 511;
    const int orow = idx >> 9;
    const int b    = orow >> 10;
    const int t    = orow & 1023;
    const int l    = t >> 1;
    const int k    = t & 1;
    up[idx] = up_tmp[(size_t)(b * 512 + l) * 1024 + o * 2 + k] + b_up[o];
}

// ---------------- causal depthwise conv(4) + bias + silu ----------------
__global__ void conv_silu_k(const float* __restrict__ xz,   // [ROWS, 2048], cols 0..1023 = xc_raw
                            const float* __restrict__ cw,   // [1024,4]
                            const float* __restrict__ cb,   // [1024]
                            float* __restrict__ xc)         // [ROWS, 1024]
{
    const int idx = blockIdx.x * blockDim.x + threadIdx.x;   // ROWS*1024
    const int d   = idx & 1023;
    const int row = idx >> 10;
    const int t   = row & 1023;
    float acc = cb[d];
#pragma unroll
    for (int j = 0; j < 4; j++) {
        const int tt = t - 3 + j;
        if (tt >= 0)
            acc = fmaf(cw[d * 4 + j], xz[(size_t)(row - 3 + j) * 2048 + d], acc);
    }
    xc[idx] = siluf(acc);
}

// ---------------- selective scan (smem B/C staging + batched prefetch) ----
// 2 threads per (b,d): lanes (2k, 2k+1) split the 16 states (8 each).
// y_out = (sum_n h_n*C_n + u*D) * silu(z)
__global__ __launch_bounds__(128)
void scan_k(const float* __restrict__ dt,     // [ROWS,1024]
            const float* __restrict__ xc,     // u [ROWS,1024]
            const float* __restrict__ xz,     // z at col 1024+d, ld 2048
            const float* __restrict__ xdbc,   // [ROWS,64]
            const float* __restrict__ A_log,  // [1024,16] this layer
            const float* __restrict__ Dp,     // [1024]
            float* __restrict__ y)            // [ROWS,1024]
{
    __shared__ __align__(16) float bc_s[32][32];  // [t_in_chunk][B(16)|C(16)]

    const int tid    = threadIdx.x;           // 128
    const int half   = tid & 1;
    const int dloc   = tid >> 1;               // 0..63
    const int b      = blockIdx.x >> 4;
    const int d      = (blockIdx.x & 15) * 64 + dloc;
    const int n0     = half * 8;

    float A2[8], h[8];
#pragma unroll
    for (int j = 0; j < 8; j++) {
        A2[j] = -__expf(A_log[d * 16 + n0 + j]) * 1.44269504f;  // A * log2(e)
        h[j]  = 0.f;
    }
    const float Dd = Dp[d];

    const float* dtp = dt   + (size_t)b * 1024 * 1024 + d;
    const float* up  = xc   + (size_t)b * 1024 * 1024 + d;
    const float* zp  = xz   + (size_t)b * 1024 * 2048 + 1024 + d;
    const float* bcb = xdbc + (size_t)b * 1024 * 64 + 32;
    float*       yp  = y    + (size_t)b * 1024 * 1024 + d;

    const int st_t = tid >> 2;        // 0..31 (t within chunk)
    const int st_c = (tid & 3) * 8;   // 0,8,16,24

    for (int c = 0; c < 32; c++) {
        __syncthreads();
        {
            const float* src = bcb + (size_t)(c * 32 + st_t) * 64 + st_c;
            *(float4*)&bc_s[st_t][st_c]     = *(const float4*)src;
            *(float4*)&bc_s[st_t][st_c + 4] = *(const float4*)(src + 4);
        }
        __syncthreads();

#pragma unroll
        for (int s = 0; s < 4; s++) {
            const int tbase = c * 32 + s * 8;
            float dt8[8], u8[8], z8[8];
#pragma unroll
            for (int j = 0; j < 8; j++) {          // 24 independent loads in flight
                dt8[j] = dtp[(size_t)(tbase + j) * 1024];
                u8[j]  = up [(size_t)(tbase + j) * 1024];
                z8[j]  = zp [(size_t)(tbase + j) * 2048];
            }
#pragma unroll
            for (int j = 0; j < 8; j++) {
                const int tt = s * 8 + j;
                float Bv[8], Cv[8];
                *(float4*)&Bv[0] = *(const float4*)&bc_s[tt][n0];
                *(float4*)&Bv[4] = *(const float4*)&bc_s[tt][n0 + 4];
                *(float4*)&Cv[0] = *(const float4*)&bc_s[tt][16 + n0];
                *(float4*)&Cv[4] = *(const float4*)&bc_s[tt][16 + n0 + 4];
                const float dtv = dt8[j];
                const float u   = u8[j];
                const float du  = dtv * u;
                float ya = 0.f, yb2 = 0.f;
#pragma unroll
                for (int n = 0; n < 8; n++) {
                    const float dA = exp2f(dtv * A2[n]);       // exp(dt*A)
                    h[n] = fmaf(dA, h[n], du * Bv[n]);
                    if (n & 1) yb2 = fmaf(h[n], Cv[n], yb2);
                    else       ya  = fmaf(h[n], Cv[n], ya);
                }
                float ysum = ya + yb2;
                ysum += __shfl_xor_sync(0xffffffffu, ysum, 1);
                if (half == 0)
                    yp[(size_t)(tbase + j) * 1024] = (ysum + u * Dd) * siluf(z8[j]);
            }
        }
    }
}

// ---------------- launcher ----------------
extern "C" void kernel_launch(void* const* d_in, const int* in_sizes, int n_in,
                              void* d_out, int out_size)
{
    (void)in_sizes; (void)n_in; (void)out_size;

    const float* motion     = (const float*)d_in[0];
    const float* skip       = (const float*)d_in[1];
    const float* embed      = (const float*)d_in[2];
    const float* w_up       = (const float*)d_in[3];
    const float* b_up       = (const float*)d_in[4];
    const float* w1         = (const float*)d_in[5];
    const float* b1         = (const float*)d_in[6];
    const float* rms_w      = (const float*)d_in[7];
    const float* w2         = (const float*)d_in[8];
    const float* b2         = (const float*)d_in[9];
    const float* ln_w       = (const float*)d_in[10];
    const float* ln_b       = (const float*)d_in[11];
    const float* in_proj_w  = (const float*)d_in[12];
    const float* conv_w     = (const float*)d_in[13];
    const float* conv_b     = (const float*)d_in[14];
    const float* x_proj_w   = (const float*)d_in[15];
    const float* dt_proj_w  = (const float*)d_in[16];
    const float* dt_proj_b  = (const float*)d_in[17];
    const float* A_log      = (const float*)d_in[18];
    const float* D_param    = (const float*)d_in[19];
    const float* out_proj_w = (const float*)d_in[20];
    const float* out_proj_b = (const float*)d_in[21];
    const float* norm_f_w   = (const float*)d_in[22];
    const float* norm_f_b   = (const float*)d_in[23];
    float* out = (float*)d_out;

    float *up_tmp, *up, *h, *x, *ln, *xz, *xc, *xdbc, *dtb, *yb;
    cudaGetSymbolAddress((void**)&up_tmp, g_up_tmp);
    cudaGetSymbolAddress((void**)&up,     g_up);
    cudaGetSymbolAddress((void**)&h,      g_h);
    cudaGetSymbolAddress((void**)&x,      g_x);
    cudaGetSymbolAddress((void**)&ln,     g_ln);
    cudaGetSymbolAddress((void**)&xz,     g_xz);
    cudaGetSymbolAddress((void**)&xc,     g_xc);
    cudaGetSymbolAddress((void**)&xdbc,   g_xdbc);
    cudaGetSymbolAddress((void**)&dtb,    g_dt);
    cudaGetSymbolAddress((void**)&yb,     g_y);

    // 1) up = motion @ w_up   (A[4096,512] @ B[512,1024] K-major)
    sgemm_k<true><<<dim3(1024/128, 4096/128), 256>>>(
        motion, 512, w_up, 1024, up_tmp, 1024,
        nullptr, nullptr, 4096, 1024, 512, 0, 0);

    // 2) rearrange [b,l,(o,k)] -> tokens, add b_up
    up_rearrange_k<<<(ROWS * 512) / 256, 256>>>(up_tmp, b_up, up);

    // 3) h = up @ w1[:, :512]^T + b1 ; h += skip @ w1[:, 512:]^T
    sgemm_k<false><<<dim3(4, 64), 256>>>(
        up, 512, w1, 1024, h, 512, b1, nullptr, ROWS, 512, 512, 0, 0);
    sgemm_k<false><<<dim3(4, 64), 256>>>(
        skip, 512, w1 + 512, 1024, h, 512, nullptr, nullptr, ROWS, 512, 512, 1, 0);

    // 4) h = silu(rmsnorm(h, rms_w)) in place
    rmsnorm_silu_k<<<ROWS, 128>>>(h, rms_w);

    // 5) x = h @ w2^T + b2 + embed[b]
    sgemm_k<false><<<dim3(4, 64), 256>>>(
        h, 512, w2, 512, x, 512, b2, embed, ROWS, 512, 512, 0, 0);

    // 6) mamba layers
    for (int i = 0; i < NDEPTH; i++) {
        layernorm_k<<<ROWS, 128>>>(x, ln_w + i * 512, ln_b + i * 512, ln);

        sgemm_k<false><<<dim3(16, 64), 256>>>(
            ln, 512, in_proj_w + (size_t)i * 2048 * 512, 512,
            xz, 2048, nullptr, nullptr, ROWS, 2048, 512, 0, 0);

        conv_silu_k<<<(ROWS * DI) / 256, 256>>>(
            xz, conv_w + (size_t)i * 1024 * 4, conv_b + i * 1024, xc);

        sgemm_k<false><<<dim3(1, 64), 256>>>(
            xc, 1024, x_proj_w + (size_t)i * 64 * 1024, 1024,
            xdbc, 64, nullptr, nullptr, ROWS, 64, 1024, 0, 0);

        sgemm_k<false><<<dim3(8, 64), 256>>>(
            xdbc, 64, dt_proj_w + (size_t)i * 1024 * 32, 32,
            dtb, 1024, dt_proj_b + i * 1024, nullptr, ROWS, 1024, 32, 0, 1);

        scan_k<<<128, 128>>>(
            dtb, xc, xz, xdbc,
            A_log + (size_t)i * 1024 * 16, D_param + i * 1024, yb);

        sgemm_k<false><<<dim3(4, 64), 256>>>(
            yb, 1024, out_proj_w + (size_t)i * 512 * 1024, 1024,
            x, 512, out_proj_b + i * 512, nullptr, ROWS, 512, 1024, 1, 0);
    }

    // 7) final layernorm -> output
    layernorm_k<<<ROWS, 128>>>(x, norm_f_w, norm_f_b, out);
}

// round 9
// speedup vs baseline: 1.3721x; 1.3721x over previous
#include <cuda_runtime.h>
#include <cuda_bf16.h>
#include <math.h>
#include <stdint.h>

// ---------------- problem constants ----------------
#define BB    8
#define LSEQ  1024            // 2*L_IN
#define ROWS  (BB*LSEQ)       // 8192 tokens
#define CC    512
#define DI    1024
#define DS    16
#define NDEPTH 4

// ---------------- scratch (device globals; no allocs allowed) ----------------
__device__ float g_up_tmp[4096*1024];   // up GEMM raw output [b*512+l, o*2+k]
__device__ float g_up   [ROWS*CC];      // rearranged up tokens
__device__ float g_h    [ROWS*CC];      // h1 / post-rms-silu
__device__ float g_x    [ROWS*CC];      // residual stream
__device__ float g_ln   [ROWS*CC];      // per-layer layernorm out
__device__ float g_xz   [ROWS*2*DI];    // in_proj out (xc_raw | z)
__device__ float g_xc   [ROWS*DI];      // conv+silu out (u)
__device__ float g_xdbc [ROWS*64];      // x_proj out (dtp|B|C)
__device__ float g_dt   [ROWS*DI];      // softplus dt
__device__ float g_y    [ROWS*DI];      // scan out * silu(z)

// ---------------- helpers ----------------
__device__ __forceinline__ float softplusf(float x) {
    return (x > 20.f) ? x : log1pf(__expf(x));
}
__device__ __forceinline__ float siluf(float x) {
    return x / (1.f + __expf(-x));
}

__device__ __forceinline__ uint32_t smem_u32(const void* p) {
    uint32_t a;
    asm("{ .reg .u64 t; cvta.to.shared.u64 t, %1; cvt.u32.u64 %0, t; }"
        : "=r"(a) : "l"(p));
    return a;
}

// split f32x4 into bf16 hi / lo pairs (packed bf16x2 words, .x in low half)
__device__ __forceinline__ void split4(float4 v, uint32_t& h01, uint32_t& h23,
                                       uint32_t& l01, uint32_t& l23) {
    __nv_bfloat162 h0 = __float22bfloat162_rn(make_float2(v.x, v.y));
    __nv_bfloat162 h1 = __float22bfloat162_rn(make_float2(v.z, v.w));
    float2 f0 = __bfloat1622float2(h0), f1 = __bfloat1622float2(h1);
    __nv_bfloat162 l0 = __float22bfloat162_rn(make_float2(v.x - f0.x, v.y - f0.y));
    __nv_bfloat162 l1 = __float22bfloat162_rn(make_float2(v.z - f1.x, v.w - f1.y));
    h01 = *(uint32_t*)&h0; h23 = *(uint32_t*)&h1;
    l01 = *(uint32_t*)&l0; l23 = *(uint32_t*)&l1;
}

__device__ __forceinline__ void ldsm4(uint32_t* r, uint32_t addr) {
    asm volatile("ldmatrix.sync.aligned.m8n8.x4.shared.b16 {%0,%1,%2,%3}, [%4];"
        : "=r"(r[0]), "=r"(r[1]), "=r"(r[2]), "=r"(r[3]) : "r"(addr));
}

__device__ __forceinline__ void mma_bf16(float* c, const uint32_t* a, const uint32_t* b) {
    asm volatile("mma.sync.aligned.m16n8k16.row.col.f32.bf16.bf16.f32 "
        "{%0,%1,%2,%3}, {%4,%5,%6,%7}, {%8,%9}, {%0,%1,%2,%3};"
        : "+f"(c[0]), "+f"(c[1]), "+f"(c[2]), "+f"(c[3])
        : "r"(a[0]), "r"(a[1]), "r"(a[2]), "r"(a[3]), "r"(b[0]), "r"(b[1]));
}

// convert 16 f32 (4 float4) -> 16 bf16 hi + 16 bf16 lo, store 2x v4 each
__device__ __forceinline__ void cvt_store(uint32_t dst_hi, uint32_t dst_lo,
                                          const float4* p) {
    uint32_t h[8], l[8];
#pragma unroll
    for (int i = 0; i < 4; i++)
        split4(p[i], h[2*i], h[2*i+1], l[2*i], l[2*i+1]);
    asm volatile("st.shared.v4.b32 [%0], {%1,%2,%3,%4};"
                 :: "r"(dst_hi),      "r"(h[0]), "r"(h[1]), "r"(h[2]), "r"(h[3]));
    asm volatile("st.shared.v4.b32 [%0], {%1,%2,%3,%4};"
                 :: "r"(dst_hi + 16), "r"(h[4]), "r"(h[5]), "r"(h[6]), "r"(h[7]));
    asm volatile("st.shared.v4.b32 [%0], {%1,%2,%3,%4};"
                 :: "r"(dst_lo),      "r"(l[0]), "r"(l[1]), "r"(l[2]), "r"(l[3]));
    asm volatile("st.shared.v4.b32 [%0], {%1,%2,%3,%4};"
                 :: "r"(dst_lo + 16), "r"(l[4]), "r"(l[5]), "r"(l[6]), "r"(l[7]));
}

// ============================================================================
// tensor-core GEMM (mma.sync bf16, split-bf16 3-term ~fp32 precision)
// C[M,N] = A[M,K] @ B[N,K]^T  (+bias[col]) (+rowvec[(row>>10)*ldc+col]) (+beta*C)
// M, N multiples of 128; K multiple of 32. Block 128x128, BK=32, 8 warps.
// smem rows pitched 80B (32 bf16 + 16B pad) -> conflict-free ldmatrix.
// regions per buffer: AH 0, AL 10240, BH 20480, BL 30720; two buffers.
// ============================================================================
#define TG_PITCH     80
#define TG_REGION    10240
#define TG_BUFSTRIDE 40960
#define TG_SMEM_BYTES (2*TG_BUFSTRIDE)

__global__ __launch_bounds__(256)
void tgemm_k(const float* __restrict__ A, int lda,
             const float* __restrict__ B, int ldb,
             float* __restrict__ C, int ldc,
             const float* __restrict__ bias,
             const float* __restrict__ rowvec,
             int K, int beta)
{
    extern __shared__ __align__(16) char smem[];
    const uint32_t sb = smem_u32(smem);
    const int tid  = threadIdx.x;
    const int wid  = tid >> 5;
    const int lane = tid & 31;
    const int m0 = blockIdx.y * 128;
    const int n0 = blockIdx.x * 128;
    const int wm = wid >> 2;          // 0..1 -> 64 rows
    const int wn = wid & 3;           // 0..3 -> 32 cols

    float acc[4][4][4];
#pragma unroll
    for (int i = 0; i < 4; i++)
#pragma unroll
        for (int j = 0; j < 4; j++)
#pragma unroll
            for (int k = 0; k < 4; k++) acc[i][j][k] = 0.f;

    // staging: thread -> row = tid>>1 (0..127), k-half = tid&1 (16 floats)
    const int s_r = tid >> 1;
    const int s_h = tid & 1;
    const float* Ap = A + (size_t)(m0 + s_r) * lda + s_h * 16;
    const float* Bp = B + (size_t)(n0 + s_r) * ldb + s_h * 16;
    const uint32_t s_off = (uint32_t)(s_r * TG_PITCH + s_h * 32);

    // ldmatrix lane-address offsets
    const int q  = lane >> 3;
    const int r8 = lane & 7;
    const uint32_t a_off = (uint32_t)((wm * 64 + (q & 1) * 8 + r8) * TG_PITCH + (q >> 1) * 16);
    const uint32_t b_off = (uint32_t)((wn * 32 + (q >> 1) * 8 + r8) * TG_PITCH + (q & 1) * 16);

    const int chunks = K >> 5;

    // prologue: stage chunk 0 into buffer 0
    float4 pa[4], pb[4];
#pragma unroll
    for (int i = 0; i < 4; i++) {
        pa[i] = ((const float4*)Ap)[i];
        pb[i] = ((const float4*)Bp)[i];
    }
    cvt_store(sb + s_off,                 sb + TG_REGION   + s_off, pa);
    cvt_store(sb + 2*TG_REGION + s_off,   sb + 3*TG_REGION + s_off, pb);
    __syncthreads();

    for (int c = 0; c < chunks; c++) {
        const uint32_t sbuf = sb + (uint32_t)(c & 1) * TG_BUFSTRIDE;
        const bool nxt = (c + 1 < chunks);
        if (nxt) {
            const float* Ap2 = Ap + (c + 1) * 32;
            const float* Bp2 = Bp + (c + 1) * 32;
#pragma unroll
            for (int i = 0; i < 4; i++) {
                pa[i] = ((const float4*)Ap2)[i];
                pb[i] = ((const float4*)Bp2)[i];
            }
        }

#pragma unroll
        for (int ks = 0; ks < 2; ks++) {
            const uint32_t kso = (uint32_t)(ks * 32);
            uint32_t bh[2][4], bl[2][4];
            ldsm4(bh[0], sbuf + 2*TG_REGION + b_off + kso);
            ldsm4(bh[1], sbuf + 2*TG_REGION + b_off + 16*TG_PITCH + kso);
            ldsm4(bl[0], sbuf + 3*TG_REGION + b_off + kso);
            ldsm4(bl[1], sbuf + 3*TG_REGION + b_off + 16*TG_PITCH + kso);
#pragma unroll
            for (int mt = 0; mt < 4; mt++) {
                uint32_t ah[4], al[4];
                ldsm4(ah, sbuf +             a_off + mt*16*TG_PITCH + kso);
                ldsm4(al, sbuf + TG_REGION + a_off + mt*16*TG_PITCH + kso);
#pragma unroll
                for (int nt = 0; nt < 4; nt++) {
                    const uint32_t* bhp = &bh[nt >> 1][(nt & 1) * 2];
                    const uint32_t* blp = &bl[nt >> 1][(nt & 1) * 2];
                    mma_bf16(acc[mt][nt], ah, bhp);
                    mma_bf16(acc[mt][nt], ah, blp);
                    mma_bf16(acc[mt][nt], al, bhp);
                }
            }
        }

        if (nxt) {
            const uint32_t dbuf = sb + (uint32_t)((c + 1) & 1) * TG_BUFSTRIDE;
            cvt_store(dbuf + s_off,               dbuf + TG_REGION   + s_off, pa);
            cvt_store(dbuf + 2*TG_REGION + s_off, dbuf + 3*TG_REGION + s_off, pb);
        }
        __syncthreads();
    }

    // epilogue: c-frag regs {0,1} -> row er, {2,3} -> row er+8; cols ec, ec+1
    const int er = lane >> 2;
    const int ec = (lane & 3) * 2;
    const int colbase = n0 + wn * 32 + ec;
#pragma unroll
    for (int mt = 0; mt < 4; mt++) {
#pragma unroll
        for (int half = 0; half < 2; half++) {
            const int row = m0 + wm * 64 + mt * 16 + er + half * 8;
            float* cp = C + (size_t)row * ldc + colbase;
            const float* rv = rowvec ? rowvec + (size_t)(row >> 10) * ldc + colbase
                                     : nullptr;
#pragma unroll
            for (int nt = 0; nt < 4; nt++) {
                float v0 = acc[mt][nt][half * 2 + 0];
                float v1 = acc[mt][nt][half * 2 + 1];
                const int co = nt * 8;
                if (bias) { v0 += bias[colbase + co]; v1 += bias[colbase + co + 1]; }
                if (rv)   { v0 += rv[co];             v1 += rv[co + 1]; }
                if (beta) { v0 += cp[co];             v1 += cp[co + 1]; }
                *(float2*)(cp + co) = make_float2(v0, v1);
            }
        }
    }
}

// ============================================================================
// SIMT SGEMM (fmaf, BK=16, double-buffered) — small GEMMs only
// ============================================================================
template<bool BKXN>
__global__ __launch_bounds__(256, 2)
void sgemm_k(const float* __restrict__ A, int lda,
             const float* __restrict__ B, int ldb,
             float* __restrict__ C, int ldc,
             const float* __restrict__ bias,
             const float* __restrict__ rowvec,
             int M, int N, int K,
             int beta, int do_softplus)
{
    __shared__ float As[2][16][128];
    __shared__ float Bs[2][16][128];

    const int tid = threadIdx.x;
    const int m0 = blockIdx.y * 128;
    const int n0 = blockIdx.x * 128;
    const int ty = tid >> 4;
    const int tx = tid & 15;

    const int a_r = tid >> 2;
    const int a_c = (tid & 3) * 4;
    const int b_r = a_r;
    const int b_c = a_c;
    const int bk_r = tid >> 5;
    const int bk_c = (tid & 31) * 4;

    float acc[8][8];
#pragma unroll
    for (int i = 0; i < 8; i++)
#pragma unroll
        for (int j = 0; j < 8; j++) acc[i][j] = 0.f;

    const float* Ab = A + (size_t)m0 * lda;
    float4 a0, a1, b0, b1;

    a0 = *(const float4*)(Ab + (size_t)a_r * lda + a_c);
    a1 = *(const float4*)(Ab + (size_t)(a_r + 64) * lda + a_c);
    if (BKXN) {
        b0 = make_float4(0.f, 0.f, 0.f, 0.f); b1 = b0;
        if (n0 + bk_c < N) {
            b0 = *(const float4*)(B + (size_t)bk_r * ldb + n0 + bk_c);
            b1 = *(const float4*)(B + (size_t)(bk_r + 8) * ldb + n0 + bk_c);
        }
    } else {
        b0 = make_float4(0.f, 0.f, 0.f, 0.f); b1 = b0;
        if (n0 + b_r < N)
            b0 = *(const float4*)(B + (size_t)(n0 + b_r) * ldb + b_c);
        if (n0 + b_r + 64 < N)
            b1 = *(const float4*)(B + (size_t)(n0 + b_r + 64) * ldb + b_c);
    }
    {
        As[0][a_c + 0][a_r] = a0.x; As[0][a_c + 1][a_r] = a0.y;
        As[0][a_c + 2][a_r] = a0.z; As[0][a_c + 3][a_r] = a0.w;
        As[0][a_c + 0][a_r + 64] = a1.x; As[0][a_c + 1][a_r + 64] = a1.y;
        As[0][a_c + 2][a_r + 64] = a1.z; As[0][a_c + 3][a_r + 64] = a1.w;
        if (BKXN) {
            *(float4*)&Bs[0][bk_r][bk_c]     = b0;
            *(float4*)&Bs[0][bk_r + 8][bk_c] = b1;
        } else {
            Bs[0][b_c + 0][b_r] = b0.x; Bs[0][b_c + 1][b_r] = b0.y;
            Bs[0][b_c + 2][b_r] = b0.z; Bs[0][b_c + 3][b_r] = b0.w;
            Bs[0][b_c + 0][b_r + 64] = b1.x; Bs[0][b_c + 1][b_r + 64] = b1.y;
            Bs[0][b_c + 2][b_r + 64] = b1.z; Bs[0][b_c + 3][b_r + 64] = b1.w;
        }
    }
    __syncthreads();

    int buf = 0;
    for (int k0 = 0; k0 < K; k0 += 16) {
        const bool nxt = (k0 + 16 < K);
        if (nxt) {
            const int kn = k0 + 16;
            a0 = *(const float4*)(Ab + (size_t)a_r * lda + kn + a_c);
            a1 = *(const float4*)(Ab + (size_t)(a_r + 64) * lda + kn + a_c);
            if (BKXN) {
                b0 = make_float4(0.f, 0.f, 0.f, 0.f); b1 = b0;
                if (n0 + bk_c < N) {
                    b0 = *(const float4*)(B + (size_t)(kn + bk_r) * ldb + n0 + bk_c);
                    b1 = *(const float4*)(B + (size_t)(kn + bk_r + 8) * ldb + n0 + bk_c);
                }
            } else {
                b0 = make_float4(0.f, 0.f, 0.f, 0.f); b1 = b0;
                if (n0 + b_r < N)
                    b0 = *(const float4*)(B + (size_t)(n0 + b_r) * ldb + kn + b_c);
                if (n0 + b_r + 64 < N)
                    b1 = *(const float4*)(B + (size_t)(n0 + b_r + 64) * ldb + kn + b_c);
            }
        }

#pragma unroll
        for (int kk = 0; kk < 16; kk++) {
            float arr[8], brr[8];
            *(float4*)&arr[0] = *(const float4*)&As[buf][kk][ty * 8];
            *(float4*)&arr[4] = *(const float4*)&As[buf][kk][ty * 8 + 4];
            *(float4*)&brr[0] = *(const float4*)&Bs[buf][kk][tx * 8];
            *(float4*)&brr[4] = *(const float4*)&Bs[buf][kk][tx * 8 + 4];
#pragma unroll
            for (int i = 0; i < 8; i++)
#pragma unroll
                for (int j = 0; j < 8; j++)
                    acc[i][j] = fmaf(arr[i], brr[j], acc[i][j]);
        }

        if (nxt) {
            const int nb = buf ^ 1;
            As[nb][a_c + 0][a_r] = a0.x; As[nb][a_c + 1][a_r] = a0.y;
            As[nb][a_c + 2][a_r] = a0.z; As[nb][a_c + 3][a_r] = a0.w;
            As[nb][a_c + 0][a_r + 64] = a1.x; As[nb][a_c + 1][a_r + 64] = a1.y;
            As[nb][a_c + 2][a_r + 64] = a1.z; As[nb][a_c + 3][a_r + 64] = a1.w;
            if (BKXN) {
                *(float4*)&Bs[nb][bk_r][bk_c]     = b0;
                *(float4*)&Bs[nb][bk_r + 8][bk_c] = b1;
            } else {
                Bs[nb][b_c + 0][b_r] = b0.x; Bs[nb][b_c + 1][b_r] = b0.y;
                Bs[nb][b_c + 2][b_r] = b0.z; Bs[nb][b_c + 3][b_r] = b0.w;
                Bs[nb][b_c + 0][b_r + 64] = b1.x; Bs[nb][b_c + 1][b_r + 64] = b1.y;
                Bs[nb][b_c + 2][b_r + 64] = b1.z; Bs[nb][b_c + 3][b_r + 64] = b1.w;
            }
            __syncthreads();
            buf = nb;
        }
    }

    const int col = n0 + tx * 8;
    if (col >= N) return;

#pragma unroll
    for (int i = 0; i < 8; i++) {
        const int row = m0 + ty * 8 + i;
        float* cp = C + (size_t)row * ldc + col;
        float v[8];
#pragma unroll
        for (int j = 0; j < 8; j++) {
            float t = acc[i][j];
            if (bias)   t += bias[col + j];
            if (rowvec) t += rowvec[(row >> 10) * ldc + col + j];
            if (beta)   t += cp[j];
            if (do_softplus) t = softplusf(t);
            v[j] = t;
        }
        *(float4*)cp       = *(float4*)&v[0];
        *(float4*)(cp + 4) = *(float4*)&v[4];
    }
}

// ---------------- layernorm (C = 512, 128 threads/row) ----------------
__global__ void layernorm_k(const float* __restrict__ x,
                            const float* __restrict__ w,
                            const float* __restrict__ b,
                            float* __restrict__ out)
{
    const int row = blockIdx.x;
    const int tid = threadIdx.x;
    float4 v = ((const float4*)(x + (size_t)row * 512))[tid];
    float s  = v.x + v.y + v.z + v.w;
    float sq = v.x * v.x + v.y * v.y + v.z * v.z + v.w * v.w;
#pragma unroll
    for (int o = 16; o > 0; o >>= 1) {
        s  += __shfl_xor_sync(0xffffffffu, s,  o);
        sq += __shfl_xor_sync(0xffffffffu, sq, o);
    }
    __shared__ float ss[4], ssq[4];
    const int wid = tid >> 5;
    if ((tid & 31) == 0) { ss[wid] = s; ssq[wid] = sq; }
    __syncthreads();
    s  = ss[0]  + ss[1]  + ss[2]  + ss[3];
    sq = ssq[0] + ssq[1] + ssq[2] + ssq[3];
    const float m   = s  * (1.f / 512.f);
    const float var = sq * (1.f / 512.f) - m * m;
    const float inv = rsqrtf(var + 1e-5f);
    float4 wv = ((const float4*)w)[tid];
    float4 bv = ((const float4*)b)[tid];
    float4 o4;
    o4.x = (v.x - m) * inv * wv.x + bv.x;
    o4.y = (v.y - m) * inv * wv.y + bv.y;
    o4.z = (v.z - m) * inv * wv.z + bv.z;
    o4.w = (v.w - m) * inv * wv.w + bv.w;
    ((float4*)(out + (size_t)row * 512))[tid] = o4;
}

// ---------------- rmsnorm + silu, in place (C = 512) ----------------
__global__ void rmsnorm_silu_k(float* __restrict__ x, const float* __restrict__ w)
{
    const int row = blockIdx.x;
    const int tid = threadIdx.x;
    float4 v = ((const float4*)(x + (size_t)row * 512))[tid];
    float sq = v.x * v.x + v.y * v.y + v.z * v.z + v.w * v.w;
#pragma unroll
    for (int o = 16; o > 0; o >>= 1) sq += __shfl_xor_sync(0xffffffffu, sq, o);
    __shared__ float ssq[4];
    const int wid = tid >> 5;
    if ((tid & 31) == 0) ssq[wid] = sq;
    __syncthreads();
    sq = ssq[0] + ssq[1] + ssq[2] + ssq[3];
    const float inv = rsqrtf(sq * (1.f / 512.f) + 1e-5f);
    float4 wv = ((const float4*)w)[tid];
    float4 o4;
    float a;
    a = v.x * inv * wv.x; o4.x = siluf(a);
    a = v.y * inv * wv.y; o4.y = siluf(a);
    a = v.z * inv * wv.z; o4.z = siluf(a);
    a = v.w * inv * wv.w; o4.w = siluf(a);
    ((float4*)(x + (size_t)row * 512))[tid] = o4;
}

// ---------------- up rearrange: [b,l, o*2+k] -> [b, 2l+k, o] (+b_up) ----------------
__global__ void up_rearrange_k(const float* __restrict__ up_tmp,
                               const float* __restrict__ b_up,
                               float* __restrict__ up)
{
    const int idx  = blockIdx.x * blockDim.x + threadIdx.x;
    const int o    = idx & 511;
    const int orow = idx >> 9;
    const int b    = orow >> 10;
    const int t    = orow & 1023;
    const int l    = t >> 1;
    const int k    = t & 1;
    up[idx] = up_tmp[(size_t)(b * 512 + l) * 1024 + o * 2 + k] + b_up[o];
}

// ---------------- causal depthwise conv(4) + bias + silu ----------------
__global__ void conv_silu_k(const float* __restrict__ xz,
                            const float* __restrict__ cw,
                            const float* __restrict__ cb,
                            float* __restrict__ xc)
{
    const int idx = blockIdx.x * blockDim.x + threadIdx.x;
    const int d   = idx & 1023;
    const int row = idx >> 10;
    const int t   = row & 1023;
    float acc = cb[d];
#pragma unroll
    for (int j = 0; j < 4; j++) {
        const int tt = t - 3 + j;
        if (tt >= 0)
            acc = fmaf(cw[d * 4 + j], xz[(size_t)(row - 3 + j) * 2048 + d], acc);
    }
    xc[idx] = siluf(acc);
}

// ---------------- selective scan ----------------
__global__ __launch_bounds__(128)
void scan_k(const float* __restrict__ dt,
            const float* __restrict__ xc,
            const float* __restrict__ xz,
            const float* __restrict__ xdbc,
            const float* __restrict__ A_log,
            const float* __restrict__ Dp,
            float* __restrict__ y)
{
    __shared__ __align__(16) float bc_s[32][32];

    const int tid    = threadIdx.x;
    const int half   = tid & 1;
    const int dloc   = tid >> 1;
    const int b      = blockIdx.x >> 4;
    const int d      = (blockIdx.x & 15) * 64 + dloc;
    const int n0     = half * 8;

    float A2[8], h[8];
#pragma unroll
    for (int j = 0; j < 8; j++) {
        A2[j] = -__expf(A_log[d * 16 + n0 + j]) * 1.44269504f;
        h[j]  = 0.f;
    }
    const float Dd = Dp[d];

    const float* dtp = dt   + (size_t)b * 1024 * 1024 + d;
    const float* up  = xc   + (size_t)b * 1024 * 1024 + d;
    const float* zp  = xz   + (size_t)b * 1024 * 2048 + 1024 + d;
    const float* bcb = xdbc + (size_t)b * 1024 * 64 + 32;
    float*       yp  = y    + (size_t)b * 1024 * 1024 + d;

    const int st_t = tid >> 2;
    const int st_c = (tid & 3) * 8;

    for (int c = 0; c < 32; c++) {
        __syncthreads();
        {
            const float* src = bcb + (size_t)(c * 32 + st_t) * 64 + st_c;
            *(float4*)&bc_s[st_t][st_c]     = *(const float4*)src;
            *(float4*)&bc_s[st_t][st_c + 4] = *(const float4*)(src + 4);
        }
        __syncthreads();

#pragma unroll
        for (int s = 0; s < 4; s++) {
            const int tbase = c * 32 + s * 8;
            float dt8[8], u8[8], z8[8];
#pragma unroll
            for (int j = 0; j < 8; j++) {
                dt8[j] = dtp[(size_t)(tbase + j) * 1024];
                u8[j]  = up [(size_t)(tbase + j) * 1024];
                z8[j]  = zp [(size_t)(tbase + j) * 2048];
            }
#pragma unroll
            for (int j = 0; j < 8; j++) {
                const int tt = s * 8 + j;
                float Bv[8], Cv[8];
                *(float4*)&Bv[0] = *(const float4*)&bc_s[tt][n0];
                *(float4*)&Bv[4] = *(const float4*)&bc_s[tt][n0 + 4];
                *(float4*)&Cv[0] = *(const float4*)&bc_s[tt][16 + n0];
                *(float4*)&Cv[4] = *(const float4*)&bc_s[tt][16 + n0 + 4];
                const float dtv = dt8[j];
                const float u   = u8[j];
                const float du  = dtv * u;
                float ya = 0.f, yb2 = 0.f;
#pragma unroll
                for (int n = 0; n < 8; n++) {
                    const float dA = exp2f(dtv * A2[n]);
                    h[n] = fmaf(dA, h[n], du * Bv[n]);
                    if (n & 1) yb2 = fmaf(h[n], Cv[n], yb2);
                    else       ya  = fmaf(h[n], Cv[n], ya);
                }
                float ysum = ya + yb2;
                ysum += __shfl_xor_sync(0xffffffffu, ysum, 1);
                if (half == 0)
                    yp[(size_t)(tbase + j) * 1024] = (ysum + u * Dd) * siluf(z8[j]);
            }
        }
    }
}

// ---------------- launcher ----------------
extern "C" void kernel_launch(void* const* d_in, const int* in_sizes, int n_in,
                              void* d_out, int out_size)
{
    (void)in_sizes; (void)n_in; (void)out_size;

    const float* motion     = (const float*)d_in[0];
    const float* skip       = (const float*)d_in[1];
    const float* embed      = (const float*)d_in[2];
    const float* w_up       = (const float*)d_in[3];
    const float* b_up       = (const float*)d_in[4];
    const float* w1         = (const float*)d_in[5];
    const float* b1         = (const float*)d_in[6];
    const float* rms_w      = (const float*)d_in[7];
    const float* w2         = (const float*)d_in[8];
    const float* b2         = (const float*)d_in[9];
    const float* ln_w       = (const float*)d_in[10];
    const float* ln_b       = (const float*)d_in[11];
    const float* in_proj_w  = (const float*)d_in[12];
    const float* conv_w     = (const float*)d_in[13];
    const float* conv_b     = (const float*)d_in[14];
    const float* x_proj_w   = (const float*)d_in[15];
    const float* dt_proj_w  = (const float*)d_in[16];
    const float* dt_proj_b  = (const float*)d_in[17];
    const float* A_log      = (const float*)d_in[18];
    const float* D_param    = (const float*)d_in[19];
    const float* out_proj_w = (const float*)d_in[20];
    const float* out_proj_b = (const float*)d_in[21];
    const float* norm_f_w   = (const float*)d_in[22];
    const float* norm_f_b   = (const float*)d_in[23];
    float* out = (float*)d_out;

    float *up_tmp, *up, *h, *x, *ln, *xz, *xc, *xdbc, *dtb, *yb;
    cudaGetSymbolAddress((void**)&up_tmp, g_up_tmp);
    cudaGetSymbolAddress((void**)&up,     g_up);
    cudaGetSymbolAddress((void**)&h,      g_h);
    cudaGetSymbolAddress((void**)&x,      g_x);
    cudaGetSymbolAddress((void**)&ln,     g_ln);
    cudaGetSymbolAddress((void**)&xz,     g_xz);
    cudaGetSymbolAddress((void**)&xc,     g_xc);
    cudaGetSymbolAddress((void**)&xdbc,   g_xdbc);
    cudaGetSymbolAddress((void**)&dtb,    g_dt);
    cudaGetSymbolAddress((void**)&yb,     g_y);

    cudaFuncSetAttribute(tgemm_k, cudaFuncAttributeMaxDynamicSharedMemorySize,
                         TG_SMEM_BYTES);

    // 1) up = motion @ w_up   (A[4096,512] @ B[512,1024] K-major) — SIMT
    sgemm_k<true><<<dim3(1024/128, 4096/128), 256>>>(
        motion, 512, w_up, 1024, up_tmp, 1024,
        nullptr, nullptr, 4096, 1024, 512, 0, 0);

    // 2) rearrange [b,l,(o,k)] -> tokens, add b_up
    up_rearrange_k<<<(ROWS * 512) / 256, 256>>>(up_tmp, b_up, up);

    // 3) h = up @ w1[:, :512]^T + b1 ; h += skip @ w1[:, 512:]^T   — tensor
    tgemm_k<<<dim3(4, 64), 256, TG_SMEM_BYTES>>>(
        up, 512, w1, 1024, h, 512, b1, nullptr, 512, 0);
    tgemm_k<<<dim3(4, 64), 256, TG_SMEM_BYTES>>>(
        skip, 512, w1 + 512, 1024, h, 512, nullptr, nullptr, 512, 1);

    // 4) h = silu(rmsnorm(h, rms_w)) in place
    rmsnorm_silu_k<<<ROWS, 128>>>(h, rms_w);

    // 5) x = h @ w2^T + b2 + embed[b]   — tensor
    tgemm_k<<<dim3(4, 64), 256, TG_SMEM_BYTES>>>(
        h, 512, w2, 512, x, 512, b2, embed, 512, 0);

    // 6) mamba layers
    for (int i = 0; i < NDEPTH; i++) {
        layernorm_k<<<ROWS, 128>>>(x, ln_w + i * 512, ln_b + i * 512, ln);

        tgemm_k<<<dim3(16, 64), 256, TG_SMEM_BYTES>>>(
            ln, 512, in_proj_w + (size_t)i * 2048 * 512, 512,
            xz, 2048, nullptr, nullptr, 512, 0);

        conv_silu_k<<<(ROWS * DI) / 256, 256>>>(
            xz, conv_w + (size_t)i * 1024 * 4, conv_b + i * 1024, xc);

        sgemm_k<false><<<dim3(1, 64), 256>>>(
            xc, 1024, x_proj_w + (size_t)i * 64 * 1024, 1024,
            xdbc, 64, nullptr, nullptr, ROWS, 64, 1024, 0, 0);

        sgemm_k<false><<<dim3(8, 64), 256>>>(
            xdbc, 64, dt_proj_w + (size_t)i * 1024 * 32, 32,
            dtb, 1024, dt_proj_b + i * 1024, nullptr, ROWS, 1024, 32, 0, 1);

        scan_k<<<128, 128>>>(
            dtb, xc, xz, xdbc,
            A_log + (size_t)i * 1024 * 16, D_param + i * 1024, yb);

        tgemm_k<<<dim3(4, 64), 256, TG_SMEM_BYTES>>>(
            yb, 1024, out_proj_w + (size_t)i * 512 * 1024, 1024,
            x, 512, out_proj_b + i * 512, nullptr, 1024, 1);
    }

    // 7) final layernorm -> output
    layernorm_k<<<ROWS, 128>>>(x, norm_f_w, norm_f_b, out);
}

// round 10
// speedup vs baseline: 1.6431x; 1.1976x over previous
#include <cuda_runtime.h>
#include <cuda_bf16.h>
#include <math.h>
#include <stdint.h>

// ---------------- problem constants ----------------
#define BB    8
#define LSEQ  1024            // 2*L_IN
#define ROWS  (BB*LSEQ)       // 8192 tokens
#define CC    512
#define DI    1024
#define DS    16
#define NDEPTH 4

// ---------------- scratch (device globals; no allocs allowed) ----------------
__device__ float g_up_tmp[4096*1024];   // up GEMM raw output [b*512+l, o*2+k]
__device__ float g_up   [ROWS*CC];      // rearranged up tokens
__device__ float g_h    [ROWS*CC];      // h1 / post-rms-silu
__device__ float g_x    [ROWS*CC];      // residual stream
__device__ float g_ln   [ROWS*CC];      // per-layer layernorm out
__device__ float g_xz   [ROWS*2*DI];    // in_proj out (xc_raw | z)
__device__ float g_xc   [ROWS*DI];      // conv+silu out (u)
__device__ float g_xdbc [ROWS*128];     // x_proj out (dtp|B|C|pad), ld=128
__device__ float g_dt   [ROWS*DI];      // softplus dt
__device__ float g_y    [ROWS*DI];      // scan out * silu(z)
__device__ float g_wupT [1024*512];     // w_up transposed to [N,K]
__device__ float g_xpw  [128*1024];     // x_proj_w padded to 128 rows

// ---------------- helpers ----------------
__device__ __forceinline__ float softplusf(float x) {
    return (x > 20.f) ? x : log1pf(__expf(x));
}
__device__ __forceinline__ float siluf(float x) {
    return x / (1.f + __expf(-x));
}

__device__ __forceinline__ uint32_t smem_u32(const void* p) {
    uint32_t a;
    asm("{ .reg .u64 t; cvta.to.shared.u64 t, %1; cvt.u32.u64 %0, t; }"
        : "=r"(a) : "l"(p));
    return a;
}

// split f32x4 into bf16 hi / lo pairs (packed bf16x2 words, .x in low half)
__device__ __forceinline__ void split4(float4 v, uint32_t& h01, uint32_t& h23,
                                       uint32_t& l01, uint32_t& l23) {
    __nv_bfloat162 h0 = __float22bfloat162_rn(make_float2(v.x, v.y));
    __nv_bfloat162 h1 = __float22bfloat162_rn(make_float2(v.z, v.w));
    float2 f0 = __bfloat1622float2(h0), f1 = __bfloat1622float2(h1);
    __nv_bfloat162 l0 = __float22bfloat162_rn(make_float2(v.x - f0.x, v.y - f0.y));
    __nv_bfloat162 l1 = __float22bfloat162_rn(make_float2(v.z - f1.x, v.w - f1.y));
    h01 = *(uint32_t*)&h0; h23 = *(uint32_t*)&h1;
    l01 = *(uint32_t*)&l0; l23 = *(uint32_t*)&l1;
}

__device__ __forceinline__ void ldsm4(uint32_t* r, uint32_t addr) {
    asm volatile("ldmatrix.sync.aligned.m8n8.x4.shared.b16 {%0,%1,%2,%3}, [%4];"
        : "=r"(r[0]), "=r"(r[1]), "=r"(r[2]), "=r"(r[3]) : "r"(addr));
}

__device__ __forceinline__ void mma_bf16(float* c, const uint32_t* a, const uint32_t* b) {
    asm volatile("mma.sync.aligned.m16n8k16.row.col.f32.bf16.bf16.f32 "
        "{%0,%1,%2,%3}, {%4,%5,%6,%7}, {%8,%9}, {%0,%1,%2,%3};"
        : "+f"(c[0]), "+f"(c[1]), "+f"(c[2]), "+f"(c[3])
        : "r"(a[0]), "r"(a[1]), "r"(a[2]), "r"(a[3]), "r"(b[0]), "r"(b[1]));
}

// convert 16 f32 (4 float4) -> 16 bf16 hi + 16 bf16 lo, store 2x v4 each
__device__ __forceinline__ void cvt_store(uint32_t dst_hi, uint32_t dst_lo,
                                          const float4* p) {
    uint32_t h[8], l[8];
#pragma unroll
    for (int i = 0; i < 4; i++)
        split4(p[i], h[2*i], h[2*i+1], l[2*i], l[2*i+1]);
    asm volatile("st.shared.v4.b32 [%0], {%1,%2,%3,%4};"
                 :: "r"(dst_hi),      "r"(h[0]), "r"(h[1]), "r"(h[2]), "r"(h[3]));
    asm volatile("st.shared.v4.b32 [%0], {%1,%2,%3,%4};"
                 :: "r"(dst_hi + 16), "r"(h[4]), "r"(h[5]), "r"(h[6]), "r"(h[7]));
    asm volatile("st.shared.v4.b32 [%0], {%1,%2,%3,%4};"
                 :: "r"(dst_lo),      "r"(l[0]), "r"(l[1]), "r"(l[2]), "r"(l[3]));
    asm volatile("st.shared.v4.b32 [%0], {%1,%2,%3,%4};"
                 :: "r"(dst_lo + 16), "r"(l[4]), "r"(l[5]), "r"(l[6]), "r"(l[7]));
}

// ============================================================================
// tensor-core GEMM (mma.sync bf16, split-bf16 3-term ~fp32 precision)
// C[M,N] = A[M,K] @ B[N,K]^T  (+bias[col]) (+rowvec[(row>>10)*ldc+col]) (+beta*C)
// M, N multiples of 128; K multiple of 32. Block 128x128, BK=32, 8 warps.
// SINGLE smem buffer (40KB) + __launch_bounds__(256,2) -> 2 CTAs/SM;
// cross-CTA overlap hides the stage/sync bubble.
// smem rows pitched 80B (32 bf16 + 16B pad) -> conflict-free ldmatrix.
// regions: AH 0, AL 10240, BH 20480, BL 30720.
// ============================================================================
#define TG_PITCH     80
#define TG_REGION    10240
#define TG_SMEM_BYTES 40960

__global__ __launch_bounds__(256, 2)
void tgemm_k(const float* __restrict__ A, int lda,
             const float* __restrict__ B, int ldb,
             float* __restrict__ C, int ldc,
             const float* __restrict__ bias,
             const float* __restrict__ rowvec,
             int K, int beta)
{
    extern __shared__ __align__(16) char smem[];
    const uint32_t sb = smem_u32(smem);
    const int tid  = threadIdx.x;
    const int wid  = tid >> 5;
    const int lane = tid & 31;
    const int m0 = blockIdx.y * 128;
    const int n0 = blockIdx.x * 128;
    const int wm = wid >> 2;          // 0..1 -> 64 rows
    const int wn = wid & 3;           // 0..3 -> 32 cols

    float acc[4][4][4];
#pragma unroll
    for (int i = 0; i < 4; i++)
#pragma unroll
        for (int j = 0; j < 4; j++)
#pragma unroll
            for (int k = 0; k < 4; k++) acc[i][j][k] = 0.f;

    // staging: thread -> row = tid>>1 (0..127), k-half = tid&1 (16 floats)
    const int s_r = tid >> 1;
    const int s_h = tid & 1;
    const float* Ap = A + (size_t)(m0 + s_r) * lda + s_h * 16;
    const float* Bp = B + (size_t)(n0 + s_r) * ldb + s_h * 16;
    const uint32_t s_off = (uint32_t)(s_r * TG_PITCH + s_h * 32);

    // ldmatrix lane-address offsets
    const int q  = lane >> 3;
    const int r8 = lane & 7;
    const uint32_t a_off = (uint32_t)((wm * 64 + (q & 1) * 8 + r8) * TG_PITCH + (q >> 1) * 16);
    const uint32_t b_off = (uint32_t)((wn * 32 + (q >> 1) * 8 + r8) * TG_PITCH + (q & 1) * 16);

    const int chunks = K >> 5;

    for (int c = 0; c < chunks; c++) {
        // issue next-chunk LDGs BEFORE the barrier: latency hides under the wait
        float4 pa[4], pb[4];
        {
            const float* Ap2 = Ap + c * 32;
            const float* Bp2 = Bp + c * 32;
#pragma unroll
            for (int i = 0; i < 4; i++) {
                pa[i] = ((const float4*)Ap2)[i];
                pb[i] = ((const float4*)Bp2)[i];
            }
        }
        __syncthreads();   // all warps done reading smem from chunk c-1
        cvt_store(sb + s_off,               sb + TG_REGION   + s_off, pa);
        cvt_store(sb + 2*TG_REGION + s_off, sb + 3*TG_REGION + s_off, pb);
        __syncthreads();   // tile staged

#pragma unroll
        for (int ks = 0; ks < 2; ks++) {
            const uint32_t kso = (uint32_t)(ks * 32);
            uint32_t bh[2][4], bl[2][4];
            ldsm4(bh[0], sb + 2*TG_REGION + b_off + kso);
            ldsm4(bh[1], sb + 2*TG_REGION + b_off + 16*TG_PITCH + kso);
            ldsm4(bl[0], sb + 3*TG_REGION + b_off + kso);
            ldsm4(bl[1], sb + 3*TG_REGION + b_off + 16*TG_PITCH + kso);
#pragma unroll
            for (int mt = 0; mt < 4; mt++) {
                uint32_t ah[4], al[4];
                ldsm4(ah, sb +             a_off + mt*16*TG_PITCH + kso);
                ldsm4(al, sb + TG_REGION + a_off + mt*16*TG_PITCH + kso);
#pragma unroll
                for (int nt = 0; nt < 4; nt++) {
                    const uint32_t* bhp = &bh[nt >> 1][(nt & 1) * 2];
                    const uint32_t* blp = &bl[nt >> 1][(nt & 1) * 2];
                    mma_bf16(acc[mt][nt], ah, bhp);
                    mma_bf16(acc[mt][nt], ah, blp);
                    mma_bf16(acc[mt][nt], al, bhp);
                }
            }
        }
    }

    // epilogue: c-frag regs {0,1} -> row er, {2,3} -> row er+8; cols ec, ec+1
    const int er = lane >> 2;
    const int ec = (lane & 3) * 2;
    const int colbase = n0 + wn * 32 + ec;
#pragma unroll
    for (int mt = 0; mt < 4; mt++) {
#pragma unroll
        for (int half = 0; half < 2; half++) {
            const int row = m0 + wm * 64 + mt * 16 + er + half * 8;
            float* cp = C + (size_t)row * ldc + colbase;
            const float* rv = rowvec ? rowvec + (size_t)(row >> 10) * ldc + colbase
                                     : nullptr;
#pragma unroll
            for (int nt = 0; nt < 4; nt++) {
                float v0 = acc[mt][nt][half * 2 + 0];
                float v1 = acc[mt][nt][half * 2 + 1];
                const int co = nt * 8;
                if (bias) { v0 += bias[colbase + co]; v1 += bias[colbase + co + 1]; }
                if (rv)   { v0 += rv[co];             v1 += rv[co + 1]; }
                if (beta) { v0 += cp[co];             v1 += cp[co + 1]; }
                *(float2*)(cp + co) = make_float2(v0, v1);
            }
        }
    }
}

// ============================================================================
// SIMT SGEMM (fmaf, BK=16, double-buffered) — dt_proj only now
// ============================================================================
__global__ __launch_bounds__(256, 2)
void sgemm_k(const float* __restrict__ A, int lda,
             const float* __restrict__ B, int ldb,
             float* __restrict__ C, int ldc,
             const float* __restrict__ bias,
             const float* __restrict__ rowvec,
             int M, int N, int K,
             int beta, int do_softplus)
{
    __shared__ float As[2][16][128];
    __shared__ float Bs[2][16][128];

    const int tid = threadIdx.x;
    const int m0 = blockIdx.y * 128;
    const int n0 = blockIdx.x * 128;
    const int ty = tid >> 4;
    const int tx = tid & 15;

    const int a_r = tid >> 2;
    const int a_c = (tid & 3) * 4;
    const int b_r = a_r;
    const int b_c = a_c;

    float acc[8][8];
#pragma unroll
    for (int i = 0; i < 8; i++)
#pragma unroll
        for (int j = 0; j < 8; j++) acc[i][j] = 0.f;

    const float* Ab = A + (size_t)m0 * lda;
    float4 a0, a1, b0, b1;

    a0 = *(const float4*)(Ab + (size_t)a_r * lda + a_c);
    a1 = *(const float4*)(Ab + (size_t)(a_r + 64) * lda + a_c);
    b0 = make_float4(0.f, 0.f, 0.f, 0.f); b1 = b0;
    if (n0 + b_r < N)
        b0 = *(const float4*)(B + (size_t)(n0 + b_r) * ldb + b_c);
    if (n0 + b_r + 64 < N)
        b1 = *(const float4*)(B + (size_t)(n0 + b_r + 64) * ldb + b_c);
    {
        As[0][a_c + 0][a_r] = a0.x; As[0][a_c + 1][a_r] = a0.y;
        As[0][a_c + 2][a_r] = a0.z; As[0][a_c + 3][a_r] = a0.w;
        As[0][a_c + 0][a_r + 64] = a1.x; As[0][a_c + 1][a_r + 64] = a1.y;
        As[0][a_c + 2][a_r + 64] = a1.z; As[0][a_c + 3][a_r + 64] = a1.w;
        Bs[0][b_c + 0][b_r] = b0.x; Bs[0][b_c + 1][b_r] = b0.y;
        Bs[0][b_c + 2][b_r] = b0.z; Bs[0][b_c + 3][b_r] = b0.w;
        Bs[0][b_c + 0][b_r + 64] = b1.x; Bs[0][b_c + 1][b_r + 64] = b1.y;
        Bs[0][b_c + 2][b_r + 64] = b1.z; Bs[0][b_c + 3][b_r + 64] = b1.w;
    }
    __syncthreads();

    int buf = 0;
    for (int k0 = 0; k0 < K; k0 += 16) {
        const bool nxt = (k0 + 16 < K);
        if (nxt) {
            const int kn = k0 + 16;
            a0 = *(const float4*)(Ab + (size_t)a_r * lda + kn + a_c);
            a1 = *(const float4*)(Ab + (size_t)(a_r + 64) * lda + kn + a_c);
            b0 = make_float4(0.f, 0.f, 0.f, 0.f); b1 = b0;
            if (n0 + b_r < N)
                b0 = *(const float4*)(B + (size_t)(n0 + b_r) * ldb + kn + b_c);
            if (n0 + b_r + 64 < N)
                b1 = *(const float4*)(B + (size_t)(n0 + b_r + 64) * ldb + kn + b_c);
        }

#pragma unroll
        for (int kk = 0; kk < 16; kk++) {
            float arr[8], brr[8];
            *(float4*)&arr[0] = *(const float4*)&As[buf][kk][ty * 8];
            *(float4*)&arr[4] = *(const float4*)&As[buf][kk][ty * 8 + 4];
            *(float4*)&brr[0] = *(const float4*)&Bs[buf][kk][tx * 8];
            *(float4*)&brr[4] = *(const float4*)&Bs[buf][kk][tx * 8 + 4];
#pragma unroll
            for (int i = 0; i < 8; i++)
#pragma unroll
                for (int j = 0; j < 8; j++)
                    acc[i][j] = fmaf(arr[i], brr[j], acc[i][j]);
        }

        if (nxt) {
            const int nb = buf ^ 1;
            As[nb][a_c + 0][a_r] = a0.x; As[nb][a_c + 1][a_r] = a0.y;
            As[nb][a_c + 2][a_r] = a0.z; As[nb][a_c + 3][a_r] = a0.w;
            As[nb][a_c + 0][a_r + 64] = a1.x; As[nb][a_c + 1][a_r + 64] = a1.y;
            As[nb][a_c + 2][a_r + 64] = a1.z; As[nb][a_c + 3][a_r + 64] = a1.w;
            Bs[nb][b_c + 0][b_r] = b0.x; Bs[nb][b_c + 1][b_r] = b0.y;
            Bs[nb][b_c + 2][b_r] = b0.z; Bs[nb][b_c + 3][b_r] = b0.w;
            Bs[nb][b_c + 0][b_r + 64] = b1.x; Bs[nb][b_c + 1][b_r + 64] = b1.y;
            Bs[nb][b_c + 2][b_r + 64] = b1.z; Bs[nb][b_c + 3][b_r + 64] = b1.w;
            __syncthreads();
            buf = nb;
        }
    }

    const int col = n0 + tx * 8;
    if (col >= N) return;

#pragma unroll
    for (int i = 0; i < 8; i++) {
        const int row = m0 + ty * 8 + i;
        float* cp = C + (size_t)row * ldc + col;
        float v[8];
#pragma unroll
        for (int j = 0; j < 8; j++) {
            float t = acc[i][j];
            if (bias)   t += bias[col + j];
            if (rowvec) t += rowvec[(row >> 10) * ldc + col + j];
            if (beta)   t += cp[j];
            if (do_softplus) t = softplusf(t);
            v[j] = t;
        }
        *(float4*)cp       = *(float4*)&v[0];
        *(float4*)(cp + 4) = *(float4*)&v[4];
    }
}

// ---------------- weight prep kernels ----------------
// transpose w_up [512 K x 1024 N] -> [1024 N x 512 K]
__global__ void transpose_wup_k(const float* __restrict__ in, float* __restrict__ out)
{
    __shared__ float t[32][33];
    const int bx = blockIdx.x;   // n tile (32)
    const int by = blockIdx.y;   // k tile (16)
    {
        const int x = bx * 32 + threadIdx.x;  // n
        const int y = by * 32 + threadIdx.y;  // k
#pragma unroll
        for (int i = 0; i < 32; i += 8)
            t[threadIdx.y + i][threadIdx.x] = in[(size_t)(y + i) * 1024 + x];
    }
    __syncthreads();
    {
        const int x = by * 32 + threadIdx.x;  // k
        const int y = bx * 32 + threadIdx.y;  // n
#pragma unroll
        for (int i = 0; i < 32; i += 8)
            out[(size_t)(y + i) * 512 + x] = t[threadIdx.x][threadIdx.y + i];
    }
}

// pad x_proj_w [64,1024] -> [128,1024] with zero rows 64..127
__global__ void pad_xpw_k(const float* __restrict__ w, float* __restrict__ out)
{
    const int idx = blockIdx.x * 256 + threadIdx.x;   // 128*1024
    out[idx] = (idx < 64 * 1024) ? w[idx] : 0.f;
}

// ---------------- layernorm (C = 512, 128 threads/row) ----------------
__global__ void layernorm_k(const float* __restrict__ x,
                            const float* __restrict__ w,
                            const float* __restrict__ b,
                            float* __restrict__ out)
{
    const int row = blockIdx.x;
    const int tid = threadIdx.x;
    float4 v = ((const float4*)(x + (size_t)row * 512))[tid];
    float s  = v.x + v.y + v.z + v.w;
    float sq = v.x * v.x + v.y * v.y + v.z * v.z + v.w * v.w;
#pragma unroll
    for (int o = 16; o > 0; o >>= 1) {
        s  += __shfl_xor_sync(0xffffffffu, s,  o);
        sq += __shfl_xor_sync(0xffffffffu, sq, o);
    }
    __shared__ float ss[4], ssq[4];
    const int wid = tid >> 5;
    if ((tid & 31) == 0) { ss[wid] = s; ssq[wid] = sq; }
    __syncthreads();
    s  = ss[0]  + ss[1]  + ss[2]  + ss[3];
    sq = ssq[0] + ssq[1] + ssq[2] + ssq[3];
    const float m   = s  * (1.f / 512.f);
    const float var = sq * (1.f / 512.f) - m * m;
    const float inv = rsqrtf(var + 1e-5f);
    float4 wv = ((const float4*)w)[tid];
    float4 bv = ((const float4*)b)[tid];
    float4 o4;
    o4.x = (v.x - m) * inv * wv.x + bv.x;
    o4.y = (v.y - m) * inv * wv.y + bv.y;
    o4.z = (v.z - m) * inv * wv.z + bv.z;
    o4.w = (v.w - m) * inv * wv.w + bv.w;
    ((float4*)(out + (size_t)row * 512))[tid] = o4;
}

// ---------------- rmsnorm + silu, in place (C = 512) ----------------
__global__ void rmsnorm_silu_k(float* __restrict__ x, const float* __restrict__ w)
{
    const int row = blockIdx.x;
    const int tid = threadIdx.x;
    float4 v = ((const float4*)(x + (size_t)row * 512))[tid];
    float sq = v.x * v.x + v.y * v.y + v.z * v.z + v.w * v.w;
#pragma unroll
    for (int o = 16; o > 0; o >>= 1) sq += __shfl_xor_sync(0xffffffffu, sq, o);
    __shared__ float ssq[4];
    const int wid = tid >> 5;
    if ((tid & 31) == 0) ssq[wid] = sq;
    __syncthreads();
    sq = ssq[0] + ssq[1] + ssq[2] + ssq[3];
    const float inv = rsqrtf(sq * (1.f / 512.f) + 1e-5f);
    float4 wv = ((const float4*)w)[tid];
    float4 o4;
    float a;
    a = v.x * inv * wv.x; o4.x = siluf(a);
    a = v.y * inv * wv.y; o4.y = siluf(a);
    a = v.z * inv * wv.z; o4.z = siluf(a);
    a = v.w * inv * wv.w; o4.w = siluf(a);
    ((float4*)(x + (size_t)row * 512))[tid] = o4;
}

// ---------------- up rearrange: [b,l, o*2+k] -> [b, 2l+k, o] (+b_up) ----------------
__global__ void up_rearrange_k(const float* __restrict__ up_tmp,
                               const float* __restrict__ b_up,
                               float* __restrict__ up)
{
    const int idx  = blockIdx.x * blockDim.x + threadIdx.x;
    const int o    = idx & 511;
    const int orow = idx >> 9;
    const int b    = orow >> 10;
    const int t    = orow & 1023;
    const int l    = t >> 1;
    const int k    = t & 1;
    up[idx] = up_tmp[(size_t)(b * 512 + l) * 1024 + o * 2 + k] + b_up[o];
}

// ---------------- causal depthwise conv(4) + bias + silu ----------------
__global__ void conv_silu_k(const float* __restrict__ xz,
                            const float* __restrict__ cw,
                            const float* __restrict__ cb,
                            float* __restrict__ xc)
{
    const int idx = blockIdx.x * blockDim.x + threadIdx.x;
    const int d   = idx & 1023;
    const int row = idx >> 10;
    const int t   = row & 1023;
    float acc = cb[d];
#pragma unroll
    for (int j = 0; j < 4; j++) {
        const int tt = t - 3 + j;
        if (tt >= 0)
            acc = fmaf(cw[d * 4 + j], xz[(size_t)(row - 3 + j) * 2048 + d], acc);
    }
    xc[idx] = siluf(acc);
}

// ---------------- selective scan (xdbc now ld=128) ----------------
__global__ __launch_bounds__(128)
void scan_k(const float* __restrict__ dt,
            const float* __restrict__ xc,
            const float* __restrict__ xz,
            const float* __restrict__ xdbc,    // [ROWS,128]: dtp|B|C|pad
            const float* __restrict__ A_log,
            const float* __restrict__ Dp,
            float* __restrict__ y)
{
    __shared__ __align__(16) float bc_s[32][32];

    const int tid    = threadIdx.x;
    const int half   = tid & 1;
    const int dloc   = tid >> 1;
    const int b      = blockIdx.x >> 4;
    const int d      = (blockIdx.x & 15) * 64 + dloc;
    const int n0     = half * 8;

    float A2[8], h[8];
#pragma unroll
    for (int j = 0; j < 8; j++) {
        A2[j] = -__expf(A_log[d * 16 + n0 + j]) * 1.44269504f;
        h[j]  = 0.f;
    }
    const float Dd = Dp[d];

    const float* dtp = dt   + (size_t)b * 1024 * 1024 + d;
    const float* up  = xc   + (size_t)b * 1024 * 1024 + d;
    const float* zp  = xz   + (size_t)b * 1024 * 2048 + 1024 + d;
    const float* bcb = xdbc + (size_t)b * 1024 * 128 + 32;
    float*       yp  = y    + (size_t)b * 1024 * 1024 + d;

    const int st_t = tid >> 2;
    const int st_c = (tid & 3) * 8;

    for (int c = 0; c < 32; c++) {
        __syncthreads();
        {
            const float* src = bcb + (size_t)(c * 32 + st_t) * 128 + st_c;
            *(float4*)&bc_s[st_t][st_c]     = *(const float4*)src;
            *(float4*)&bc_s[st_t][st_c + 4] = *(const float4*)(src + 4);
        }
        __syncthreads();

#pragma unroll
        for (int s = 0; s < 4; s++) {
            const int tbase = c * 32 + s * 8;
            float dt8[8], u8[8], z8[8];
#pragma unroll
            for (int j = 0; j < 8; j++) {
                dt8[j] = dtp[(size_t)(tbase + j) * 1024];
                u8[j]  = up [(size_t)(tbase + j) * 1024];
                z8[j]  = zp [(size_t)(tbase + j) * 2048];
            }
#pragma unroll
            for (int j = 0; j < 8; j++) {
                const int tt = s * 8 + j;
                float Bv[8], Cv[8];
                *(float4*)&Bv[0] = *(const float4*)&bc_s[tt][n0];
                *(float4*)&Bv[4] = *(const float4*)&bc_s[tt][n0 + 4];
                *(float4*)&Cv[0] = *(const float4*)&bc_s[tt][16 + n0];
                *(float4*)&Cv[4] = *(const float4*)&bc_s[tt][16 + n0 + 4];
                const float dtv = dt8[j];
                const float u   = u8[j];
                const float du  = dtv * u;
                float ya = 0.f, yb2 = 0.f;
#pragma unroll
                for (int n = 0; n < 8; n++) {
                    const float dA = exp2f(dtv * A2[n]);
                    h[n] = fmaf(dA, h[n], du * Bv[n]);
                    if (n & 1) yb2 = fmaf(h[n], Cv[n], yb2);
                    else       ya  = fmaf(h[n], Cv[n], ya);
                }
                float ysum = ya + yb2;
                ysum += __shfl_xor_sync(0xffffffffu, ysum, 1);
                if (half == 0)
                    yp[(size_t)(tbase + j) * 1024] = (ysum + u * Dd) * siluf(z8[j]);
            }
        }
    }
}

// ---------------- launcher ----------------
extern "C" void kernel_launch(void* const* d_in, const int* in_sizes, int n_in,
                              void* d_out, int out_size)
{
    (void)in_sizes; (void)n_in; (void)out_size;

    const float* motion     = (const float*)d_in[0];
    const float* skip       = (const float*)d_in[1];
    const float* embed      = (const float*)d_in[2];
    const float* w_up       = (const float*)d_in[3];
    const float* b_up       = (const float*)d_in[4];
    const float* w1         = (const float*)d_in[5];
    const float* b1         = (const float*)d_in[6];
    const float* rms_w      = (const float*)d_in[7];
    const float* w2         = (const float*)d_in[8];
    const float* b2         = (const float*)d_in[9];
    const float* ln_w       = (const float*)d_in[10];
    const float* ln_b       = (const float*)d_in[11];
    const float* in_proj_w  = (const float*)d_in[12];
    const float* conv_w     = (const float*)d_in[13];
    const float* conv_b     = (const float*)d_in[14];
    const float* x_proj_w   = (const float*)d_in[15];
    const float* dt_proj_w  = (const float*)d_in[16];
    const float* dt_proj_b  = (const float*)d_in[17];
    const float* A_log      = (const float*)d_in[18];
    const float* D_param    = (const float*)d_in[19];
    const float* out_proj_w = (const float*)d_in[20];
    const float* out_proj_b = (const float*)d_in[21];
    const float* norm_f_w   = (const float*)d_in[22];
    const float* norm_f_b   = (const float*)d_in[23];
    float* out = (float*)d_out;

    float *up_tmp, *up, *h, *x, *ln, *xz, *xc, *xdbc, *dtb, *yb, *wupT, *xpw;
    cudaGetSymbolAddress((void**)&up_tmp, g_up_tmp);
    cudaGetSymbolAddress((void**)&up,     g_up);
    cudaGetSymbolAddress((void**)&h,      g_h);
    cudaGetSymbolAddress((void**)&x,      g_x);
    cudaGetSymbolAddress((void**)&ln,     g_ln);
    cudaGetSymbolAddress((void**)&xz,     g_xz);
    cudaGetSymbolAddress((void**)&xc,     g_xc);
    cudaGetSymbolAddress((void**)&xdbc,   g_xdbc);
    cudaGetSymbolAddress((void**)&dtb,    g_dt);
    cudaGetSymbolAddress((void**)&yb,     g_y);
    cudaGetSymbolAddress((void**)&wupT,   g_wupT);
    cudaGetSymbolAddress((void**)&xpw,    g_xpw);

    cudaFuncSetAttribute(tgemm_k, cudaFuncAttributeMaxDynamicSharedMemorySize,
                         TG_SMEM_BYTES);

    // 0) transpose w_up [512K,1024N] -> [1024N,512K]
    transpose_wup_k<<<dim3(32, 16), dim3(32, 8)>>>(w_up, wupT);

    // 1) up = motion @ w_up  — tensor (A[4096,512] @ wupT[1024,512]^T)
    tgemm_k<<<dim3(8, 32), 256, TG_SMEM_BYTES>>>(
        motion, 512, wupT, 512, up_tmp, 1024, nullptr, nullptr, 512, 0);

    // 2) rearrange [b,l,(o,k)] -> tokens, add b_up
    up_rearrange_k<<<(ROWS * 512) / 256, 256>>>(up_tmp, b_up, up);

    // 3) h = up @ w1[:, :512]^T + b1 ; h += skip @ w1[:, 512:]^T   — tensor
    tgemm_k<<<dim3(4, 64), 256, TG_SMEM_BYTES>>>(
        up, 512, w1, 1024, h, 512, b1, nullptr, 512, 0);
    tgemm_k<<<dim3(4, 64), 256, TG_SMEM_BYTES>>>(
        skip, 512, w1 + 512, 1024, h, 512, nullptr, nullptr, 512, 1);

    // 4) h = silu(rmsnorm(h, rms_w)) in place
    rmsnorm_silu_k<<<ROWS, 128>>>(h, rms_w);

    // 5) x = h @ w2^T + b2 + embed[b]   — tensor
    tgemm_k<<<dim3(4, 64), 256, TG_SMEM_BYTES>>>(
        h, 512, w2, 512, x, 512, b2, embed, 512, 0);

    // 6) mamba layers
    for (int i = 0; i < NDEPTH; i++) {
        layernorm_k<<<ROWS, 128>>>(x, ln_w + i * 512, ln_b + i * 512, ln);

        tgemm_k<<<dim3(16, 64), 256, TG_SMEM_BYTES>>>(
            ln, 512, in_proj_w + (size_t)i * 2048 * 512, 512,
            xz, 2048, nullptr, nullptr, 512, 0);

        conv_silu_k<<<(ROWS * DI) / 256, 256>>>(
            xz, conv_w + (size_t)i * 1024 * 4, conv_b + i * 1024, xc);

        // x_proj via tensor path: pad weights [64,1024] -> [128,1024]
        pad_xpw_k<<<512, 256>>>(x_proj_w + (size_t)i * 64 * 1024, xpw);
        tgemm_k<<<dim3(1, 64), 256, TG_SMEM_BYTES>>>(
            xc, 1024, xpw, 1024, xdbc, 128, nullptr, nullptr, 1024, 0);

        sgemm_k<<<dim3(8, 64), 256>>>(
            xdbc, 128, dt_proj_w + (size_t)i * 1024 * 32, 32,
            dtb, 1024, dt_proj_b + i * 1024, nullptr, ROWS, 1024, 32, 0, 1);

        scan_k<<<128, 128>>>(
            dtb, xc, xz, xdbc,
            A_log + (size_t)i * 1024 * 16, D_param + i * 1024, yb);

        tgemm_k<<<dim3(4, 64), 256, TG_SMEM_BYTES>>>(
            yb, 1024, out_proj_w + (size_t)i * 512 * 1024, 1024,
            x, 512, out_proj_b + i * 512, nullptr, 1024, 1);
    }

    // 7) final layernorm -> output
    layernorm_k<<<ROWS, 128>>>(x, norm_f_w, norm_f_b, out);
}

// round 11
// speedup vs baseline: 1.7085x; 1.0398x over previous
#include <cuda_runtime.h>
#include <cuda_bf16.h>
#include <math.h>
#include <stdint.h>

// ---------------- problem constants ----------------
#define BB    8
#define LSEQ  1024            // 2*L_IN
#define ROWS  (BB*LSEQ)       // 8192 tokens
#define CC    512
#define DI    1024
#define DS    16
#define NDEPTH 4

// weight-pack offsets (elements) in the converted bf16 weight bank
#define OFF_W1   0
#define SZ_W1    (512*1024)
#define OFF_W2   (OFF_W1 + SZ_W1)
#define SZ_W2    (512*512)
#define OFF_IP   (OFF_W2 + SZ_W2)
#define SZ_IP    (2048*512)
#define OFF_XP   (OFF_IP + 4*SZ_IP)
#define SZ_XP    (128*1024)
#define OFF_OP   (OFF_XP + 4*SZ_XP)
#define SZ_OP    (512*1024)
#define WB_TOTAL (OFF_OP + 4*SZ_OP)   // 7,602,176

// ---------------- scratch (device globals; no allocs allowed) ----------------
__device__ float g_up_tmp[4096*1024];   // up GEMM raw output
__device__ float g_h    [ROWS*CC];      // h1 (pre-rmsnorm)
__device__ float g_x    [ROWS*CC];      // residual stream
__device__ float g_xz   [ROWS*2*DI];    // in_proj out (xc_raw | z)
__device__ float g_xc   [ROWS*DI];      // conv+silu out f32 (scan u)
__device__ float g_xdbc [ROWS*128];     // x_proj out (dtp|B|C|pad), ld=128
__device__ float g_dt   [ROWS*DI];      // softplus dt

// bf16 hi/lo operand buffers
__device__ __align__(16) __nv_bfloat16 g_mo_h[4096*512],  g_mo_l[4096*512];
__device__ __align__(16) __nv_bfloat16 g_sk_h[ROWS*512],  g_sk_l[ROWS*512];
__device__ __align__(16) __nv_bfloat16 g_upb_h[ROWS*512], g_upb_l[ROWS*512];
__device__ __align__(16) __nv_bfloat16 g_hh[ROWS*512],    g_hl[ROWS*512];
__device__ __align__(16) __nv_bfloat16 g_lnh[ROWS*512],   g_lnl[ROWS*512];
__device__ __align__(16) __nv_bfloat16 g_xch[ROWS*1024],  g_xcl[ROWS*1024];
__device__ __align__(16) __nv_bfloat16 g_yh[ROWS*1024],   g_yl[ROWS*1024];
__device__ __align__(16) __nv_bfloat16 g_wupT_h[1024*512], g_wupT_l[1024*512];
__device__ __align__(16) __nv_bfloat16 g_wb_h[WB_TOTAL],   g_wb_l[WB_TOTAL];

// ---------------- helpers ----------------
__device__ __forceinline__ float softplusf(float x) {
    return (x > 20.f) ? x : log1pf(__expf(x));
}
__device__ __forceinline__ float siluf(float x) {
    return x / (1.f + __expf(-x));
}

__device__ __forceinline__ uint32_t smem_u32(const void* p) {
    uint32_t a;
    asm("{ .reg .u64 t; cvta.to.shared.u64 t, %1; cvt.u32.u64 %0, t; }"
        : "=r"(a) : "l"(p));
    return a;
}

__device__ __forceinline__ void split1(float v, __nv_bfloat16& h, __nv_bfloat16& l) {
    h = __float2bfloat16(v);
    l = __float2bfloat16(v - __bfloat162float(h));
}

// split f32x4 into bf16 hi / lo pairs (packed bf16x2 words, .x in low half)
__device__ __forceinline__ void split4(float4 v, uint32_t& h01, uint32_t& h23,
                                       uint32_t& l01, uint32_t& l23) {
    __nv_bfloat162 h0 = __float22bfloat162_rn(make_float2(v.x, v.y));
    __nv_bfloat162 h1 = __float22bfloat162_rn(make_float2(v.z, v.w));
    float2 f0 = __bfloat1622float2(h0), f1 = __bfloat1622float2(h1);
    __nv_bfloat162 l0 = __float22bfloat162_rn(make_float2(v.x - f0.x, v.y - f0.y));
    __nv_bfloat162 l1 = __float22bfloat162_rn(make_float2(v.z - f1.x, v.w - f1.y));
    h01 = *(uint32_t*)&h0; h23 = *(uint32_t*)&h1;
    l01 = *(uint32_t*)&l0; l23 = *(uint32_t*)&l1;
}

__device__ __forceinline__ void ldsm4(uint32_t* r, uint32_t addr) {
    asm volatile("ldmatrix.sync.aligned.m8n8.x4.shared.b16 {%0,%1,%2,%3}, [%4];"
        : "=r"(r[0]), "=r"(r[1]), "=r"(r[2]), "=r"(r[3]) : "r"(addr));
}

__device__ __forceinline__ void mma_bf16(float* c, const uint32_t* a, const uint32_t* b) {
    asm volatile("mma.sync.aligned.m16n8k16.row.col.f32.bf16.bf16.f32 "
        "{%0,%1,%2,%3}, {%4,%5,%6,%7}, {%8,%9}, {%0,%1,%2,%3};"
        : "+f"(c[0]), "+f"(c[1]), "+f"(c[2]), "+f"(c[3])
        : "r"(a[0]), "r"(a[1]), "r"(a[2]), "r"(a[3]), "r"(b[0]), "r"(b[1]));
}

#define CP16(dst, src) \
    asm volatile("cp.async.cg.shared.global [%0], [%1], 16;" \
                 :: "r"(dst), "l"(src) : "memory")
#define CP_COMMIT() asm volatile("cp.async.commit_group;" ::: "memory")
#define CP_WAIT0()  asm volatile("cp.async.wait_group 0;" ::: "memory")

// ============================================================================
// tensor-core GEMM v3: pre-converted bf16 hi/lo operands, cp.async pipeline.
// C[M,N] = (Ah+Al)[M,K] @ (Bh+Bl)[N,K]^T (3-term) (+bias)(+rowvec)(+beta*C)
// Block 128x128, BK=32, 8 warps (2x4). Double-buffered 32KB stages.
// smem region layout per stage: AH 0, AL 8192, BH 16384, BL 24576.
// rows are 64B (32 bf16); XOR swizzle col16' = col16 ^ ((row>>1)&3)
// -> conflict-free ldmatrix phases and clean cp.async dsts.
// ============================================================================
#define TGV_REGION 8192
#define TGV_STAGE  32768
#define TGV_SMEM   65536

__global__ __launch_bounds__(256, 2)
void tgemm_k(const __nv_bfloat16* __restrict__ Ah, const __nv_bfloat16* __restrict__ Al,
             int lda,
             const __nv_bfloat16* __restrict__ Bh, const __nv_bfloat16* __restrict__ Bl,
             int ldb,
             float* __restrict__ C, int ldc,
             const float* __restrict__ bias,
             const float* __restrict__ rowvec,
             int K, int beta)
{
    extern __shared__ __align__(16) char smem[];
    const uint32_t sb = smem_u32(smem);
    const int tid  = threadIdx.x;
    const int wid  = tid >> 5;
    const int lane = tid & 31;
    const int m0 = blockIdx.y * 128;
    const int n0 = blockIdx.x * 128;
    const int wm = wid >> 2;          // 0..1 -> 64 rows
    const int wn = wid & 3;           // 0..3 -> 32 cols

    float acc[4][4][4];
#pragma unroll
    for (int i = 0; i < 4; i++)
#pragma unroll
        for (int j = 0; j < 4; j++)
#pragma unroll
            for (int k = 0; k < 4; k++) acc[i][j][k] = 0.f;

    // ---- cp.async staging geometry: thread -> row tid>>1, col16 pair ----
    const int s_row = tid >> 1;
    const int c0    = (tid & 1) * 2;             // col16 base {0,2}
    const int ssw   = (s_row >> 1) & 3;
    const uint32_t d0 = (uint32_t)(s_row * 64 + ((c0     ^ ssw) * 16));
    const uint32_t d1 = (uint32_t)(s_row * 64 + (((c0+1) ^ ssw) * 16));
    const __nv_bfloat16* Ah_s = Ah + (size_t)(m0 + s_row) * lda + c0 * 8;
    const __nv_bfloat16* Al_s = Al + (size_t)(m0 + s_row) * lda + c0 * 8;
    const __nv_bfloat16* Bh_s = Bh + (size_t)(n0 + s_row) * ldb + c0 * 8;
    const __nv_bfloat16* Bl_s = Bl + (size_t)(n0 + s_row) * ldb + c0 * 8;

    // ---- ldmatrix relative offsets (XOR swizzle baked in) ----
    const int q  = lane >> 3;
    const int r8 = lane & 7;
    const int qh = q >> 1;
    const int qb = q & 1;
    uint32_t a_rel[4][2], b_rel[2][2];
#pragma unroll
    for (int mt = 0; mt < 4; mt++) {
        const int ar = wm * 64 + mt * 16 + (q & 1) * 8 + r8;
        const int sw = (ar >> 1) & 3;
#pragma unroll
        for (int ks = 0; ks < 2; ks++)
            a_rel[mt][ks] = (uint32_t)(ar * 64 + (((ks * 2 + qh) ^ sw) * 16));
    }
#pragma unroll
    for (int h = 0; h < 2; h++) {
        const int br = wn * 32 + h * 16 + (q >> 1) * 8 + r8;
        const int sw = (br >> 1) & 3;
#pragma unroll
        for (int ks = 0; ks < 2; ks++)
            b_rel[h][ks] = (uint32_t)(2 * TGV_REGION + br * 64 + (((ks * 2 + qb) ^ sw) * 16));
    }

    const int chunks = K >> 5;

    // prologue: stage chunk 0 into buffer 0
    {
        const uint32_t s0 = sb;
        CP16(s0 + d0, Ah_s);                    CP16(s0 + d1, Ah_s + 8);
        CP16(s0 + TGV_REGION + d0, Al_s);       CP16(s0 + TGV_REGION + d1, Al_s + 8);
        CP16(s0 + 2*TGV_REGION + d0, Bh_s);     CP16(s0 + 2*TGV_REGION + d1, Bh_s + 8);
        CP16(s0 + 3*TGV_REGION + d0, Bl_s);     CP16(s0 + 3*TGV_REGION + d1, Bl_s + 8);
        CP_COMMIT();
    }

    for (int c = 0; c < chunks; c++) {
        CP_WAIT0();
        __syncthreads();
        const uint32_t sbuf = sb + (uint32_t)(c & 1) * TGV_STAGE;
        if (c + 1 < chunks) {
            const uint32_t sn = sb + (uint32_t)((c + 1) & 1) * TGV_STAGE;
            const int ko = (c + 1) * 32;
            CP16(sn + d0, Ah_s + ko);                CP16(sn + d1, Ah_s + ko + 8);
            CP16(sn + TGV_REGION + d0, Al_s + ko);   CP16(sn + TGV_REGION + d1, Al_s + ko + 8);
            CP16(sn + 2*TGV_REGION + d0, Bh_s + ko); CP16(sn + 2*TGV_REGION + d1, Bh_s + ko + 8);
            CP16(sn + 3*TGV_REGION + d0, Bl_s + ko); CP16(sn + 3*TGV_REGION + d1, Bl_s + ko + 8);
            CP_COMMIT();
        }

#pragma unroll
        for (int ks = 0; ks < 2; ks++) {
            uint32_t bh[2][4], bl[2][4];
            ldsm4(bh[0], sbuf + b_rel[0][ks]);
            ldsm4(bh[1], sbuf + b_rel[1][ks]);
            ldsm4(bl[0], sbuf + b_rel[0][ks] + TGV_REGION);
            ldsm4(bl[1], sbuf + b_rel[1][ks] + TGV_REGION);
#pragma unroll
            for (int mt = 0; mt < 4; mt++) {
                uint32_t ah[4], al[4];
                ldsm4(ah, sbuf + a_rel[mt][ks]);
                ldsm4(al, sbuf + a_rel[mt][ks] + TGV_REGION);
#pragma unroll
                for (int nt = 0; nt < 4; nt++) {
                    const uint32_t* bhp = &bh[nt >> 1][(nt & 1) * 2];
                    const uint32_t* blp = &bl[nt >> 1][(nt & 1) * 2];
                    mma_bf16(acc[mt][nt], ah, bhp);
                    mma_bf16(acc[mt][nt], ah, blp);
                    mma_bf16(acc[mt][nt], al, bhp);
                }
            }
        }
    }

    // epilogue
    const int er = lane >> 2;
    const int ec = (lane & 3) * 2;
    const int colbase = n0 + wn * 32 + ec;
#pragma unroll
    for (int mt = 0; mt < 4; mt++) {
#pragma unroll
        for (int half = 0; half < 2; half++) {
            const int row = m0 + wm * 64 + mt * 16 + er + half * 8;
            float* cp = C + (size_t)row * ldc + colbase;
            const float* rv = rowvec ? rowvec + (size_t)(row >> 10) * ldc + colbase
                                     : nullptr;
#pragma unroll
            for (int nt = 0; nt < 4; nt++) {
                float v0 = acc[mt][nt][half * 2 + 0];
                float v1 = acc[mt][nt][half * 2 + 1];
                const int co = nt * 8;
                if (bias) { v0 += bias[colbase + co]; v1 += bias[colbase + co + 1]; }
                if (rv)   { v0 += rv[co];             v1 += rv[co + 1]; }
                if (beta) { v0 += cp[co];             v1 += cp[co + 1]; }
                *(float2*)(cp + co) = make_float2(v0, v1);
            }
        }
    }
}

// ============================================================================
// SIMT SGEMM (fmaf, BK=16, double-buffered) — dt_proj only
// ============================================================================
__global__ __launch_bounds__(256, 2)
void sgemm_k(const float* __restrict__ A, int lda,
             const float* __restrict__ B, int ldb,
             float* __restrict__ C, int ldc,
             const float* __restrict__ bias,
             int M, int N, int K, int do_softplus)
{
    __shared__ float As[2][16][128];
    __shared__ float Bs[2][16][128];

    const int tid = threadIdx.x;
    const int m0 = blockIdx.y * 128;
    const int n0 = blockIdx.x * 128;
    const int ty = tid >> 4;
    const int tx = tid & 15;

    const int a_r = tid >> 2;
    const int a_c = (tid & 3) * 4;
    const int b_r = a_r;
    const int b_c = a_c;

    float acc[8][8];
#pragma unroll
    for (int i = 0; i < 8; i++)
#pragma unroll
        for (int j = 0; j < 8; j++) acc[i][j] = 0.f;

    const float* Ab = A + (size_t)m0 * lda;
    float4 a0, a1, b0, b1;

    a0 = *(const float4*)(Ab + (size_t)a_r * lda + a_c);
    a1 = *(const float4*)(Ab + (size_t)(a_r + 64) * lda + a_c);
    b0 = make_float4(0.f, 0.f, 0.f, 0.f); b1 = b0;
    if (n0 + b_r < N)
        b0 = *(const float4*)(B + (size_t)(n0 + b_r) * ldb + b_c);
    if (n0 + b_r + 64 < N)
        b1 = *(const float4*)(B + (size_t)(n0 + b_r + 64) * ldb + b_c);
    {
        As[0][a_c + 0][a_r] = a0.x; As[0][a_c + 1][a_r] = a0.y;
        As[0][a_c + 2][a_r] = a0.z; As[0][a_c + 3][a_r] = a0.w;
        As[0][a_c + 0][a_r + 64] = a1.x; As[0][a_c + 1][a_r + 64] = a1.y;
        As[0][a_c + 2][a_r + 64] = a1.z; As[0][a_c + 3][a_r + 64] = a1.w;
        Bs[0][b_c + 0][b_r] = b0.x; Bs[0][b_c + 1][b_r] = b0.y;
        Bs[0][b_c + 2][b_r] = b0.z; Bs[0][b_c + 3][b_r] = b0.w;
        Bs[0][b_c + 0][b_r + 64] = b1.x; Bs[0][b_c + 1][b_r + 64] = b1.y;
        Bs[0][b_c + 2][b_r + 64] = b1.z; Bs[0][b_c + 3][b_r + 64] = b1.w;
    }
    __syncthreads();

    int buf = 0;
    for (int k0 = 0; k0 < K; k0 += 16) {
        const bool nxt = (k0 + 16 < K);
        if (nxt) {
            const int kn = k0 + 16;
            a0 = *(const float4*)(Ab + (size_t)a_r * lda + kn + a_c);
            a1 = *(const float4*)(Ab + (size_t)(a_r + 64) * lda + kn + a_c);
            b0 = make_float4(0.f, 0.f, 0.f, 0.f); b1 = b0;
            if (n0 + b_r < N)
                b0 = *(const float4*)(B + (size_t)(n0 + b_r) * ldb + kn + b_c);
            if (n0 + b_r + 64 < N)
                b1 = *(const float4*)(B + (size_t)(n0 + b_r + 64) * ldb + kn + b_c);
        }

#pragma unroll
        for (int kk = 0; kk < 16; kk++) {
            float arr[8], brr[8];
            *(float4*)&arr[0] = *(const float4*)&As[buf][kk][ty * 8];
            *(float4*)&arr[4] = *(const float4*)&As[buf][kk][ty * 8 + 4];
            *(float4*)&brr[0] = *(const float4*)&Bs[buf][kk][tx * 8];
            *(float4*)&brr[4] = *(const float4*)&Bs[buf][kk][tx * 8 + 4];
#pragma unroll
            for (int i = 0; i < 8; i++)
#pragma unroll
                for (int j = 0; j < 8; j++)
                    acc[i][j] = fmaf(arr[i], brr[j], acc[i][j]);
        }

        if (nxt) {
            const int nb = buf ^ 1;
            As[nb][a_c + 0][a_r] = a0.x; As[nb][a_c + 1][a_r] = a0.y;
            As[nb][a_c + 2][a_r] = a0.z; As[nb][a_c + 3][a_r] = a0.w;
            As[nb][a_c + 0][a_r + 64] = a1.x; As[nb][a_c + 1][a_r + 64] = a1.y;
            As[nb][a_c + 2][a_r + 64] = a1.z; As[nb][a_c + 3][a_r + 64] = a1.w;
            Bs[nb][b_c + 0][b_r] = b0.x; Bs[nb][b_c + 1][b_r] = b0.y;
            Bs[nb][b_c + 2][b_r] = b0.z; Bs[nb][b_c + 3][b_r] = b0.w;
            Bs[nb][b_c + 0][b_r + 64] = b1.x; Bs[nb][b_c + 1][b_r + 64] = b1.y;
            Bs[nb][b_c + 2][b_r + 64] = b1.z; Bs[nb][b_c + 3][b_r + 64] = b1.w;
            __syncthreads();
            buf = nb;
        }
    }

    const int col = n0 + tx * 8;
    if (col >= N) return;

#pragma unroll
    for (int i = 0; i < 8; i++) {
        const int row = m0 + ty * 8 + i;
        float* cp = C + (size_t)row * ldc + col;
        float v[8];
#pragma unroll
        for (int j = 0; j < 8; j++) {
            float t = acc[i][j];
            if (bias) t += bias[col + j];
            if (do_softplus) t = softplusf(t);
            v[j] = t;
        }
        *(float4*)cp       = *(float4*)&v[0];
        *(float4*)(cp + 4) = *(float4*)&v[4];
    }
}

// ---------------- weight prep ----------------
// mega-convert: all rectangular weights -> bf16 hi/lo bank (x_proj zero-padded)
__global__ void weights_conv_k(const float* __restrict__ w1,
                               const float* __restrict__ w2,
                               const float* __restrict__ ipw,
                               const float* __restrict__ xpw,
                               const float* __restrict__ opw,
                               __nv_bfloat16* __restrict__ wh,
                               __nv_bfloat16* __restrict__ wl)
{
    const int idx = blockIdx.x * 256 + threadIdx.x;
    float v;
    if (idx < OFF_W2)       v = w1[idx];
    else if (idx < OFF_IP)  v = w2[idx - OFF_W2];
    else if (idx < OFF_XP)  v = ipw[idx - OFF_IP];
    else if (idx < OFF_OP) {
        const int l = idx - OFF_XP;
        const int layer = l / SZ_XP;
        const int r = l % SZ_XP;
        const int row = r >> 10, col = r & 1023;
        v = (row < 64) ? xpw[layer * 64 * 1024 + row * 1024 + col] : 0.f;
    } else                  v = opw[idx - OFF_OP];
    __nv_bfloat16 h, l;
    split1(v, h, l);
    wh[idx] = h; wl[idx] = l;
}

// transpose w_up [512 K x 1024 N] -> bf16 hi/lo [1024 N x 512 K]
__global__ void transpose_wup_k(const float* __restrict__ in,
                                __nv_bfloat16* __restrict__ oh,
                                __nv_bfloat16* __restrict__ ol)
{
    __shared__ float t[32][33];
    const int bx = blockIdx.x, by = blockIdx.y;
    {
        const int x = bx * 32 + threadIdx.x;
        const int y = by * 32 + threadIdx.y;
#pragma unroll
        for (int i = 0; i < 32; i += 8)
            t[threadIdx.y + i][threadIdx.x] = in[(size_t)(y + i) * 1024 + x];
    }
    __syncthreads();
    {
        const int x = by * 32 + threadIdx.x;
        const int y = bx * 32 + threadIdx.y;
#pragma unroll
        for (int i = 0; i < 32; i += 8) {
            __nv_bfloat16 h, l;
            split1(t[threadIdx.x][threadIdx.y + i], h, l);
            oh[(size_t)(y + i) * 512 + x] = h;
            ol[(size_t)(y + i) * 512 + x] = l;
        }
    }
}

// f32 -> bf16 hi/lo, vectorized x4 (n multiple of 1024)
__global__ void convert_pair_k(const float* __restrict__ src,
                               __nv_bfloat16* __restrict__ h,
                               __nv_bfloat16* __restrict__ l)
{
    const int i = blockIdx.x * 256 + threadIdx.x;
    float4 v = ((const float4*)src)[i];
    uint32_t h01, h23, l01, l23;
    split4(v, h01, h23, l01, l23);
    ((uint2*)h)[i] = make_uint2(h01, h23);
    ((uint2*)l)[i] = make_uint2(l01, l23);
}

// ---------------- layernorm -> f32 out (final) ----------------
__global__ void layernorm_k(const float* __restrict__ x,
                            const float* __restrict__ w,
                            const float* __restrict__ b,
                            float* __restrict__ out)
{
    const int row = blockIdx.x;
    const int tid = threadIdx.x;
    float4 v = ((const float4*)(x + (size_t)row * 512))[tid];
    float s  = v.x + v.y + v.z + v.w;
    float sq = v.x * v.x + v.y * v.y + v.z * v.z + v.w * v.w;
#pragma unroll
    for (int o = 16; o > 0; o >>= 1) {
        s  += __shfl_xor_sync(0xffffffffu, s,  o);
        sq += __shfl_xor_sync(0xffffffffu, sq, o);
    }
    __shared__ float ss[4], ssq[4];
    const int wid = tid >> 5;
    if ((tid & 31) == 0) { ss[wid] = s; ssq[wid] = sq; }
    __syncthreads();
    s  = ss[0]  + ss[1]  + ss[2]  + ss[3];
    sq = ssq[0] + ssq[1] + ssq[2] + ssq[3];
    const float m   = s  * (1.f / 512.f);
    const float var = sq * (1.f / 512.f) - m * m;
    const float inv = rsqrtf(var + 1e-5f);
    float4 wv = ((const float4*)w)[tid];
    float4 bv = ((const float4*)b)[tid];
    float4 o4;
    o4.x = (v.x - m) * inv * wv.x + bv.x;
    o4.y = (v.y - m) * inv * wv.y + bv.y;
    o4.z = (v.z - m) * inv * wv.z + bv.z;
    o4.w = (v.w - m) * inv * wv.w + bv.w;
    ((float4*)(out + (size_t)row * 512))[tid] = o4;
}

// ---------------- layernorm -> bf16 hi/lo pair (per-layer) ----------------
__global__ void layernorm_bf_k(const float* __restrict__ x,
                               const float* __restrict__ w,
                               const float* __restrict__ b,
                               __nv_bfloat16* __restrict__ oh,
                               __nv_bfloat16* __restrict__ ol)
{
    const int row = blockIdx.x;
    const int tid = threadIdx.x;
    float4 v = ((const float4*)(x + (size_t)row * 512))[tid];
    float s  = v.x + v.y + v.z + v.w;
    float sq = v.x * v.x + v.y * v.y + v.z * v.z + v.w * v.w;
#pragma unroll
    for (int o = 16; o > 0; o >>= 1) {
        s  += __shfl_xor_sync(0xffffffffu, s,  o);
        sq += __shfl_xor_sync(0xffffffffu, sq, o);
    }
    __shared__ float ss[4], ssq[4];
    const int wid = tid >> 5;
    if ((tid & 31) == 0) { ss[wid] = s; ssq[wid] = sq; }
    __syncthreads();
    s  = ss[0]  + ss[1]  + ss[2]  + ss[3];
    sq = ssq[0] + ssq[1] + ssq[2] + ssq[3];
    const float m   = s  * (1.f / 512.f);
    const float var = sq * (1.f / 512.f) - m * m;
    const float inv = rsqrtf(var + 1e-5f);
    float4 wv = ((const float4*)w)[tid];
    float4 bv = ((const float4*)b)[tid];
    float4 o4;
    o4.x = (v.x - m) * inv * wv.x + bv.x;
    o4.y = (v.y - m) * inv * wv.y + bv.y;
    o4.z = (v.z - m) * inv * wv.z + bv.z;
    o4.w = (v.w - m) * inv * wv.w + bv.w;
    uint32_t h01, h23, l01, l23;
    split4(o4, h01, h23, l01, l23);
    ((uint2*)(oh + (size_t)row * 512))[tid] = make_uint2(h01, h23);
    ((uint2*)(ol + (size_t)row * 512))[tid] = make_uint2(l01, l23);
}

// ---------------- rmsnorm + silu -> bf16 hi/lo pair ----------------
__global__ void rmsnorm_silu_k(const float* __restrict__ x,
                               const float* __restrict__ w,
                               __nv_bfloat16* __restrict__ oh,
                               __nv_bfloat16* __restrict__ ol)
{
    const int row = blockIdx.x;
    const int tid = threadIdx.x;
    float4 v = ((const float4*)(x + (size_t)row * 512))[tid];
    float sq = v.x * v.x + v.y * v.y + v.z * v.z + v.w * v.w;
#pragma unroll
    for (int o = 16; o > 0; o >>= 1) sq += __shfl_xor_sync(0xffffffffu, sq, o);
    __shared__ float ssq[4];
    const int wid = tid >> 5;
    if ((tid & 31) == 0) ssq[wid] = sq;
    __syncthreads();
    sq = ssq[0] + ssq[1] + ssq[2] + ssq[3];
    const float inv = rsqrtf(sq * (1.f / 512.f) + 1e-5f);
    float4 wv = ((const float4*)w)[tid];
    float4 o4;
    float a;
    a = v.x * inv * wv.x; o4.x = siluf(a);
    a = v.y * inv * wv.y; o4.y = siluf(a);
    a = v.z * inv * wv.z; o4.z = siluf(a);
    a = v.w * inv * wv.w; o4.w = siluf(a);
    uint32_t h01, h23, l01, l23;
    split4(o4, h01, h23, l01, l23);
    ((uint2*)(oh + (size_t)row * 512))[tid] = make_uint2(h01, h23);
    ((uint2*)(ol + (size_t)row * 512))[tid] = make_uint2(l01, l23);
}

// ---------------- up rearrange -> bf16 hi/lo (+b_up) ----------------
__global__ void up_rearrange_k(const float* __restrict__ up_tmp,
                               const float* __restrict__ b_up,
                               __nv_bfloat16* __restrict__ oh,
                               __nv_bfloat16* __restrict__ ol)
{
    const int idx  = blockIdx.x * blockDim.x + threadIdx.x;
    const int o    = idx & 511;
    const int orow = idx >> 9;
    const int b    = orow >> 10;
    const int t    = orow & 1023;
    const int l    = t >> 1;
    const int k    = t & 1;
    const float v = up_tmp[(size_t)(b * 512 + l) * 1024 + o * 2 + k] + b_up[o];
    __nv_bfloat16 h, lo;
    split1(v, h, lo);
    oh[idx] = h; ol[idx] = lo;
}

// ---------------- causal depthwise conv(4) + bias + silu -> f32 + bf16 pair --
__global__ void conv_silu_k(const float* __restrict__ xz,
                            const float* __restrict__ cw,
                            const float* __restrict__ cb,
                            float* __restrict__ xc,
                            __nv_bfloat16* __restrict__ oh,
                            __nv_bfloat16* __restrict__ ol)
{
    const int idx = blockIdx.x * blockDim.x + threadIdx.x;
    const int d   = idx & 1023;
    const int row = idx >> 10;
    const int t   = row & 1023;
    float acc = cb[d];
#pragma unroll
    for (int j = 0; j < 4; j++) {
        const int tt = t - 3 + j;
        if (tt >= 0)
            acc = fmaf(cw[d * 4 + j], xz[(size_t)(row - 3 + j) * 2048 + d], acc);
    }
    const float v = siluf(acc);
    xc[idx] = v;
    __nv_bfloat16 h, l;
    split1(v, h, l);
    oh[idx] = h; ol[idx] = l;
}

// ---------------- selective scan -> bf16 hi/lo y ----------------
__global__ __launch_bounds__(128)
void scan_k(const float* __restrict__ dt,
            const float* __restrict__ xc,
            const float* __restrict__ xz,
            const float* __restrict__ xdbc,    // [ROWS,128]: dtp|B|C|pad
            const float* __restrict__ A_log,
            const float* __restrict__ Dp,
            __nv_bfloat16* __restrict__ yh,
            __nv_bfloat16* __restrict__ yl)
{
    __shared__ __align__(16) float bc_s[32][32];

    const int tid    = threadIdx.x;
    const int half   = tid & 1;
    const int dloc   = tid >> 1;
    const int b      = blockIdx.x >> 4;
    const int d      = (blockIdx.x & 15) * 64 + dloc;
    const int n0     = half * 8;

    float A2[8], h[8];
#pragma unroll
    for (int j = 0; j < 8; j++) {
        A2[j] = -__expf(A_log[d * 16 + n0 + j]) * 1.44269504f;
        h[j]  = 0.f;
    }
    const float Dd = Dp[d];

    const float* dtp = dt   + (size_t)b * 1024 * 1024 + d;
    const float* up  = xc   + (size_t)b * 1024 * 1024 + d;
    const float* zp  = xz   + (size_t)b * 1024 * 2048 + 1024 + d;
    const float* bcb = xdbc + (size_t)b * 1024 * 128 + 32;
    __nv_bfloat16* yhp = yh + (size_t)b * 1024 * 1024 + d;
    __nv_bfloat16* ylp = yl + (size_t)b * 1024 * 1024 + d;

    const int st_t = tid >> 2;
    const int st_c = (tid & 3) * 8;

    for (int c = 0; c < 32; c++) {
        __syncthreads();
        {
            const float* src = bcb + (size_t)(c * 32 + st_t) * 128 + st_c;
            *(float4*)&bc_s[st_t][st_c]     = *(const float4*)src;
            *(float4*)&bc_s[st_t][st_c + 4] = *(const float4*)(src + 4);
        }
        __syncthreads();

#pragma unroll
        for (int s = 0; s < 4; s++) {
            const int tbase = c * 32 + s * 8;
            float dt8[8], u8[8], z8[8];
#pragma unroll
            for (int j = 0; j < 8; j++) {
                dt8[j] = dtp[(size_t)(tbase + j) * 1024];
                u8[j]  = up [(size_t)(tbase + j) * 1024];
                z8[j]  = zp [(size_t)(tbase + j) * 2048];
            }
#pragma unroll
            for (int j = 0; j < 8; j++) {
                const int tt = s * 8 + j;
                float Bv[8], Cv[8];
                *(float4*)&Bv[0] = *(const float4*)&bc_s[tt][n0];
                *(float4*)&Bv[4] = *(const float4*)&bc_s[tt][n0 + 4];
                *(float4*)&Cv[0] = *(const float4*)&bc_s[tt][16 + n0];
                *(float4*)&Cv[4] = *(const float4*)&bc_s[tt][16 + n0 + 4];
                const float dtv = dt8[j];
                const float u   = u8[j];
                const float du  = dtv * u;
                float ya = 0.f, yb2 = 0.f;
#pragma unroll
                for (int n = 0; n < 8; n++) {
                    const float dA = exp2f(dtv * A2[n]);
                    h[n] = fmaf(dA, h[n], du * Bv[n]);
                    if (n & 1) yb2 = fmaf(h[n], Cv[n], yb2);
                    else       ya  = fmaf(h[n], Cv[n], ya);
                }
                float ysum = ya + yb2;
                ysum += __shfl_xor_sync(0xffffffffu, ysum, 1);
                if (half == 0) {
                    const float w = (ysum + u * Dd) * siluf(z8[j]);
                    __nv_bfloat16 wh, wl;
                    split1(w, wh, wl);
                    yhp[(size_t)(tbase + j) * 1024] = wh;
                    ylp[(size_t)(tbase + j) * 1024] = wl;
                }
            }
        }
    }
}

// ---------------- launcher ----------------
extern "C" void kernel_launch(void* const* d_in, const int* in_sizes, int n_in,
                              void* d_out, int out_size)
{
    (void)in_sizes; (void)n_in; (void)out_size;

    const float* motion     = (const float*)d_in[0];
    const float* skip       = (const float*)d_in[1];
    const float* embed      = (const float*)d_in[2];
    const float* w_up       = (const float*)d_in[3];
    const float* b_up       = (const float*)d_in[4];
    const float* w1         = (const float*)d_in[5];
    const float* b1         = (const float*)d_in[6];
    const float* rms_w      = (const float*)d_in[7];
    const float* w2         = (const float*)d_in[8];
    const float* b2         = (const float*)d_in[9];
    const float* ln_w       = (const float*)d_in[10];
    const float* ln_b       = (const float*)d_in[11];
    const float* in_proj_w  = (const float*)d_in[12];
    const float* conv_w     = (const float*)d_in[13];
    const float* conv_b     = (const float*)d_in[14];
    const float* x_proj_w   = (const float*)d_in[15];
    const float* dt_proj_w  = (const float*)d_in[16];
    const float* dt_proj_b  = (const float*)d_in[17];
    const float* A_log      = (const float*)d_in[18];
    const float* D_param    = (const float*)d_in[19];
    const float* out_proj_w = (const float*)d_in[20];
    const float* out_proj_b = (const float*)d_in[21];
    const float* norm_f_w   = (const float*)d_in[22];
    const float* norm_f_b   = (const float*)d_in[23];
    float* out = (float*)d_out;

    float *up_tmp, *h, *x, *xz, *xc, *xdbc, *dtb;
    cudaGetSymbolAddress((void**)&up_tmp, g_up_tmp);
    cudaGetSymbolAddress((void**)&h,      g_h);
    cudaGetSymbolAddress((void**)&x,      g_x);
    cudaGetSymbolAddress((void**)&xz,     g_xz);
    cudaGetSymbolAddress((void**)&xc,     g_xc);
    cudaGetSymbolAddress((void**)&xdbc,   g_xdbc);
    cudaGetSymbolAddress((void**)&dtb,    g_dt);

    __nv_bfloat16 *mo_h, *mo_l, *sk_h, *sk_l, *up_h, *up_l, *hh, *hl;
    __nv_bfloat16 *ln_h, *ln_l, *xc_h, *xc_l, *y_h, *y_l;
    __nv_bfloat16 *wupT_h, *wupT_l, *wb_h, *wb_l;
    cudaGetSymbolAddress((void**)&mo_h, g_mo_h);  cudaGetSymbolAddress((void**)&mo_l, g_mo_l);
    cudaGetSymbolAddress((void**)&sk_h, g_sk_h);  cudaGetSymbolAddress((void**)&sk_l, g_sk_l);
    cudaGetSymbolAddress((void**)&up_h, g_upb_h); cudaGetSymbolAddress((void**)&up_l, g_upb_l);
    cudaGetSymbolAddress((void**)&hh,   g_hh);    cudaGetSymbolAddress((void**)&hl,   g_hl);
    cudaGetSymbolAddress((void**)&ln_h, g_lnh);   cudaGetSymbolAddress((void**)&ln_l, g_lnl);
    cudaGetSymbolAddress((void**)&xc_h, g_xch);   cudaGetSymbolAddress((void**)&xc_l, g_xcl);
    cudaGetSymbolAddress((void**)&y_h,  g_yh);    cudaGetSymbolAddress((void**)&y_l,  g_yl);
    cudaGetSymbolAddress((void**)&wupT_h, g_wupT_h); cudaGetSymbolAddress((void**)&wupT_l, g_wupT_l);
    cudaGetSymbolAddress((void**)&wb_h, g_wb_h);  cudaGetSymbolAddress((void**)&wb_l, g_wb_l);

    cudaFuncSetAttribute(tgemm_k, cudaFuncAttributeMaxDynamicSharedMemorySize,
                         TGV_SMEM);

    // ---- weight + input conversion ----
    weights_conv_k<<<WB_TOTAL / 256, 256>>>(w1, w2, in_proj_w, x_proj_w,
                                            out_proj_w, wb_h, wb_l);
    transpose_wup_k<<<dim3(32, 16), dim3(32, 8)>>>(w_up, wupT_h, wupT_l);
    convert_pair_k<<<(4096 * 512 / 4) / 256, 256>>>(motion, mo_h, mo_l);
    convert_pair_k<<<(ROWS * 512 / 4) / 256, 256>>>(skip, sk_h, sk_l);

    // 1) up = motion @ w_up
    tgemm_k<<<dim3(8, 32), 256, TGV_SMEM>>>(
        mo_h, mo_l, 512, wupT_h, wupT_l, 512, up_tmp, 1024,
        nullptr, nullptr, 512, 0);

    // 2) rearrange + b_up -> bf16 pair
    up_rearrange_k<<<(ROWS * 512) / 256, 256>>>(up_tmp, b_up, up_h, up_l);

    // 3) h = up @ w1[:, :512]^T + b1 ; h += skip @ w1[:, 512:]^T
    tgemm_k<<<dim3(4, 64), 256, TGV_SMEM>>>(
        up_h, up_l, 512, wb_h + OFF_W1, wb_l + OFF_W1, 1024, h, 512,
        b1, nullptr, 512, 0);
    tgemm_k<<<dim3(4, 64), 256, TGV_SMEM>>>(
        sk_h, sk_l, 512, wb_h + OFF_W1 + 512, wb_l + OFF_W1 + 512, 1024, h, 512,
        nullptr, nullptr, 512, 1);

    // 4) silu(rmsnorm(h)) -> bf16 pair
    rmsnorm_silu_k<<<ROWS, 128>>>(h, rms_w, hh, hl);

    // 5) x = h @ w2^T + b2 + embed[b]
    tgemm_k<<<dim3(4, 64), 256, TGV_SMEM>>>(
        hh, hl, 512, wb_h + OFF_W2, wb_l + OFF_W2, 512, x, 512,
        b2, embed, 512, 0);

    // 6) mamba layers
    for (int i = 0; i < NDEPTH; i++) {
        layernorm_bf_k<<<ROWS, 128>>>(x, ln_w + i * 512, ln_b + i * 512, ln_h, ln_l);

        tgemm_k<<<dim3(16, 64), 256, TGV_SMEM>>>(
            ln_h, ln_l, 512,
            wb_h + OFF_IP + (size_t)i * SZ_IP, wb_l + OFF_IP + (size_t)i * SZ_IP, 512,
            xz, 2048, nullptr, nullptr, 512, 0);

        conv_silu_k<<<(ROWS * DI) / 256, 256>>>(
            xz, conv_w + (size_t)i * 1024 * 4, conv_b + i * 1024, xc, xc_h, xc_l);

        tgemm_k<<<dim3(1, 64), 256, TGV_SMEM>>>(
            xc_h, xc_l, 1024,
            wb_h + OFF_XP + (size_t)i * SZ_XP, wb_l + OFF_XP + (size_t)i * SZ_XP, 1024,
            xdbc, 128, nullptr, nullptr, 1024, 0);

        sgemm_k<<<dim3(8, 64), 256>>>(
            xdbc, 128, dt_proj_w + (size_t)i * 1024 * 32, 32,
            dtb, 1024, dt_proj_b + i * 1024, ROWS, 1024, 32, 1);

        scan_k<<<128, 128>>>(
            dtb, xc, xz, xdbc,
            A_log + (size_t)i * 1024 * 16, D_param + i * 1024, y_h, y_l);

        tgemm_k<<<dim3(4, 64), 256, TGV_SMEM>>>(
            y_h, y_l, 1024,
            wb_h + OFF_OP + (size_t)i * SZ_OP, wb_l + OFF_OP + (size_t)i * SZ_OP, 1024,
            x, 512, out_proj_b + i * 512, nullptr, 1024, 1);
    }

    // 7) final layernorm -> output
    layernorm_k<<<ROWS, 128>>>(x, norm_f_w, norm_f_b, out);
}

// round 12
// speedup vs baseline: 1.8334x; 1.0731x over previous
#include <cuda_runtime.h>
#include <cuda_bf16.h>
#include <math.h>
#include <stdint.h>

// ---------------- problem constants ----------------
#define BB    8
#define LSEQ  1024            // 2*L_IN
#define ROWS  (BB*LSEQ)       // 8192 tokens
#define CC    512
#define DI    1024
#define DS    16
#define NDEPTH 4

// weight-pack offsets (elements) in the converted bf16 weight bank
#define OFF_W1   0
#define SZ_W1    (512*1024)
#define OFF_W2   (OFF_W1 + SZ_W1)
#define SZ_W2    (512*512)
#define OFF_IP   (OFF_W2 + SZ_W2)
#define SZ_IP    (2048*512)
#define OFF_XP   (OFF_IP + 4*SZ_IP)
#define SZ_XP    (128*1024)
#define OFF_OP   (OFF_XP + 4*SZ_XP)
#define SZ_OP    (512*1024)
#define WB_TOTAL (OFF_OP + 4*SZ_OP)   // 7,602,176

// ---------------- scratch (device globals; no allocs allowed) ----------------
__device__ float g_up_tmp[4096*1024];   // up GEMM raw output
__device__ float g_h    [ROWS*CC];      // h1 (pre-rmsnorm)
__device__ float g_x    [ROWS*CC];      // residual stream
__device__ float g_xz   [ROWS*2*DI];    // in_proj out (xc_raw | z)
__device__ float g_xc   [ROWS*DI];      // conv+silu out f32 (scan u)
__device__ float g_xdbc [ROWS*128];     // x_proj out (dtp|B|C|pad), ld=128
__device__ float g_xpart[4*ROWS*128];   // x_proj split-K partials
__device__ float g_dt   [ROWS*DI];      // softplus dt

// bf16 hi/lo operand buffers
__device__ __align__(16) __nv_bfloat16 g_mo_h[4096*512],  g_mo_l[4096*512];
__device__ __align__(16) __nv_bfloat16 g_sk_h[ROWS*512],  g_sk_l[ROWS*512];
__device__ __align__(16) __nv_bfloat16 g_upb_h[ROWS*512], g_upb_l[ROWS*512];
__device__ __align__(16) __nv_bfloat16 g_hh[ROWS*512],    g_hl[ROWS*512];
__device__ __align__(16) __nv_bfloat16 g_lnh[ROWS*512],   g_lnl[ROWS*512];
__device__ __align__(16) __nv_bfloat16 g_xch[ROWS*1024],  g_xcl[ROWS*1024];
__device__ __align__(16) __nv_bfloat16 g_yh[ROWS*1024],   g_yl[ROWS*1024];
__device__ __align__(16) __nv_bfloat16 g_wupT_h[1024*512], g_wupT_l[1024*512];
__device__ __align__(16) __nv_bfloat16 g_wb_h[WB_TOTAL],   g_wb_l[WB_TOTAL];

// ---------------- helpers ----------------
__device__ __forceinline__ float softplusf(float x) {
    return (x > 20.f) ? x : log1pf(__expf(x));
}
__device__ __forceinline__ float siluf(float x) {
    return x / (1.f + __expf(-x));
}

__device__ __forceinline__ uint32_t smem_u32(const void* p) {
    uint32_t a;
    asm("{ .reg .u64 t; cvta.to.shared.u64 t, %1; cvt.u32.u64 %0, t; }"
        : "=r"(a) : "l"(p));
    return a;
}

__device__ __forceinline__ void split1(float v, __nv_bfloat16& h, __nv_bfloat16& l) {
    h = __float2bfloat16(v);
    l = __float2bfloat16(v - __bfloat162float(h));
}

// split f32x4 into bf16 hi / lo pairs (packed bf16x2 words, .x in low half)
__device__ __forceinline__ void split4(float4 v, uint32_t& h01, uint32_t& h23,
                                       uint32_t& l01, uint32_t& l23) {
    __nv_bfloat162 h0 = __float22bfloat162_rn(make_float2(v.x, v.y));
    __nv_bfloat162 h1 = __float22bfloat162_rn(make_float2(v.z, v.w));
    float2 f0 = __bfloat1622float2(h0), f1 = __bfloat1622float2(h1);
    __nv_bfloat162 l0 = __float22bfloat162_rn(make_float2(v.x - f0.x, v.y - f0.y));
    __nv_bfloat162 l1 = __float22bfloat162_rn(make_float2(v.z - f1.x, v.w - f1.y));
    h01 = *(uint32_t*)&h0; h23 = *(uint32_t*)&h1;
    l01 = *(uint32_t*)&l0; l23 = *(uint32_t*)&l1;
}

__device__ __forceinline__ void ldsm4(uint32_t* r, uint32_t addr) {
    asm volatile("ldmatrix.sync.aligned.m8n8.x4.shared.b16 {%0,%1,%2,%3}, [%4];"
        : "=r"(r[0]), "=r"(r[1]), "=r"(r[2]), "=r"(r[3]) : "r"(addr));
}

__device__ __forceinline__ void mma_bf16(float* c, const uint32_t* a, const uint32_t* b) {
    asm volatile("mma.sync.aligned.m16n8k16.row.col.f32.bf16.bf16.f32 "
        "{%0,%1,%2,%3}, {%4,%5,%6,%7}, {%8,%9}, {%0,%1,%2,%3};"
        : "+f"(c[0]), "+f"(c[1]), "+f"(c[2]), "+f"(c[3])
        : "r"(a[0]), "r"(a[1]), "r"(a[2]), "r"(a[3]), "r"(b[0]), "r"(b[1]));
}

#define CP16(dst, src) \
    asm volatile("cp.async.cg.shared.global [%0], [%1], 16;" \
                 :: "r"(dst), "l"(src) : "memory")
#define CP_COMMIT() asm volatile("cp.async.commit_group;" ::: "memory")
#define CP_WAIT0()  asm volatile("cp.async.wait_group 0;" ::: "memory")

// ============================================================================
// tensor-core GEMM v3.1: bf16 hi/lo operands, cp.async double-buffer pipeline,
// split-K via blockIdx.z (K = per-split chunk; C += z*zstrC; use beta=0).
// C[M,N] = (Ah+Al)[M,K] @ (Bh+Bl)[N,K]^T (3-term) (+bias)(+rowvec)(+beta*C)
// Block 128x128, BK=32, 8 warps (2x4). XOR-swizzled 64B rows.
// ============================================================================
#define TGV_REGION 8192
#define TGV_STAGE  32768
#define TGV_SMEM   65536

__global__ __launch_bounds__(256, 2)
void tgemm_k(const __nv_bfloat16* __restrict__ Ah, const __nv_bfloat16* __restrict__ Al,
             int lda,
             const __nv_bfloat16* __restrict__ Bh, const __nv_bfloat16* __restrict__ Bl,
             int ldb,
             float* __restrict__ C, int ldc,
             const float* __restrict__ bias,
             const float* __restrict__ rowvec,
             int K, int beta, int zstrC)
{
    extern __shared__ __align__(16) char smem[];
    const uint32_t sb = smem_u32(smem);
    const int tid  = threadIdx.x;
    const int wid  = tid >> 5;
    const int lane = tid & 31;
    const int m0 = blockIdx.y * 128;
    const int n0 = blockIdx.x * 128;
    const int kz = blockIdx.z * K;          // split-K offset
    C += (size_t)blockIdx.z * zstrC;
    const int wm = wid >> 2;
    const int wn = wid & 3;

    float acc[4][4][4];
#pragma unroll
    for (int i = 0; i < 4; i++)
#pragma unroll
        for (int j = 0; j < 4; j++)
#pragma unroll
            for (int k = 0; k < 4; k++) acc[i][j][k] = 0.f;

    // ---- cp.async staging geometry ----
    const int s_row = tid >> 1;
    const int c0    = (tid & 1) * 2;
    const int ssw   = (s_row >> 1) & 3;
    const uint32_t d0 = (uint32_t)(s_row * 64 + ((c0     ^ ssw) * 16));
    const uint32_t d1 = (uint32_t)(s_row * 64 + (((c0+1) ^ ssw) * 16));
    const __nv_bfloat16* Ah_s = Ah + (size_t)(m0 + s_row) * lda + kz + c0 * 8;
    const __nv_bfloat16* Al_s = Al + (size_t)(m0 + s_row) * lda + kz + c0 * 8;
    const __nv_bfloat16* Bh_s = Bh + (size_t)(n0 + s_row) * ldb + kz + c0 * 8;
    const __nv_bfloat16* Bl_s = Bl + (size_t)(n0 + s_row) * ldb + kz + c0 * 8;

    // ---- ldmatrix relative offsets (XOR swizzle baked in) ----
    const int q  = lane >> 3;
    const int r8 = lane & 7;
    const int qh = q >> 1;
    const int qb = q & 1;
    uint32_t a_rel[4][2], b_rel[2][2];
#pragma unroll
    for (int mt = 0; mt < 4; mt++) {
        const int ar = wm * 64 + mt * 16 + (q & 1) * 8 + r8;
        const int sw = (ar >> 1) & 3;
#pragma unroll
        for (int ks = 0; ks < 2; ks++)
            a_rel[mt][ks] = (uint32_t)(ar * 64 + (((ks * 2 + qh) ^ sw) * 16));
    }
#pragma unroll
    for (int h = 0; h < 2; h++) {
        const int br = wn * 32 + h * 16 + (q >> 1) * 8 + r8;
        const int sw = (br >> 1) & 3;
#pragma unroll
        for (int ks = 0; ks < 2; ks++)
            b_rel[h][ks] = (uint32_t)(2 * TGV_REGION + br * 64 + (((ks * 2 + qb) ^ sw) * 16));
    }

    const int chunks = K >> 5;

    // prologue
    {
        const uint32_t s0 = sb;
        CP16(s0 + d0, Ah_s);                    CP16(s0 + d1, Ah_s + 8);
        CP16(s0 + TGV_REGION + d0, Al_s);       CP16(s0 + TGV_REGION + d1, Al_s + 8);
        CP16(s0 + 2*TGV_REGION + d0, Bh_s);     CP16(s0 + 2*TGV_REGION + d1, Bh_s + 8);
        CP16(s0 + 3*TGV_REGION + d0, Bl_s);     CP16(s0 + 3*TGV_REGION + d1, Bl_s + 8);
        CP_COMMIT();
    }

    for (int c = 0; c < chunks; c++) {
        CP_WAIT0();
        __syncthreads();
        const uint32_t sbuf = sb + (uint32_t)(c & 1) * TGV_STAGE;
        if (c + 1 < chunks) {
            const uint32_t sn = sb + (uint32_t)((c + 1) & 1) * TGV_STAGE;
            const int ko = (c + 1) * 32;
            CP16(sn + d0, Ah_s + ko);                CP16(sn + d1, Ah_s + ko + 8);
            CP16(sn + TGV_REGION + d0, Al_s + ko);   CP16(sn + TGV_REGION + d1, Al_s + ko + 8);
            CP16(sn + 2*TGV_REGION + d0, Bh_s + ko); CP16(sn + 2*TGV_REGION + d1, Bh_s + ko + 8);
            CP16(sn + 3*TGV_REGION + d0, Bl_s + ko); CP16(sn + 3*TGV_REGION + d1, Bl_s + ko + 8);
            CP_COMMIT();
        }

#pragma unroll
        for (int ks = 0; ks < 2; ks++) {
            uint32_t bh[2][4], bl[2][4];
            ldsm4(bh[0], sbuf + b_rel[0][ks]);
            ldsm4(bh[1], sbuf + b_rel[1][ks]);
            ldsm4(bl[0], sbuf + b_rel[0][ks] + TGV_REGION);
            ldsm4(bl[1], sbuf + b_rel[1][ks] + TGV_REGION);
#pragma unroll
            for (int mt = 0; mt < 4; mt++) {
                uint32_t ah[4], al[4];
                ldsm4(ah, sbuf + a_rel[mt][ks]);
                ldsm4(al, sbuf + a_rel[mt][ks] + TGV_REGION);
#pragma unroll
                for (int nt = 0; nt < 4; nt++) {
                    const uint32_t* bhp = &bh[nt >> 1][(nt & 1) * 2];
                    const uint32_t* blp = &bl[nt >> 1][(nt & 1) * 2];
                    mma_bf16(acc[mt][nt], ah, bhp);
                    mma_bf16(acc[mt][nt], ah, blp);
                    mma_bf16(acc[mt][nt], al, bhp);
                }
            }
        }
    }

    // epilogue
    const int er = lane >> 2;
    const int ec = (lane & 3) * 2;
    const int colbase = n0 + wn * 32 + ec;
#pragma unroll
    for (int mt = 0; mt < 4; mt++) {
#pragma unroll
        for (int half = 0; half < 2; half++) {
            const int row = m0 + wm * 64 + mt * 16 + er + half * 8;
            float* cp = C + (size_t)row * ldc + colbase;
            const float* rv = rowvec ? rowvec + (size_t)(row >> 10) * ldc + colbase
                                     : nullptr;
#pragma unroll
            for (int nt = 0; nt < 4; nt++) {
                float v0 = acc[mt][nt][half * 2 + 0];
                float v1 = acc[mt][nt][half * 2 + 1];
                const int co = nt * 8;
                if (bias) { v0 += bias[colbase + co]; v1 += bias[colbase + co + 1]; }
                if (rv)   { v0 += rv[co];             v1 += rv[co + 1]; }
                if (beta) { v0 += cp[co];             v1 += cp[co + 1]; }
                *(float2*)(cp + co) = make_float2(v0, v1);
            }
        }
    }
}

// 4-way split-K reduce: out[i] = sum_z parts[z][i], vectorized float4
__global__ void reduce4_k(const float* __restrict__ p, float* __restrict__ out)
{
    const int i = blockIdx.x * 256 + threadIdx.x;   // over ROWS*128/4
    const int STR = ROWS * 128 / 4;
    float4 a = ((const float4*)p)[i];
    float4 b = ((const float4*)p)[i + STR];
    float4 c = ((const float4*)p)[i + 2 * STR];
    float4 d = ((const float4*)p)[i + 3 * STR];
    float4 o;
    o.x = (a.x + b.x) + (c.x + d.x);
    o.y = (a.y + b.y) + (c.y + d.y);
    o.z = (a.z + b.z) + (c.z + d.z);
    o.w = (a.w + b.w) + (c.w + d.w);
    ((float4*)out)[i] = o;
}

// ============================================================================
// SIMT SGEMM (fmaf, BK=16, double-buffered) — dt_proj only
// ============================================================================
__global__ __launch_bounds__(256, 2)
void sgemm_k(const float* __restrict__ A, int lda,
             const float* __restrict__ B, int ldb,
             float* __restrict__ C, int ldc,
             const float* __restrict__ bias,
             int M, int N, int K, int do_softplus)
{
    __shared__ float As[2][16][128];
    __shared__ float Bs[2][16][128];

    const int tid = threadIdx.x;
    const int m0 = blockIdx.y * 128;
    const int n0 = blockIdx.x * 128;
    const int ty = tid >> 4;
    const int tx = tid & 15;

    const int a_r = tid >> 2;
    const int a_c = (tid & 3) * 4;
    const int b_r = a_r;
    const int b_c = a_c;

    float acc[8][8];
#pragma unroll
    for (int i = 0; i < 8; i++)
#pragma unroll
        for (int j = 0; j < 8; j++) acc[i][j] = 0.f;

    const float* Ab = A + (size_t)m0 * lda;
    float4 a0, a1, b0, b1;

    a0 = *(const float4*)(Ab + (size_t)a_r * lda + a_c);
    a1 = *(const float4*)(Ab + (size_t)(a_r + 64) * lda + a_c);
    b0 = make_float4(0.f, 0.f, 0.f, 0.f); b1 = b0;
    if (n0 + b_r < N)
        b0 = *(const float4*)(B + (size_t)(n0 + b_r) * ldb + b_c);
    if (n0 + b_r + 64 < N)
        b1 = *(const float4*)(B + (size_t)(n0 + b_r + 64) * ldb + b_c);
    {
        As[0][a_c + 0][a_r] = a0.x; As[0][a_c + 1][a_r] = a0.y;
        As[0][a_c + 2][a_r] = a0.z; As[0][a_c + 3][a_r] = a0.w;
        As[0][a_c + 0][a_r + 64] = a1.x; As[0][a_c + 1][a_r + 64] = a1.y;
        As[0][a_c + 2][a_r + 64] = a1.z; As[0][a_c + 3][a_r + 64] = a1.w;
        Bs[0][b_c + 0][b_r] = b0.x; Bs[0][b_c + 1][b_r] = b0.y;
        Bs[0][b_c + 2][b_r] = b0.z; Bs[0][b_c + 3][b_r] = b0.w;
        Bs[0][b_c + 0][b_r + 64] = b1.x; Bs[0][b_c + 1][b_r + 64] = b1.y;
        Bs[0][b_c + 2][b_r + 64] = b1.z; Bs[0][b_c + 3][b_r + 64] = b1.w;
    }
    __syncthreads();

    int buf = 0;
    for (int k0 = 0; k0 < K; k0 += 16) {
        const bool nxt = (k0 + 16 < K);
        if (nxt) {
            const int kn = k0 + 16;
            a0 = *(const float4*)(Ab + (size_t)a_r * lda + kn + a_c);
            a1 = *(const float4*)(Ab + (size_t)(a_r + 64) * lda + kn + a_c);
            b0 = make_float4(0.f, 0.f, 0.f, 0.f); b1 = b0;
            if (n0 + b_r < N)
                b0 = *(const float4*)(B + (size_t)(n0 + b_r) * ldb + kn + b_c);
            if (n0 + b_r + 64 < N)
                b1 = *(const float4*)(B + (size_t)(n0 + b_r + 64) * ldb + kn + b_c);
        }

#pragma unroll
        for (int kk = 0; kk < 16; kk++) {
            float arr[8], brr[8];
            *(float4*)&arr[0] = *(const float4*)&As[buf][kk][ty * 8];
            *(float4*)&arr[4] = *(const float4*)&As[buf][kk][ty * 8 + 4];
            *(float4*)&brr[0] = *(const float4*)&Bs[buf][kk][tx * 8];
            *(float4*)&brr[4] = *(const float4*)&Bs[buf][kk][tx * 8 + 4];
#pragma unroll
            for (int i = 0; i < 8; i++)
#pragma unroll
                for (int j = 0; j < 8; j++)
                    acc[i][j] = fmaf(arr[i], brr[j], acc[i][j]);
        }

        if (nxt) {
            const int nb = buf ^ 1;
            As[nb][a_c + 0][a_r] = a0.x; As[nb][a_c + 1][a_r] = a0.y;
            As[nb][a_c + 2][a_r] = a0.z; As[nb][a_c + 3][a_r] = a0.w;
            As[nb][a_c + 0][a_r + 64] = a1.x; As[nb][a_c + 1][a_r + 64] = a1.y;
            As[nb][a_c + 2][a_r + 64] = a1.z; As[nb][a_c + 3][a_r + 64] = a1.w;
            Bs[nb][b_c + 0][b_r] = b0.x; Bs[nb][b_c + 1][b_r] = b0.y;
            Bs[nb][b_c + 2][b_r] = b0.z; Bs[nb][b_c + 3][b_r] = b0.w;
            Bs[nb][b_c + 0][b_r + 64] = b1.x; Bs[nb][b_c + 1][b_r + 64] = b1.y;
            Bs[nb][b_c + 2][b_r + 64] = b1.z; Bs[nb][b_c + 3][b_r + 64] = b1.w;
            __syncthreads();
            buf = nb;
        }
    }

    const int col = n0 + tx * 8;
    if (col >= N) return;

#pragma unroll
    for (int i = 0; i < 8; i++) {
        const int row = m0 + ty * 8 + i;
        float* cp = C + (size_t)row * ldc + col;
        float v[8];
#pragma unroll
        for (int j = 0; j < 8; j++) {
            float t = acc[i][j];
            if (bias) t += bias[col + j];
            if (do_softplus) t = softplusf(t);
            v[j] = t;
        }
        *(float4*)cp       = *(float4*)&v[0];
        *(float4*)(cp + 4) = *(float4*)&v[4];
    }
}

// ---------------- weight prep ----------------
__global__ void weights_conv_k(const float* __restrict__ w1,
                               const float* __restrict__ w2,
                               const float* __restrict__ ipw,
                               const float* __restrict__ xpw,
                               const float* __restrict__ opw,
                               __nv_bfloat16* __restrict__ wh,
                               __nv_bfloat16* __restrict__ wl)
{
    const int idx = blockIdx.x * 256 + threadIdx.x;
    float v;
    if (idx < OFF_W2)       v = w1[idx];
    else if (idx < OFF_IP)  v = w2[idx - OFF_W2];
    else if (idx < OFF_XP)  v = ipw[idx - OFF_IP];
    else if (idx < OFF_OP) {
        const int l = idx - OFF_XP;
        const int layer = l / SZ_XP;
        const int r = l % SZ_XP;
        const int row = r >> 10, col = r & 1023;
        v = (row < 64) ? xpw[layer * 64 * 1024 + row * 1024 + col] : 0.f;
    } else                  v = opw[idx - OFF_OP];
    __nv_bfloat16 h, l;
    split1(v, h, l);
    wh[idx] = h; wl[idx] = l;
}

__global__ void transpose_wup_k(const float* __restrict__ in,
                                __nv_bfloat16* __restrict__ oh,
                                __nv_bfloat16* __restrict__ ol)
{
    __shared__ float t[32][33];
    const int bx = blockIdx.x, by = blockIdx.y;
    {
        const int x = bx * 32 + threadIdx.x;
        const int y = by * 32 + threadIdx.y;
#pragma unroll
        for (int i = 0; i < 32; i += 8)
            t[threadIdx.y + i][threadIdx.x] = in[(size_t)(y + i) * 1024 + x];
    }
    __syncthreads();
    {
        const int x = by * 32 + threadIdx.x;
        const int y = bx * 32 + threadIdx.y;
#pragma unroll
        for (int i = 0; i < 32; i += 8) {
            __nv_bfloat16 h, l;
            split1(t[threadIdx.x][threadIdx.y + i], h, l);
            oh[(size_t)(y + i) * 512 + x] = h;
            ol[(size_t)(y + i) * 512 + x] = l;
        }
    }
}

__global__ void convert_pair_k(const float* __restrict__ src,
                               __nv_bfloat16* __restrict__ h,
                               __nv_bfloat16* __restrict__ l)
{
    const int i = blockIdx.x * 256 + threadIdx.x;
    float4 v = ((const float4*)src)[i];
    uint32_t h01, h23, l01, l23;
    split4(v, h01, h23, l01, l23);
    ((uint2*)h)[i] = make_uint2(h01, h23);
    ((uint2*)l)[i] = make_uint2(l01, l23);
}

// ---------------- layernorm -> f32 out (final) ----------------
__global__ void layernorm_k(const float* __restrict__ x,
                            const float* __restrict__ w,
                            const float* __restrict__ b,
                            float* __restrict__ out)
{
    const int row = blockIdx.x;
    const int tid = threadIdx.x;
    float4 v = ((const float4*)(x + (size_t)row * 512))[tid];
    float s  = v.x + v.y + v.z + v.w;
    float sq = v.x * v.x + v.y * v.y + v.z * v.z + v.w * v.w;
#pragma unroll
    for (int o = 16; o > 0; o >>= 1) {
        s  += __shfl_xor_sync(0xffffffffu, s,  o);
        sq += __shfl_xor_sync(0xffffffffu, sq, o);
    }
    __shared__ float ss[4], ssq[4];
    const int wid = tid >> 5;
    if ((tid & 31) == 0) { ss[wid] = s; ssq[wid] = sq; }
    __syncthreads();
    s  = ss[0]  + ss[1]  + ss[2]  + ss[3];
    sq = ssq[0] + ssq[1] + ssq[2] + ssq[3];
    const float m   = s  * (1.f / 512.f);
    const float var = sq * (1.f / 512.f) - m * m;
    const float inv = rsqrtf(var + 1e-5f);
    float4 wv = ((const float4*)w)[tid];
    float4 bv = ((const float4*)b)[tid];
    float4 o4;
    o4.x = (v.x - m) * inv * wv.x + bv.x;
    o4.y = (v.y - m) * inv * wv.y + bv.y;
    o4.z = (v.z - m) * inv * wv.z + bv.z;
    o4.w = (v.w - m) * inv * wv.w + bv.w;
    ((float4*)(out + (size_t)row * 512))[tid] = o4;
}

// ---------------- layernorm -> bf16 hi/lo pair ----------------
__global__ void layernorm_bf_k(const float* __restrict__ x,
                               const float* __restrict__ w,
                               const float* __restrict__ b,
                               __nv_bfloat16* __restrict__ oh,
                               __nv_bfloat16* __restrict__ ol)
{
    const int row = blockIdx.x;
    const int tid = threadIdx.x;
    float4 v = ((const float4*)(x + (size_t)row * 512))[tid];
    float s  = v.x + v.y + v.z + v.w;
    float sq = v.x * v.x + v.y * v.y + v.z * v.z + v.w * v.w;
#pragma unroll
    for (int o = 16; o > 0; o >>= 1) {
        s  += __shfl_xor_sync(0xffffffffu, s,  o);
        sq += __shfl_xor_sync(0xffffffffu, sq, o);
    }
    __shared__ float ss[4], ssq[4];
    const int wid = tid >> 5;
    if ((tid & 31) == 0) { ss[wid] = s; ssq[wid] = sq; }
    __syncthreads();
    s  = ss[0]  + ss[1]  + ss[2]  + ss[3];
    sq = ssq[0] + ssq[1] + ssq[2] + ssq[3];
    const float m   = s  * (1.f / 512.f);
    const float var = sq * (1.f / 512.f) - m * m;
    const float inv = rsqrtf(var + 1e-5f);
    float4 wv = ((const float4*)w)[tid];
    float4 bv = ((const float4*)b)[tid];
    float4 o4;
    o4.x = (v.x - m) * inv * wv.x + bv.x;
    o4.y = (v.y - m) * inv * wv.y + bv.y;
    o4.z = (v.z - m) * inv * wv.z + bv.z;
    o4.w = (v.w - m) * inv * wv.w + bv.w;
    uint32_t h01, h23, l01, l23;
    split4(o4, h01, h23, l01, l23);
    ((uint2*)(oh + (size_t)row * 512))[tid] = make_uint2(h01, h23);
    ((uint2*)(ol + (size_t)row * 512))[tid] = make_uint2(l01, l23);
}

// ---------------- rmsnorm + silu -> bf16 hi/lo pair ----------------
__global__ void rmsnorm_silu_k(const float* __restrict__ x,
                               const float* __restrict__ w,
                               __nv_bfloat16* __restrict__ oh,
                               __nv_bfloat16* __restrict__ ol)
{
    const int row = blockIdx.x;
    const int tid = threadIdx.x;
    float4 v = ((const float4*)(x + (size_t)row * 512))[tid];
    float sq = v.x * v.x + v.y * v.y + v.z * v.z + v.w * v.w;
#pragma unroll
    for (int o = 16; o > 0; o >>= 1) sq += __shfl_xor_sync(0xffffffffu, sq, o);
    __shared__ float ssq[4];
    const int wid = tid >> 5;
    if ((tid & 31) == 0) ssq[wid] = sq;
    __syncthreads();
    sq = ssq[0] + ssq[1] + ssq[2] + ssq[3];
    const float inv = rsqrtf(sq * (1.f / 512.f) + 1e-5f);
    float4 wv = ((const float4*)w)[tid];
    float4 o4;
    float a;
    a = v.x * inv * wv.x; o4.x = siluf(a);
    a = v.y * inv * wv.y; o4.y = siluf(a);
    a = v.z * inv * wv.z; o4.z = siluf(a);
    a = v.w * inv * wv.w; o4.w = siluf(a);
    uint32_t h01, h23, l01, l23;
    split4(o4, h01, h23, l01, l23);
    ((uint2*)(oh + (size_t)row * 512))[tid] = make_uint2(h01, h23);
    ((uint2*)(ol + (size_t)row * 512))[tid] = make_uint2(l01, l23);
}

// ---------------- up rearrange -> bf16 hi/lo (+b_up) ----------------
__global__ void up_rearrange_k(const float* __restrict__ up_tmp,
                               const float* __restrict__ b_up,
                               __nv_bfloat16* __restrict__ oh,
                               __nv_bfloat16* __restrict__ ol)
{
    const int idx  = blockIdx.x * blockDim.x + threadIdx.x;
    const int o    = idx & 511;
    const int orow = idx >> 9;
    const int b    = orow >> 10;
    const int t    = orow & 1023;
    const int l    = t >> 1;
    const int k    = t & 1;
    const float v = up_tmp[(size_t)(b * 512 + l) * 1024 + o * 2 + k] + b_up[o];
    __nv_bfloat16 h, lo;
    split1(v, h, lo);
    oh[idx] = h; ol[idx] = lo;
}

// ---------------- causal depthwise conv(4) + bias + silu ----------------
__global__ void conv_silu_k(const float* __restrict__ xz,
                            const float* __restrict__ cw,
                            const float* __restrict__ cb,
                            float* __restrict__ xc,
                            __nv_bfloat16* __restrict__ oh,
                            __nv_bfloat16* __restrict__ ol)
{
    const int idx = blockIdx.x * blockDim.x + threadIdx.x;
    const int d   = idx & 1023;
    const int row = idx >> 10;
    const int t   = row & 1023;
    float acc = cb[d];
#pragma unroll
    for (int j = 0; j < 4; j++) {
        const int tt = t - 3 + j;
        if (tt >= 0)
            acc = fmaf(cw[d * 4 + j], xz[(size_t)(row - 3 + j) * 2048 + d], acc);
    }
    const float v = siluf(acc);
    xc[idx] = v;
    __nv_bfloat16 h, l;
    split1(v, h, l);
    oh[idx] = h; ol[idx] = l;
}

// ---------------- selective scan: 4 threads per channel ----------------
// lanes 4k..4k+3 split the 16 states (4 each); 2-level shfl reduce.
__global__ __launch_bounds__(128)
void scan_k(const float* __restrict__ dt,
            const float* __restrict__ xc,
            const float* __restrict__ xz,
            const float* __restrict__ xdbc,    // [ROWS,128]: dtp|B|C|pad
            const float* __restrict__ A_log,
            const float* __restrict__ Dp,
            __nv_bfloat16* __restrict__ yh,
            __nv_bfloat16* __restrict__ yl)
{
    __shared__ __align__(16) float bc_s[32][32];

    const int tid     = threadIdx.x;         // 128
    const int quarter = tid & 3;
    const int dloc    = tid >> 2;             // 0..31
    const int b       = blockIdx.x >> 5;      // 0..7
    const int d       = (blockIdx.x & 31) * 32 + dloc;
    const int n0      = quarter * 4;

    float A2[4], h[4];
#pragma unroll
    for (int j = 0; j < 4; j++) {
        A2[j] = -__expf(A_log[d * 16 + n0 + j]) * 1.44269504f;
        h[j]  = 0.f;
    }
    const float Dd = Dp[d];

    const float* dtp = dt   + (size_t)b * 1024 * 1024 + d;
    const float* up  = xc   + (size_t)b * 1024 * 1024 + d;
    const float* zp  = xz   + (size_t)b * 1024 * 2048 + 1024 + d;
    const float* bcb = xdbc + (size_t)b * 1024 * 128 + 32;
    __nv_bfloat16* yhp = yh + (size_t)b * 1024 * 1024 + d;
    __nv_bfloat16* ylp = yl + (size_t)b * 1024 * 1024 + d;

    const int st_t = tid >> 2;
    const int st_c = (tid & 3) * 8;

    for (int c = 0; c < 32; c++) {
        __syncthreads();
        {
            const float* src = bcb + (size_t)(c * 32 + st_t) * 128 + st_c;
            *(float4*)&bc_s[st_t][st_c]     = *(const float4*)src;
            *(float4*)&bc_s[st_t][st_c + 4] = *(const float4*)(src + 4);
        }
        __syncthreads();

#pragma unroll
        for (int s = 0; s < 4; s++) {
            const int tbase = c * 32 + s * 8;
            float dt8[8], u8[8], z8[8];
#pragma unroll
            for (int j = 0; j < 8; j++) {
                dt8[j] = dtp[(size_t)(tbase + j) * 1024];
                u8[j]  = up [(size_t)(tbase + j) * 1024];
                z8[j]  = zp [(size_t)(tbase + j) * 2048];
            }
#pragma unroll
            for (int j = 0; j < 8; j++) {
                const int tt = s * 8 + j;
                float Bv[4], Cv[4];
                *(float4*)&Bv[0] = *(const float4*)&bc_s[tt][n0];
                *(float4*)&Cv[0] = *(const float4*)&bc_s[tt][16 + n0];
                const float dtv = dt8[j];
                const float u   = u8[j];
                const float du  = dtv * u;
                float ya = 0.f, yb2 = 0.f;
#pragma unroll
                for (int n = 0; n < 4; n++) {
                    const float dA = exp2f(dtv * A2[n]);
                    h[n] = fmaf(dA, h[n], du * Bv[n]);
                    if (n & 1) yb2 = fmaf(h[n], Cv[n], yb2);
                    else       ya  = fmaf(h[n], Cv[n], ya);
                }
                float ysum = ya + yb2;
                ysum += __shfl_xor_sync(0xffffffffu, ysum, 1);
                ysum += __shfl_xor_sync(0xffffffffu, ysum, 2);
                if (quarter == 0) {
                    const float w = (ysum + u * Dd) * siluf(z8[j]);
                    __nv_bfloat16 wh, wl;
                    split1(w, wh, wl);
                    yhp[(size_t)(tbase + j) * 1024] = wh;
                    ylp[(size_t)(tbase + j) * 1024] = wl;
                }
            }
        }
    }
}

// ---------------- launcher ----------------
extern "C" void kernel_launch(void* const* d_in, const int* in_sizes, int n_in,
                              void* d_out, int out_size)
{
    (void)in_sizes; (void)n_in; (void)out_size;

    const float* motion     = (const float*)d_in[0];
    const float* skip       = (const float*)d_in[1];
    const float* embed      = (const float*)d_in[2];
    const float* w_up       = (const float*)d_in[3];
    const float* b_up       = (const float*)d_in[4];
    const float* w1         = (const float*)d_in[5];
    const float* b1         = (const float*)d_in[6];
    const float* rms_w      = (const float*)d_in[7];
    const float* w2         = (const float*)d_in[8];
    const float* b2         = (const float*)d_in[9];
    const float* ln_w       = (const float*)d_in[10];
    const float* ln_b       = (const float*)d_in[11];
    const float* in_proj_w  = (const float*)d_in[12];
    const float* conv_w     = (const float*)d_in[13];
    const float* conv_b     = (const float*)d_in[14];
    const float* x_proj_w   = (const float*)d_in[15];
    const float* dt_proj_w  = (const float*)d_in[16];
    const float* dt_proj_b  = (const float*)d_in[17];
    const float* A_log      = (const float*)d_in[18];
    const float* D_param    = (const float*)d_in[19];
    const float* out_proj_w = (const float*)d_in[20];
    const float* out_proj_b = (const float*)d_in[21];
    const float* norm_f_w   = (const float*)d_in[22];
    const float* norm_f_b   = (const float*)d_in[23];
    float* out = (float*)d_out;

    float *up_tmp, *h, *x, *xz, *xc, *xdbc, *xpart, *dtb;
    cudaGetSymbolAddress((void**)&up_tmp, g_up_tmp);
    cudaGetSymbolAddress((void**)&h,      g_h);
    cudaGetSymbolAddress((void**)&x,      g_x);
    cudaGetSymbolAddress((void**)&xz,     g_xz);
    cudaGetSymbolAddress((void**)&xc,     g_xc);
    cudaGetSymbolAddress((void**)&xdbc,   g_xdbc);
    cudaGetSymbolAddress((void**)&xpart,  g_xpart);
    cudaGetSymbolAddress((void**)&dtb,    g_dt);

    __nv_bfloat16 *mo_h, *mo_l, *sk_h, *sk_l, *up_h, *up_l, *hh, *hl;
    __nv_bfloat16 *ln_h, *ln_l, *xc_h, *xc_l, *y_h, *y_l;
    __nv_bfloat16 *wupT_h, *wupT_l, *wb_h, *wb_l;
    cudaGetSymbolAddress((void**)&mo_h, g_mo_h);  cudaGetSymbolAddress((void**)&mo_l, g_mo_l);
    cudaGetSymbolAddress((void**)&sk_h, g_sk_h);  cudaGetSymbolAddress((void**)&sk_l, g_sk_l);
    cudaGetSymbolAddress((void**)&up_h, g_upb_h); cudaGetSymbolAddress((void**)&up_l, g_upb_l);
    cudaGetSymbolAddress((void**)&hh,   g_hh);    cudaGetSymbolAddress((void**)&hl,   g_hl);
    cudaGetSymbolAddress((void**)&ln_h, g_lnh);   cudaGetSymbolAddress((void**)&ln_l, g_lnl);
    cudaGetSymbolAddress((void**)&xc_h, g_xch);   cudaGetSymbolAddress((void**)&xc_l, g_xcl);
    cudaGetSymbolAddress((void**)&y_h,  g_yh);    cudaGetSymbolAddress((void**)&y_l,  g_yl);
    cudaGetSymbolAddress((void**)&wupT_h, g_wupT_h); cudaGetSymbolAddress((void**)&wupT_l, g_wupT_l);
    cudaGetSymbolAddress((void**)&wb_h, g_wb_h);  cudaGetSymbolAddress((void**)&wb_l, g_wb_l);

    cudaFuncSetAttribute(tgemm_k, cudaFuncAttributeMaxDynamicSharedMemorySize,
                         TGV_SMEM);

    // ---- weight + input conversion ----
    weights_conv_k<<<WB_TOTAL / 256, 256>>>(w1, w2, in_proj_w, x_proj_w,
                                            out_proj_w, wb_h, wb_l);
    transpose_wup_k<<<dim3(32, 16), dim3(32, 8)>>>(w_up, wupT_h, wupT_l);
    convert_pair_k<<<(4096 * 512 / 4) / 256, 256>>>(motion, mo_h, mo_l);
    convert_pair_k<<<(ROWS * 512 / 4) / 256, 256>>>(skip, sk_h, sk_l);

    // 1) up = motion @ w_up
    tgemm_k<<<dim3(8, 32), 256, TGV_SMEM>>>(
        mo_h, mo_l, 512, wupT_h, wupT_l, 512, up_tmp, 1024,
        nullptr, nullptr, 512, 0, 0);

    // 2) rearrange + b_up -> bf16 pair
    up_rearrange_k<<<(ROWS * 512) / 256, 256>>>(up_tmp, b_up, up_h, up_l);

    // 3) h = up @ w1[:, :512]^T + b1 ; h += skip @ w1[:, 512:]^T
    tgemm_k<<<dim3(4, 64), 256, TGV_SMEM>>>(
        up_h, up_l, 512, wb_h + OFF_W1, wb_l + OFF_W1, 1024, h, 512,
        b1, nullptr, 512, 0, 0);
    tgemm_k<<<dim3(4, 64), 256, TGV_SMEM>>>(
        sk_h, sk_l, 512, wb_h + OFF_W1 + 512, wb_l + OFF_W1 + 512, 1024, h, 512,
        nullptr, nullptr, 512, 1, 0);

    // 4) silu(rmsnorm(h)) -> bf16 pair
    rmsnorm_silu_k<<<ROWS, 128>>>(h, rms_w, hh, hl);

    // 5) x = h @ w2^T + b2 + embed[b]
    tgemm_k<<<dim3(4, 64), 256, TGV_SMEM>>>(
        hh, hl, 512, wb_h + OFF_W2, wb_l + OFF_W2, 512, x, 512,
        b2, embed, 512, 0, 0);

    // 6) mamba layers
    for (int i = 0; i < NDEPTH; i++) {
        layernorm_bf_k<<<ROWS, 128>>>(x, ln_w + i * 512, ln_b + i * 512, ln_h, ln_l);

        tgemm_k<<<dim3(16, 64), 256, TGV_SMEM>>>(
            ln_h, ln_l, 512,
            wb_h + OFF_IP + (size_t)i * SZ_IP, wb_l + OFF_IP + (size_t)i * SZ_IP, 512,
            xz, 2048, nullptr, nullptr, 512, 0, 0);

        conv_silu_k<<<(ROWS * DI) / 256, 256>>>(
            xz, conv_w + (size_t)i * 1024 * 4, conv_b + i * 1024, xc, xc_h, xc_l);

        // x_proj split-K=4: grid (1,64,4), K_part=256, partials -> reduce
        tgemm_k<<<dim3(1, 64, 4), 256, TGV_SMEM>>>(
            xc_h, xc_l, 1024,
            wb_h + OFF_XP + (size_t)i * SZ_XP, wb_l + OFF_XP + (size_t)i * SZ_XP, 1024,
            xpart, 128, nullptr, nullptr, 256, 0, ROWS * 128);
        reduce4_k<<<(ROWS * 128 / 4) / 256, 256>>>(xpart, xdbc);

        sgemm_k<<<dim3(8, 64), 256>>>(
            xdbc, 128, dt_proj_w + (size_t)i * 1024 * 32, 32,
            dtb, 1024, dt_proj_b + i * 1024, ROWS, 1024, 32, 1);

        scan_k<<<256, 128>>>(
            dtb, xc, xz, xdbc,
            A_log + (size_t)i * 1024 * 16, D_param + i * 1024, y_h, y_l);

        tgemm_k<<<dim3(4, 64), 256, TGV_SMEM>>>(
            y_h, y_l, 1024,
            wb_h + OFF_OP + (size_t)i * SZ_OP, wb_l + OFF_OP + (size_t)i * SZ_OP, 1024,
            x, 512, out_proj_b + i * 512, nullptr, 1024, 1, 0);
    }

    // 7) final layernorm -> output
    layernorm_k<<<ROWS, 128>>>(x, norm_f_w, norm_f_b, out);
}

// round 13
// speedup vs baseline: 1.8384x; 1.0027x over previous
#include <cuda_runtime.h>
#include <cuda_bf16.h>
#include <math.h>
#include <stdint.h>

// ---------------- problem constants ----------------
#define BB    8
#define LSEQ  1024            // 2*L_IN
#define ROWS  (BB*LSEQ)       // 8192 tokens
#define CC    512
#define DI    1024
#define DS    16
#define NDEPTH 4

// weight-pack offsets (elements) in the converted bf16 weight bank
#define OFF_W1   0
#define SZ_W1    (512*1024)
#define OFF_W2   (OFF_W1 + SZ_W1)
#define SZ_W2    (512*512)
#define OFF_IP   (OFF_W2 + SZ_W2)
#define SZ_IP    (2048*512)
#define OFF_XP   (OFF_IP + 4*SZ_IP)
#define SZ_XP    (128*1024)
#define OFF_OP   (OFF_XP + 4*SZ_XP)
#define SZ_OP    (512*1024)
#define WB_TOTAL (OFF_OP + 4*SZ_OP)   // 7,602,176

// ---------------- scratch (device globals; no allocs allowed) ----------------
__device__ float g_up_tmp[4096*1024];   // up GEMM raw output
__device__ float g_h    [ROWS*CC];      // h1 (pre-rmsnorm)
__device__ float g_x    [ROWS*CC];      // residual stream
__device__ float g_xz   [ROWS*2*DI];    // in_proj out (xc_raw | z)
__device__ float g_xc   [ROWS*DI];      // conv+silu out f32 (scan u)
__device__ float g_xdbc [ROWS*128];     // x_proj out (dtp|B|C|pad), ld=128
__device__ float g_xpart[4*ROWS*128];   // x_proj split-K partials
__device__ float g_dt   [ROWS*DI];      // softplus dt

// bf16 hi/lo operand buffers
__device__ __align__(16) __nv_bfloat16 g_mo_h[4096*512],  g_mo_l[4096*512];
__device__ __align__(16) __nv_bfloat16 g_cat_h[ROWS*1024], g_cat_l[ROWS*1024]; // [up|skip]
__device__ __align__(16) __nv_bfloat16 g_hh[ROWS*512],    g_hl[ROWS*512];
__device__ __align__(16) __nv_bfloat16 g_lnh[ROWS*512],   g_lnl[ROWS*512];
__device__ __align__(16) __nv_bfloat16 g_xch[ROWS*1024],  g_xcl[ROWS*1024];
__device__ __align__(16) __nv_bfloat16 g_yh[ROWS*1024],   g_yl[ROWS*1024];
__device__ __align__(16) __nv_bfloat16 g_wupT_h[1024*512], g_wupT_l[1024*512];
__device__ __align__(16) __nv_bfloat16 g_wb_h[WB_TOTAL],   g_wb_l[WB_TOTAL];

// ---------------- helpers ----------------
__device__ __forceinline__ float softplusf(float x) {
    return (x > 20.f) ? x : log1pf(__expf(x));
}
__device__ __forceinline__ float siluf(float x) {
    return x / (1.f + __expf(-x));
}

__device__ __forceinline__ uint32_t smem_u32(const void* p) {
    uint32_t a;
    asm("{ .reg .u64 t; cvta.to.shared.u64 t, %1; cvt.u32.u64 %0, t; }"
        : "=r"(a) : "l"(p));
    return a;
}

__device__ __forceinline__ void split1(float v, __nv_bfloat16& h, __nv_bfloat16& l) {
    h = __float2bfloat16(v);
    l = __float2bfloat16(v - __bfloat162float(h));
}

// split f32x4 into bf16 hi / lo pairs (packed bf16x2 words, .x in low half)
__device__ __forceinline__ void split4(float4 v, uint32_t& h01, uint32_t& h23,
                                       uint32_t& l01, uint32_t& l23) {
    __nv_bfloat162 h0 = __float22bfloat162_rn(make_float2(v.x, v.y));
    __nv_bfloat162 h1 = __float22bfloat162_rn(make_float2(v.z, v.w));
    float2 f0 = __bfloat1622float2(h0), f1 = __bfloat1622float2(h1);
    __nv_bfloat162 l0 = __float22bfloat162_rn(make_float2(v.x - f0.x, v.y - f0.y));
    __nv_bfloat162 l1 = __float22bfloat162_rn(make_float2(v.z - f1.x, v.w - f1.y));
    h01 = *(uint32_t*)&h0; h23 = *(uint32_t*)&h1;
    l01 = *(uint32_t*)&l0; l23 = *(uint32_t*)&l1;
}

__device__ __forceinline__ void ldsm4(uint32_t* r, uint32_t addr) {
    asm volatile("ldmatrix.sync.aligned.m8n8.x4.shared.b16 {%0,%1,%2,%3}, [%4];"
        : "=r"(r[0]), "=r"(r[1]), "=r"(r[2]), "=r"(r[3]) : "r"(addr));
}

__device__ __forceinline__ void mma_bf16(float* c, const uint32_t* a, const uint32_t* b) {
    asm volatile("mma.sync.aligned.m16n8k16.row.col.f32.bf16.bf16.f32 "
        "{%0,%1,%2,%3}, {%4,%5,%6,%7}, {%8,%9}, {%0,%1,%2,%3};"
        : "+f"(c[0]), "+f"(c[1]), "+f"(c[2]), "+f"(c[3])
        : "r"(a[0]), "r"(a[1]), "r"(a[2]), "r"(a[3]), "r"(b[0]), "r"(b[1]));
}

#define CP16(dst, src) \
    asm volatile("cp.async.cg.shared.global [%0], [%1], 16;" \
                 :: "r"(dst), "l"(src) : "memory")
#define CP_COMMIT() asm volatile("cp.async.commit_group;" ::: "memory")
#define CP_WAIT1()  asm volatile("cp.async.wait_group 1;" ::: "memory")

// ============================================================================
// tensor-core GEMM v3.2: bf16 hi/lo operands, 3-stage cp.async pipeline,
// split-K via blockIdx.z (K = per-split chunk; C += z*zstrC; use beta=0).
// C[M,N] = (Ah+Al)[M,K] @ (Bh+Bl)[N,K]^T (3-term) (+bias)(+rowvec)(+beta*C)
// Block 128x128, BK=32, 8 warps (2x4). XOR-swizzled 64B rows.
// 3 stages x 32KB = 96KB dynamic smem; 2 CTAs/SM (192KB < 228KB).
// ============================================================================
#define TGV_REGION 8192
#define TGV_STAGE  32768
#define TGV_SMEM   98304

__global__ __launch_bounds__(256, 2)
void tgemm_k(const __nv_bfloat16* __restrict__ Ah, const __nv_bfloat16* __restrict__ Al,
             int lda,
             const __nv_bfloat16* __restrict__ Bh, const __nv_bfloat16* __restrict__ Bl,
             int ldb,
             float* __restrict__ C, int ldc,
             const float* __restrict__ bias,
             const float* __restrict__ rowvec,
             int K, int beta, int zstrC)
{
    extern __shared__ __align__(16) char smem[];
    const uint32_t sb = smem_u32(smem);
    const int tid  = threadIdx.x;
    const int wid  = tid >> 5;
    const int lane = tid & 31;
    const int m0 = blockIdx.y * 128;
    const int n0 = blockIdx.x * 128;
    const int kz = blockIdx.z * K;          // split-K offset
    C += (size_t)blockIdx.z * zstrC;
    const int wm = wid >> 2;
    const int wn = wid & 3;

    float acc[4][4][4];
#pragma unroll
    for (int i = 0; i < 4; i++)
#pragma unroll
        for (int j = 0; j < 4; j++)
#pragma unroll
            for (int k = 0; k < 4; k++) acc[i][j][k] = 0.f;

    // ---- cp.async staging geometry ----
    const int s_row = tid >> 1;
    const int c0    = (tid & 1) * 2;
    const int ssw   = (s_row >> 1) & 3;
    const uint32_t d0 = (uint32_t)(s_row * 64 + ((c0     ^ ssw) * 16));
    const uint32_t d1 = (uint32_t)(s_row * 64 + (((c0+1) ^ ssw) * 16));
    const __nv_bfloat16* Ah_s = Ah + (size_t)(m0 + s_row) * lda + kz + c0 * 8;
    const __nv_bfloat16* Al_s = Al + (size_t)(m0 + s_row) * lda + kz + c0 * 8;
    const __nv_bfloat16* Bh_s = Bh + (size_t)(n0 + s_row) * ldb + kz + c0 * 8;
    const __nv_bfloat16* Bl_s = Bl + (size_t)(n0 + s_row) * ldb + kz + c0 * 8;

    // ---- ldmatrix relative offsets (XOR swizzle baked in) ----
    const int q  = lane >> 3;
    const int r8 = lane & 7;
    const int qh = q >> 1;
    const int qb = q & 1;
    uint32_t a_rel[4][2], b_rel[2][2];
#pragma unroll
    for (int mt = 0; mt < 4; mt++) {
        const int ar = wm * 64 + mt * 16 + (q & 1) * 8 + r8;
        const int sw = (ar >> 1) & 3;
#pragma unroll
        for (int ks = 0; ks < 2; ks++)
            a_rel[mt][ks] = (uint32_t)(ar * 64 + (((ks * 2 + qh) ^ sw) * 16));
    }
#pragma unroll
    for (int h = 0; h < 2; h++) {
        const int br = wn * 32 + h * 16 + (q >> 1) * 8 + r8;
        const int sw = (br >> 1) & 3;
#pragma unroll
        for (int ks = 0; ks < 2; ks++)
            b_rel[h][ks] = (uint32_t)(2 * TGV_REGION + br * 64 + (((ks * 2 + qb) ^ sw) * 16));
    }

    const int chunks = K >> 5;

    // prologue: stage chunks 0 and 1 into buffers 0 and 1 (separate groups)
#pragma unroll
    for (int p = 0; p < 2; p++) {
        const uint32_t s0 = sb + (uint32_t)p * TGV_STAGE;
        const int ko = p * 32;
        CP16(s0 + d0, Ah_s + ko);                CP16(s0 + d1, Ah_s + ko + 8);
        CP16(s0 + TGV_REGION + d0, Al_s + ko);   CP16(s0 + TGV_REGION + d1, Al_s + ko + 8);
        CP16(s0 + 2*TGV_REGION + d0, Bh_s + ko); CP16(s0 + 2*TGV_REGION + d1, Bh_s + ko + 8);
        CP16(s0 + 3*TGV_REGION + d0, Bl_s + ko); CP16(s0 + 3*TGV_REGION + d1, Bl_s + ko + 8);
        CP_COMMIT();
    }

    int buf = 0, pf = 2;
    for (int c = 0; c < chunks; c++) {
        CP_WAIT1();         // stage `buf` complete (<=1 group still in flight)
        __syncthreads();    // all warps finished reading the buffer we'll overwrite
        const uint32_t sbuf = sb + (uint32_t)buf * TGV_STAGE;
        if (c + 2 < chunks) {
            const uint32_t sn = sb + (uint32_t)pf * TGV_STAGE;
            const int ko = (c + 2) * 32;
            CP16(sn + d0, Ah_s + ko);                CP16(sn + d1, Ah_s + ko + 8);
            CP16(sn + TGV_REGION + d0, Al_s + ko);   CP16(sn + TGV_REGION + d1, Al_s + ko + 8);
            CP16(sn + 2*TGV_REGION + d0, Bh_s + ko); CP16(sn + 2*TGV_REGION + d1, Bh_s + ko + 8);
            CP16(sn + 3*TGV_REGION + d0, Bl_s + ko); CP16(sn + 3*TGV_REGION + d1, Bl_s + ko + 8);
            CP_COMMIT();
        }

#pragma unroll
        for (int ks = 0; ks < 2; ks++) {
            uint32_t bh[2][4], bl[2][4];
            ldsm4(bh[0], sbuf + b_rel[0][ks]);
            ldsm4(bh[1], sbuf + b_rel[1][ks]);
            ldsm4(bl[0], sbuf + b_rel[0][ks] + TGV_REGION);
            ldsm4(bl[1], sbuf + b_rel[1][ks] + TGV_REGION);
#pragma unroll
            for (int mt = 0; mt < 4; mt++) {
                uint32_t ah[4], al[4];
                ldsm4(ah, sbuf + a_rel[mt][ks]);
                ldsm4(al, sbuf + a_rel[mt][ks] + TGV_REGION);
#pragma unroll
                for (int nt = 0; nt < 4; nt++) {
                    const uint32_t* bhp = &bh[nt >> 1][(nt & 1) * 2];
                    const uint32_t* blp = &bl[nt >> 1][(nt & 1) * 2];
                    mma_bf16(acc[mt][nt], ah, bhp);
                    mma_bf16(acc[mt][nt], ah, blp);
                    mma_bf16(acc[mt][nt], al, bhp);
                }
            }
        }
        buf = (buf == 2) ? 0 : buf + 1;
        pf  = (pf  == 2) ? 0 : pf  + 1;
    }

    // epilogue
    const int er = lane >> 2;
    const int ec = (lane & 3) * 2;
    const int colbase = n0 + wn * 32 + ec;
#pragma unroll
    for (int mt = 0; mt < 4; mt++) {
#pragma unroll
        for (int half = 0; half < 2; half++) {
            const int row = m0 + wm * 64 + mt * 16 + er + half * 8;
            float* cp = C + (size_t)row * ldc + colbase;
            const float* rv = rowvec ? rowvec + (size_t)(row >> 10) * ldc + colbase
                                     : nullptr;
#pragma unroll
            for (int nt = 0; nt < 4; nt++) {
                float v0 = acc[mt][nt][half * 2 + 0];
                float v1 = acc[mt][nt][half * 2 + 1];
                const int co = nt * 8;
                if (bias) { v0 += bias[colbase + co]; v1 += bias[colbase + co + 1]; }
                if (rv)   { v0 += rv[co];             v1 += rv[co + 1]; }
                if (beta) { v0 += cp[co];             v1 += cp[co + 1]; }
                *(float2*)(cp + co) = make_float2(v0, v1);
            }
        }
    }
}

// 4-way split-K reduce: out[i] = sum_z parts[z][i], vectorized float4
__global__ void reduce4_k(const float* __restrict__ p, float* __restrict__ out)
{
    const int i = blockIdx.x * 256 + threadIdx.x;   // over ROWS*128/4
    const int STR = ROWS * 128 / 4;
    float4 a = ((const float4*)p)[i];
    float4 b = ((const float4*)p)[i + STR];
    float4 c = ((const float4*)p)[i + 2 * STR];
    float4 d = ((const float4*)p)[i + 3 * STR];
    float4 o;
    o.x = (a.x + b.x) + (c.x + d.x);
    o.y = (a.y + b.y) + (c.y + d.y);
    o.z = (a.z + b.z) + (c.z + d.z);
    o.w = (a.w + b.w) + (c.w + d.w);
    ((float4*)out)[i] = o;
}

// ============================================================================
// SIMT SGEMM (fmaf, BK=16, double-buffered) — dt_proj only
// ============================================================================
__global__ __launch_bounds__(256, 2)
void sgemm_k(const float* __restrict__ A, int lda,
             const float* __restrict__ B, int ldb,
             float* __restrict__ C, int ldc,
             const float* __restrict__ bias,
             int M, int N, int K, int do_softplus)
{
    __shared__ float As[2][16][128];
    __shared__ float Bs[2][16][128];

    const int tid = threadIdx.x;
    const int m0 = blockIdx.y * 128;
    const int n0 = blockIdx.x * 128;
    const int ty = tid >> 4;
    const int tx = tid & 15;

    const int a_r = tid >> 2;
    const int a_c = (tid & 3) * 4;
    const int b_r = a_r;
    const int b_c = a_c;

    float acc[8][8];
#pragma unroll
    for (int i = 0; i < 8; i++)
#pragma unroll
        for (int j = 0; j < 8; j++) acc[i][j] = 0.f;

    const float* Ab = A + (size_t)m0 * lda;
    float4 a0, a1, b0, b1;

    a0 = *(const float4*)(Ab + (size_t)a_r * lda + a_c);
    a1 = *(const float4*)(Ab + (size_t)(a_r + 64) * lda + a_c);
    b0 = make_float4(0.f, 0.f, 0.f, 0.f); b1 = b0;
    if (n0 + b_r < N)
        b0 = *(const float4*)(B + (size_t)(n0 + b_r) * ldb + b_c);
    if (n0 + b_r + 64 < N)
        b1 = *(const float4*)(B + (size_t)(n0 + b_r + 64) * ldb + b_c);
    {
        As[0][a_c + 0][a_r] = a0.x; As[0][a_c + 1][a_r] = a0.y;
        As[0][a_c + 2][a_r] = a0.z; As[0][a_c + 3][a_r] = a0.w;
        As[0][a_c + 0][a_r + 64] = a1.x; As[0][a_c + 1][a_r + 64] = a1.y;
        As[0][a_c + 2][a_r + 64] = a1.z; As[0][a_c + 3][a_r + 64] = a1.w;
        Bs[0][b_c + 0][b_r] = b0.x; Bs[0][b_c + 1][b_r] = b0.y;
        Bs[0][b_c + 2][b_r] = b0.z; Bs[0][b_c + 3][b_r] = b0.w;
        Bs[0][b_c + 0][b_r + 64] = b1.x; Bs[0][b_c + 1][b_r + 64] = b1.y;
        Bs[0][b_c + 2][b_r + 64] = b1.z; Bs[0][b_c + 3][b_r + 64] = b1.w;
    }
    __syncthreads();

    int buf = 0;
    for (int k0 = 0; k0 < K; k0 += 16) {
        const bool nxt = (k0 + 16 < K);
        if (nxt) {
            const int kn = k0 + 16;
            a0 = *(const float4*)(Ab + (size_t)a_r * lda + kn + a_c);
            a1 = *(const float4*)(Ab + (size_t)(a_r + 64) * lda + kn + a_c);
            b0 = make_float4(0.f, 0.f, 0.f, 0.f); b1 = b0;
            if (n0 + b_r < N)
                b0 = *(const float4*)(B + (size_t)(n0 + b_r) * ldb + kn + b_c);
            if (n0 + b_r + 64 < N)
                b1 = *(const float4*)(B + (size_t)(n0 + b_r + 64) * ldb + kn + b_c);
        }

#pragma unroll
        for (int kk = 0; kk < 16; kk++) {
            float arr[8], brr[8];
            *(float4*)&arr[0] = *(const float4*)&As[buf][kk][ty * 8];
            *(float4*)&arr[4] = *(const float4*)&As[buf][kk][ty * 8 + 4];
            *(float4*)&brr[0] = *(const float4*)&Bs[buf][kk][tx * 8];
            *(float4*)&brr[4] = *(const float4*)&Bs[buf][kk][tx * 8 + 4];
#pragma unroll
            for (int i = 0; i < 8; i++)
#pragma unroll
                for (int j = 0; j < 8; j++)
                    acc[i][j] = fmaf(arr[i], brr[j], acc[i][j]);
        }

        if (nxt) {
            const int nb = buf ^ 1;
            As[nb][a_c + 0][a_r] = a0.x; As[nb][a_c + 1][a_r] = a0.y;
            As[nb][a_c + 2][a_r] = a0.z; As[nb][a_c + 3][a_r] = a0.w;
            As[nb][a_c + 0][a_r + 64] = a1.x; As[nb][a_c + 1][a_r + 64] = a1.y;
            As[nb][a_c + 2][a_r + 64] = a1.z; As[nb][a_c + 3][a_r + 64] = a1.w;
            Bs[nb][b_c + 0][b_r] = b0.x; Bs[nb][b_c + 1][b_r] = b0.y;
            Bs[nb][b_c + 2][b_r] = b0.z; Bs[nb][b_c + 3][b_r] = b0.w;
            Bs[nb][b_c + 0][b_r + 64] = b1.x; Bs[nb][b_c + 1][b_r + 64] = b1.y;
            Bs[nb][b_c + 2][b_r + 64] = b1.z; Bs[nb][b_c + 3][b_r + 64] = b1.w;
            __syncthreads();
            buf = nb;
        }
    }

    const int col = n0 + tx * 8;
    if (col >= N) return;

#pragma unroll
    for (int i = 0; i < 8; i++) {
        const int row = m0 + ty * 8 + i;
        float* cp = C + (size_t)row * ldc + col;
        float v[8];
#pragma unroll
        for (int j = 0; j < 8; j++) {
            float t = acc[i][j];
            if (bias) t += bias[col + j];
            if (do_softplus) t = softplusf(t);
            v[j] = t;
        }
        *(float4*)cp       = *(float4*)&v[0];
        *(float4*)(cp + 4) = *(float4*)&v[4];
    }
}

// ---------------- weight prep ----------------
__global__ void weights_conv_k(const float* __restrict__ w1,
                               const float* __restrict__ w2,
                               const float* __restrict__ ipw,
                               const float* __restrict__ xpw,
                               const float* __restrict__ opw,
                               __nv_bfloat16* __restrict__ wh,
                               __nv_bfloat16* __restrict__ wl)
{
    const int idx = blockIdx.x * 256 + threadIdx.x;
    float v;
    if (idx < OFF_W2)       v = w1[idx];
    else if (idx < OFF_IP)  v = w2[idx - OFF_W2];
    else if (idx < OFF_XP)  v = ipw[idx - OFF_IP];
    else if (idx < OFF_OP) {
        const int l = idx - OFF_XP;
        const int layer = l / SZ_XP;
        const int r = l % SZ_XP;
        const int row = r >> 10, col = r & 1023;
        v = (row < 64) ? xpw[layer * 64 * 1024 + row * 1024 + col] : 0.f;
    } else                  v = opw[idx - OFF_OP];
    __nv_bfloat16 h, l;
    split1(v, h, l);
    wh[idx] = h; wl[idx] = l;
}

__global__ void transpose_wup_k(const float* __restrict__ in,
                                __nv_bfloat16* __restrict__ oh,
                                __nv_bfloat16* __restrict__ ol)
{
    __shared__ float t[32][33];
    const int bx = blockIdx.x, by = blockIdx.y;
    {
        const int x = bx * 32 + threadIdx.x;
        const int y = by * 32 + threadIdx.y;
#pragma unroll
        for (int i = 0; i < 32; i += 8)
            t[threadIdx.y + i][threadIdx.x] = in[(size_t)(y + i) * 1024 + x];
    }
    __syncthreads();
    {
        const int x = by * 32 + threadIdx.x;
        const int y = bx * 32 + threadIdx.y;
#pragma unroll
        for (int i = 0; i < 32; i += 8) {
            __nv_bfloat16 h, l;
            split1(t[threadIdx.x][threadIdx.y + i], h, l);
            oh[(size_t)(y + i) * 512 + x] = h;
            ol[(size_t)(y + i) * 512 + x] = l;
        }
    }
}

// motion convert (dense, ld 512)
__global__ void convert_pair_k(const float* __restrict__ src,
                               __nv_bfloat16* __restrict__ h,
                               __nv_bfloat16* __restrict__ l)
{
    const int i = blockIdx.x * 256 + threadIdx.x;
    float4 v = ((const float4*)src)[i];
    uint32_t h01, h23, l01, l23;
    split4(v, h01, h23, l01, l23);
    ((uint2*)h)[i] = make_uint2(h01, h23);
    ((uint2*)l)[i] = make_uint2(l01, l23);
}

// skip convert into cat buffer cols 512..1023 (ld 1024)
__global__ void convert_skip_k(const float* __restrict__ src,
                               __nv_bfloat16* __restrict__ h,
                               __nv_bfloat16* __restrict__ l)
{
    const int i = blockIdx.x * 256 + threadIdx.x;   // over ROWS*512/4
    const int row  = i >> 7;
    const int col4 = i & 127;
    float4 v = ((const float4*)src)[i];
    uint32_t h01, h23, l01, l23;
    split4(v, h01, h23, l01, l23);
    const int o = row * 256 + 128 + col4;           // uint2 units, ld=1024 elems
    ((uint2*)h)[o] = make_uint2(h01, h23);
    ((uint2*)l)[o] = make_uint2(l01, l23);
}

// ---------------- layernorm -> f32 out (final) ----------------
__global__ void layernorm_k(const float* __restrict__ x,
                            const float* __restrict__ w,
                            const float* __restrict__ b,
                            float* __restrict__ out)
{
    const int row = blockIdx.x;
    const int tid = threadIdx.x;
    float4 v = ((const float4*)(x + (size_t)row * 512))[tid];
    float s  = v.x + v.y + v.z + v.w;
    float sq = v.x * v.x + v.y * v.y + v.z * v.z + v.w * v.w;
#pragma unroll
    for (int o = 16; o > 0; o >>= 1) {
        s  += __shfl_xor_sync(0xffffffffu, s,  o);
        sq += __shfl_xor_sync(0xffffffffu, sq, o);
    }
    __shared__ float ss[4], ssq[4];
    const int wid = tid >> 5;
    if ((tid & 31) == 0) { ss[wid] = s; ssq[wid] = sq; }
    __syncthreads();
    s  = ss[0]  + ss[1]  + ss[2]  + ss[3];
    sq = ssq[0] + ssq[1] + ssq[2] + ssq[3];
    const float m   = s  * (1.f / 512.f);
    const float var = sq * (1.f / 512.f) - m * m;
    const float inv = rsqrtf(var + 1e-5f);
    float4 wv = ((const float4*)w)[tid];
    float4 bv = ((const float4*)b)[tid];
    float4 o4;
    o4.x = (v.x - m) * inv * wv.x + bv.x;
    o4.y = (v.y - m) * inv * wv.y + bv.y;
    o4.z = (v.z - m) * inv * wv.z + bv.z;
    o4.w = (v.w - m) * inv * wv.w + bv.w;
    ((float4*)(out + (size_t)row * 512))[tid] = o4;
}

// ---------------- layernorm -> bf16 hi/lo pair ----------------
__global__ void layernorm_bf_k(const float* __restrict__ x,
                               const float* __restrict__ w,
                               const float* __restrict__ b,
                               __nv_bfloat16* __restrict__ oh,
                               __nv_bfloat16* __restrict__ ol)
{
    const int row = blockIdx.x;
    const int tid = threadIdx.x;
    float4 v = ((const float4*)(x + (size_t)row * 512))[tid];
    float s  = v.x + v.y + v.z + v.w;
    float sq = v.x * v.x + v.y * v.y + v.z * v.z + v.w * v.w;
#pragma unroll
    for (int o = 16; o > 0; o >>= 1) {
        s  += __shfl_xor_sync(0xffffffffu, s,  o);
        sq += __shfl_xor_sync(0xffffffffu, sq, o);
    }
    __shared__ float ss[4], ssq[4];
    const int wid = tid >> 5;
    if ((tid & 31) == 0) { ss[wid] = s; ssq[wid] = sq; }
    __syncthreads();
    s  = ss[0]  + ss[1]  + ss[2]  + ss[3];
    sq = ssq[0] + ssq[1] + ssq[2] + ssq[3];
    const float m   = s  * (1.f / 512.f);
    const float var = sq * (1.f / 512.f) - m * m;
    const float inv = rsqrtf(var + 1e-5f);
    float4 wv = ((const float4*)w)[tid];
    float4 bv = ((const float4*)b)[tid];
    float4 o4;
    o4.x = (v.x - m) * inv * wv.x + bv.x;
    o4.y = (v.y - m) * inv * wv.y + bv.y;
    o4.z = (v.z - m) * inv * wv.z + bv.z;
    o4.w = (v.w - m) * inv * wv.w + bv.w;
    uint32_t h01, h23, l01, l23;
    split4(o4, h01, h23, l01, l23);
    ((uint2*)(oh + (size_t)row * 512))[tid] = make_uint2(h01, h23);
    ((uint2*)(ol + (size_t)row * 512))[tid] = make_uint2(l01, l23);
}

// ---------------- rmsnorm + silu -> bf16 hi/lo pair ----------------
__global__ void rmsnorm_silu_k(const float* __restrict__ x,
                               const float* __restrict__ w,
                               __nv_bfloat16* __restrict__ oh,
                               __nv_bfloat16* __restrict__ ol)
{
    const int row = blockIdx.x;
    const int tid = threadIdx.x;
    float4 v = ((const float4*)(x + (size_t)row * 512))[tid];
    float sq = v.x * v.x + v.y * v.y + v.z * v.z + v.w * v.w;
#pragma unroll
    for (int o = 16; o > 0; o >>= 1) sq += __shfl_xor_sync(0xffffffffu, sq, o);
    __shared__ float ssq[4];
    const int wid = tid >> 5;
    if ((tid & 31) == 0) ssq[wid] = sq;
    __syncthreads();
    sq = ssq[0] + ssq[1] + ssq[2] + ssq[3];
    const float inv = rsqrtf(sq * (1.f / 512.f) + 1e-5f);
    float4 wv = ((const float4*)w)[tid];
    float4 o4;
    float a;
    a = v.x * inv * wv.x; o4.x = siluf(a);
    a = v.y * inv * wv.y; o4.y = siluf(a);
    a = v.z * inv * wv.z; o4.z = siluf(a);
    a = v.w * inv * wv.w; o4.w = siluf(a);
    uint32_t h01, h23, l01, l23;
    split4(o4, h01, h23, l01, l23);
    ((uint2*)(oh + (size_t)row * 512))[tid] = make_uint2(h01, h23);
    ((uint2*)(ol + (size_t)row * 512))[tid] = make_uint2(l01, l23);
}

// ---------------- up rearrange -> cat buffer cols 0..511 (+b_up) ----------------
__global__ void up_rearrange_k(const float* __restrict__ up_tmp,
                               const float* __restrict__ b_up,
                               __nv_bfloat16* __restrict__ oh,
                               __nv_bfloat16* __restrict__ ol)
{
    const int idx  = blockIdx.x * blockDim.x + threadIdx.x;   // ROWS*512
    const int o    = idx & 511;
    const int orow = idx >> 9;
    const int b    = orow >> 10;
    const int t    = orow & 1023;
    const int l    = t >> 1;
    const int k    = t & 1;
    const float v = up_tmp[(size_t)(b * 512 + l) * 1024 + o * 2 + k] + b_up[o];
    __nv_bfloat16 h, lo;
    split1(v, h, lo);
    const size_t oo = (size_t)orow * 1024 + o;   // cat buffer, ld 1024
    oh[oo] = h; ol[oo] = lo;
}

// ---------------- causal depthwise conv(4) + bias + silu ----------------
__global__ void conv_silu_k(const float* __restrict__ xz,
                            const float* __restrict__ cw,
                            const float* __restrict__ cb,
                            float* __restrict__ xc,
                            __nv_bfloat16* __restrict__ oh,
                            __nv_bfloat16* __restrict__ ol)
{
    const int idx = blockIdx.x * blockDim.x + threadIdx.x;
    const int d   = idx & 1023;
    const int row = idx >> 10;
    const int t   = row & 1023;
    float acc = cb[d];
#pragma unroll
    for (int j = 0; j < 4; j++) {
        const int tt = t - 3 + j;
        if (tt >= 0)
            acc = fmaf(cw[d * 4 + j], xz[(size_t)(row - 3 + j) * 2048 + d], acc);
    }
    const float v = siluf(acc);
    xc[idx] = v;
    __nv_bfloat16 h, l;
    split1(v, h, l);
    oh[idx] = h; ol[idx] = l;
}

// ---------------- selective scan: 4 threads per channel ----------------
__global__ __launch_bounds__(128)
void scan_k(const float* __restrict__ dt,
            const float* __restrict__ xc,
            const float* __restrict__ xz,
            const float* __restrict__ xdbc,    // [ROWS,128]: dtp|B|C|pad
            const float* __restrict__ A_log,
            const float* __restrict__ Dp,
            __nv_bfloat16* __restrict__ yh,
            __nv_bfloat16* __restrict__ yl)
{
    __shared__ __align__(16) float bc_s[32][32];

    const int tid     = threadIdx.x;         // 128
    const int quarter = tid & 3;
    const int dloc    = tid >> 2;             // 0..31
    const int b       = blockIdx.x >> 5;      // 0..7
    const int d       = (blockIdx.x & 31) * 32 + dloc;
    const int n0      = quarter * 4;

    float A2[4], h[4];
#pragma unroll
    for (int j = 0; j < 4; j++) {
        A2[j] = -__expf(A_log[d * 16 + n0 + j]) * 1.44269504f;
        h[j]  = 0.f;
    }
    const float Dd = Dp[d];

    const float* dtp = dt   + (size_t)b * 1024 * 1024 + d;
    const float* up  = xc   + (size_t)b * 1024 * 1024 + d;
    const float* zp  = xz   + (size_t)b * 1024 * 2048 + 1024 + d;
    const float* bcb = xdbc + (size_t)b * 1024 * 128 + 32;
    __nv_bfloat16* yhp = yh + (size_t)b * 1024 * 1024 + d;
    __nv_bfloat16* ylp = yl + (size_t)b * 1024 * 1024 + d;

    const int st_t = tid >> 2;
    const int st_c = (tid & 3) * 8;

    for (int c = 0; c < 32; c++) {
        __syncthreads();
        {
            const float* src = bcb + (size_t)(c * 32 + st_t) * 128 + st_c;
            *(float4*)&bc_s[st_t][st_c]     = *(const float4*)src;
            *(float4*)&bc_s[st_t][st_c + 4] = *(const float4*)(src + 4);
        }
        __syncthreads();

#pragma unroll
        for (int s = 0; s < 4; s++) {
            const int tbase = c * 32 + s * 8;
            float dt8[8], u8[8], z8[8];
#pragma unroll
            for (int j = 0; j < 8; j++) {
                dt8[j] = dtp[(size_t)(tbase + j) * 1024];
                u8[j]  = up [(size_t)(tbase + j) * 1024];
                z8[j]  = zp [(size_t)(tbase + j) * 2048];
            }
#pragma unroll
            for (int j = 0; j < 8; j++) {
                const int tt = s * 8 + j;
                float Bv[4], Cv[4];
                *(float4*)&Bv[0] = *(const float4*)&bc_s[tt][n0];
                *(float4*)&Cv[0] = *(const float4*)&bc_s[tt][16 + n0];
                const float dtv = dt8[j];
                const float u   = u8[j];
                const float du  = dtv * u;
                float ya = 0.f, yb2 = 0.f;
#pragma unroll
                for (int n = 0; n < 4; n++) {
                    const float dA = exp2f(dtv * A2[n]);
                    h[n] = fmaf(dA, h[n], du * Bv[n]);
                    if (n & 1) yb2 = fmaf(h[n], Cv[n], yb2);
                    else       ya  = fmaf(h[n], Cv[n], ya);
                }
                float ysum = ya + yb2;
                ysum += __shfl_xor_sync(0xffffffffu, ysum, 1);
                ysum += __shfl_xor_sync(0xffffffffu, ysum, 2);
                if (quarter == 0) {
                    const float w = (ysum + u * Dd) * siluf(z8[j]);
                    __nv_bfloat16 wh, wl;
                    split1(w, wh, wl);
                    yhp[(size_t)(tbase + j) * 1024] = wh;
                    ylp[(size_t)(tbase + j) * 1024] = wl;
                }
            }
        }
    }
}

// ---------------- launcher ----------------
extern "C" void kernel_launch(void* const* d_in, const int* in_sizes, int n_in,
                              void* d_out, int out_size)
{
    (void)in_sizes; (void)n_in; (void)out_size;

    const float* motion     = (const float*)d_in[0];
    const float* skip       = (const float*)d_in[1];
    const float* embed      = (const float*)d_in[2];
    const float* w_up       = (const float*)d_in[3];
    const float* b_up       = (const float*)d_in[4];
    const float* w1         = (const float*)d_in[5];
    const float* b1         = (const float*)d_in[6];
    const float* rms_w      = (const float*)d_in[7];
    const float* w2         = (const float*)d_in[8];
    const float* b2         = (const float*)d_in[9];
    const float* ln_w       = (const float*)d_in[10];
    const float* ln_b       = (const float*)d_in[11];
    const float* in_proj_w  = (const float*)d_in[12];
    const float* conv_w     = (const float*)d_in[13];
    const float* conv_b     = (const float*)d_in[14];
    const float* x_proj_w   = (const float*)d_in[15];
    const float* dt_proj_w  = (const float*)d_in[16];
    const float* dt_proj_b  = (const float*)d_in[17];
    const float* A_log      = (const float*)d_in[18];
    const float* D_param    = (const float*)d_in[19];
    const float* out_proj_w = (const float*)d_in[20];
    const float* out_proj_b = (const float*)d_in[21];
    const float* norm_f_w   = (const float*)d_in[22];
    const float* norm_f_b   = (const float*)d_in[23];
    float* out = (float*)d_out;

    float *up_tmp, *h, *x, *xz, *xc, *xdbc, *xpart, *dtb;
    cudaGetSymbolAddress((void**)&up_tmp, g_up_tmp);
    cudaGetSymbolAddress((void**)&h,      g_h);
    cudaGetSymbolAddress((void**)&x,      g_x);
    cudaGetSymbolAddress((void**)&xz,     g_xz);
    cudaGetSymbolAddress((void**)&xc,     g_xc);
    cudaGetSymbolAddress((void**)&xdbc,   g_xdbc);
    cudaGetSymbolAddress((void**)&xpart,  g_xpart);
    cudaGetSymbolAddress((void**)&dtb,    g_dt);

    __nv_bfloat16 *mo_h, *mo_l, *cat_h, *cat_l, *hh, *hl;
    __nv_bfloat16 *ln_h, *ln_l, *xc_h, *xc_l, *y_h, *y_l;
    __nv_bfloat16 *wupT_h, *wupT_l, *wb_h, *wb_l;
    cudaGetSymbolAddress((void**)&mo_h, g_mo_h);   cudaGetSymbolAddress((void**)&mo_l, g_mo_l);
    cudaGetSymbolAddress((void**)&cat_h, g_cat_h); cudaGetSymbolAddress((void**)&cat_l, g_cat_l);
    cudaGetSymbolAddress((void**)&hh,   g_hh);     cudaGetSymbolAddress((void**)&hl,   g_hl);
    cudaGetSymbolAddress((void**)&ln_h, g_lnh);    cudaGetSymbolAddress((void**)&ln_l, g_lnl);
    cudaGetSymbolAddress((void**)&xc_h, g_xch);    cudaGetSymbolAddress((void**)&xc_l, g_xcl);
    cudaGetSymbolAddress((void**)&y_h,  g_yh);     cudaGetSymbolAddress((void**)&y_l,  g_yl);
    cudaGetSymbolAddress((void**)&wupT_h, g_wupT_h); cudaGetSymbolAddress((void**)&wupT_l, g_wupT_l);
    cudaGetSymbolAddress((void**)&wb_h, g_wb_h);   cudaGetSymbolAddress((void**)&wb_l, g_wb_l);

    cudaFuncSetAttribute(tgemm_k, cudaFuncAttributeMaxDynamicSharedMemorySize,
                         TGV_SMEM);

    // ---- weight + input conversion ----
    weights_conv_k<<<WB_TOTAL / 256, 256>>>(w1, w2, in_proj_w, x_proj_w,
                                            out_proj_w, wb_h, wb_l);
    transpose_wup_k<<<dim3(32, 16), dim3(32, 8)>>>(w_up, wupT_h, wupT_l);
    convert_pair_k<<<(4096 * 512 / 4) / 256, 256>>>(motion, mo_h, mo_l);
    convert_skip_k<<<(ROWS * 512 / 4) / 256, 256>>>(skip, cat_h, cat_l);

    // 1) up = motion @ w_up
    tgemm_k<<<dim3(8, 32), 256, TGV_SMEM>>>(
        mo_h, mo_l, 512, wupT_h, wupT_l, 512, up_tmp, 1024,
        nullptr, nullptr, 512, 0, 0);

    // 2) rearrange + b_up -> cat cols 0..511
    up_rearrange_k<<<(ROWS * 512) / 256, 256>>>(up_tmp, b_up, cat_h, cat_l);

    // 3) h = [up|skip] @ w1^T + b1   (single K=1024 GEMM)
    tgemm_k<<<dim3(4, 64), 256, TGV_SMEM>>>(
        cat_h, cat_l, 1024, wb_h + OFF_W1, wb_l + OFF_W1, 1024, h, 512,
        b1, nullptr, 1024, 0, 0);

    // 4) silu(rmsnorm(h)) -> bf16 pair
    rmsnorm_silu_k<<<ROWS, 128>>>(h, rms_w, hh, hl);

    // 5) x = h @ w2^T + b2 + embed[b]
    tgemm_k<<<dim3(4, 64), 256, TGV_SMEM>>>(
        hh, hl, 512, wb_h + OFF_W2, wb_l + OFF_W2, 512, x, 512,
        b2, embed, 512, 0, 0);

    // 6) mamba layers
    for (int i = 0; i < NDEPTH; i++) {
        layernorm_bf_k<<<ROWS, 128>>>(x, ln_w + i * 512, ln_b + i * 512, ln_h, ln_l);

        tgemm_k<<<dim3(16, 64), 256, TGV_SMEM>>>(
            ln_h, ln_l, 512,
            wb_h + OFF_IP + (size_t)i * SZ_IP, wb_l + OFF_IP + (size_t)i * SZ_IP, 512,
            xz, 2048, nullptr, nullptr, 512, 0, 0);

        conv_silu_k<<<(ROWS * DI) / 256, 256>>>(
            xz, conv_w + (size_t)i * 1024 * 4, conv_b + i * 1024, xc, xc_h, xc_l);

        // x_proj split-K=4
        tgemm_k<<<dim3(1, 64, 4), 256, TGV_SMEM>>>(
            xc_h, xc_l, 1024,
            wb_h + OFF_XP + (size_t)i * SZ_XP, wb_l + OFF_XP + (size_t)i * SZ_XP, 1024,
            xpart, 128, nullptr, nullptr, 256, 0, ROWS * 128);
        reduce4_k<<<(ROWS * 128 / 4) / 256, 256>>>(xpart, xdbc);

        sgemm_k<<<dim3(8, 64), 256>>>(
            xdbc, 128, dt_proj_w + (size_t)i * 1024 * 32, 32,
            dtb, 1024, dt_proj_b + i * 1024, ROWS, 1024, 32, 1);

        scan_k<<<256, 128>>>(
            dtb, xc, xz, xdbc,
            A_log + (size_t)i * 1024 * 16, D_param + i * 1024, y_h, y_l);

        tgemm_k<<<dim3(4, 64), 256, TGV_SMEM>>>(
            y_h, y_l, 1024,
            wb_h + OFF_OP + (size_t)i * SZ_OP, wb_l + OFF_OP + (size_t)i * SZ_OP, 1024,
            x, 512, out_proj_b + i * 512, nullptr, 1024, 1, 0);
    }

    // 7) final layernorm -> output
    layernorm_k<<<ROWS, 128>>>(x, norm_f_w, norm_f_b, out);
}